// round 1
// baseline (speedup 1.0000x reference)
#include <cuda_runtime.h>
#include <math.h>

#define NB     2
#define NSEQ   256
#define NM     8
#define ND     256
#define NH     8
#define NDH    64
#define NINNER 512
#define NTOK   (NB*NSEQ*NM)          // 4096
#define NBN    (NB*NSEQ)             // 512

// ---------------- scratch (static device globals; no allocation) ----------------
__device__ float g_xt[NTOK*ND];                                  // [token(b,n,m)][d]     4MB
__device__ float g_q [NTOK*NINNER];                              // [token][h*64+d]       8MB
__device__ float g_kv[NTOK*2*NINNER];                            // [token][k:512 | v:512] 16MB
__device__ float g_S [(size_t)NB*NH*NM*NSEQ*NM*NSEQ];            // [e=(b,h,z)][(i*8+m)*256+j] 268MB
__device__ float g_mx[NB*NH*NM*NM*NSEQ];                         // [e][m][j]  softmax max
__device__ float g_rs[NB*NH*NM*NM*NSEQ];                         // [e][m][j]  1/sum
__device__ float g_ao[(size_t)NBN*4096];                         // attn out [b*N+i][z*512+h*64+d]
__device__ float g_y1[(size_t)NBN*2048];                         // Wout result [b*N+n][m*256+d]
__device__ float g_x2[NTOK*ND];                                  // post-LN1
__device__ float g_hf[(size_t)NTOK*2048];                        // FFN1 out
__device__ float g_fi[(size_t)NTOK*1024];                        // GEGLU out
__device__ float g_y2[NTOK*ND];                                  // FFN2 out

// ---------------- generic 64x64x16 fp32 GEMM body ----------------
// C[m0+64, n0+64] = alpha * A @ op(B) + bias.   A row-major [*, K] lda.
// BT=false: B[k*ldb + c]   (row-major KxN)
// BT=true : B[c*ldb + k]   (i.e. C = A @ B'^T with B' row-major NxK)
template<bool BT>
__device__ __forceinline__ void gemm_body(
    const float* __restrict__ A, int lda,
    const float* __restrict__ B, int ldb,
    float* __restrict__ C, int ldc,
    int K, int m0, int n0,
    const float* __restrict__ bias, float alpha)
{
    __shared__ float As[16][64];
    __shared__ float Bs[16][64];
    const int tid = threadIdx.x;
    const int tx = tid & 15, ty = tid >> 4;
    float acc[4][4] = {};
    for (int k0 = 0; k0 < K; k0 += 16) {
        {   // A tile: 64 rows x 16 k, float4 along k, transpose into As[k][row]
            int r  = tid >> 2;
            int kq = (tid & 3) << 2;
            float4 a4 = *(const float4*)(A + (size_t)(m0 + r) * lda + k0 + kq);
            As[kq+0][r] = a4.x; As[kq+1][r] = a4.y; As[kq+2][r] = a4.z; As[kq+3][r] = a4.w;
        }
        if (!BT) {
            int r = tid >> 4;
            int c = (tid & 15) << 2;
            *(float4*)&Bs[r][c] = *(const float4*)(B + (size_t)(k0 + r) * ldb + n0 + c);
        } else {
            int c  = tid >> 2;
            int kq = (tid & 3) << 2;
            float4 b4 = *(const float4*)(B + (size_t)(n0 + c) * ldb + k0 + kq);
            Bs[kq+0][c] = b4.x; Bs[kq+1][c] = b4.y; Bs[kq+2][c] = b4.z; Bs[kq+3][c] = b4.w;
        }
        __syncthreads();
        #pragma unroll
        for (int k = 0; k < 16; k++) {
            float4 av = *(const float4*)&As[k][ty << 2];
            float4 bv = *(const float4*)&Bs[k][tx << 2];
            float a[4] = {av.x, av.y, av.z, av.w};
            float b[4] = {bv.x, bv.y, bv.z, bv.w};
            #pragma unroll
            for (int i = 0; i < 4; i++)
                #pragma unroll
                for (int j = 0; j < 4; j++)
                    acc[i][j] += a[i] * b[j];
        }
        __syncthreads();
    }
    float4 bi = make_float4(0.f, 0.f, 0.f, 0.f);
    if (bias) bi = *(const float4*)&bias[n0 + (tx << 2)];
    #pragma unroll
    for (int i = 0; i < 4; i++) {
        float4 o;
        o.x = acc[i][0]*alpha + bi.x;
        o.y = acc[i][1]*alpha + bi.y;
        o.z = acc[i][2]*alpha + bi.z;
        o.w = acc[i][3]*alpha + bi.w;
        *(float4*)&C[(size_t)(m0 + (ty<<2) + i) * ldc + n0 + (tx<<2)] = o;
    }
}

// ---------------- kernels ----------------

// x[b,d,m,n] -> g_xt[(b*N+n)*M+m][d]   (32x32 smem tile transpose over (d,n))
__global__ __launch_bounds__(256) void k_tr(const float* __restrict__ x) {
    __shared__ float tile[32][33];
    int zi = blockIdx.z;                 // b*8 + m
    int b = zi >> 3, m = zi & 7;
    int n0 = blockIdx.x * 32, d0 = blockIdx.y * 32;
    #pragma unroll
    for (int r = 0; r < 4; r++) {
        int d = d0 + threadIdx.y + r*8;
        int n = n0 + threadIdx.x;
        tile[threadIdx.y + r*8][threadIdx.x] =
            x[((size_t)(b*ND + d)*NM + m)*NSEQ + n];
    }
    __syncthreads();
    #pragma unroll
    for (int r = 0; r < 4; r++) {
        int n = n0 + threadIdx.y + r*8;
        int d = d0 + threadIdx.x;
        g_xt[((size_t)(b*NSEQ + n)*NM + m)*ND + d] = tile[threadIdx.x][threadIdx.y + r*8];
    }
}

__global__ __launch_bounds__(256) void k_gemm_q(const float* __restrict__ Wq) {
    gemm_body<false>(g_xt, ND, Wq, NINNER, g_q, NINNER, ND,
                     blockIdx.y*64, blockIdx.x*64, nullptr, 1.f);
}
__global__ __launch_bounds__(256) void k_gemm_kv(const float* __restrict__ Wkv) {
    gemm_body<false>(g_xt, ND, Wkv, 2*NINNER, g_kv, 2*NINNER, ND,
                     blockIdx.y*64, blockIdx.x*64, nullptr, 1.f);
}

// S[e=(b,h,z)][(i,m), j] = 0.125 * Q'[(i,m),d] @ K_z[j,d]^T
__global__ __launch_bounds__(256) void k_sim() {
    int e = blockIdx.z;
    int z = e & 7, h = (e >> 3) & 7, b = e >> 6;
    const float* A = g_q  + (size_t)b * NSEQ * NM * NINNER + h * NDH;       // row (i*8+m), lda=512
    const float* B = g_kv + (size_t)b * NSEQ * NM * (2*NINNER)
                   + (size_t)z * (2*NINNER) + h * NDH;                      // row j, ldb=8192
    float* C = g_S + (size_t)e * (NSEQ*NM) * NSEQ;
    gemm_body<true>(A, NINNER, B, NM*2*NINNER, C, NSEQ, NDH,
                    blockIdx.y*64, blockIdx.x*64, nullptr, 0.125f);
}

// online softmax stats over i (stride 2048) for each (e, m, j)
__global__ __launch_bounds__(256) void k_stats() {
    int idx = blockIdx.x * 256 + threadIdx.x;          // [e][m][j]
    int j = idx & 255, m = (idx >> 8) & 7, e = idx >> 11;
    const float* p = g_S + (size_t)e * (NSEQ*NM*NSEQ) + m * NSEQ + j;
    float mx = -3.4e38f, sm = 0.f;
    #pragma unroll 4
    for (int i = 0; i < NSEQ; i++) {
        float s = p[(size_t)i * (NM*NSEQ)];
        if (s > mx) { sm *= __expf(mx - s); mx = s; }
        sm += __expf(s - mx);
    }
    g_mx[idx] = mx;
    g_rs[idx] = 1.f / sm;
}

// O_z[i,d] = sum_{m,j} exp(S-mx[m,j])*rs[m,j] * V[(j,m),d]
__global__ __launch_bounds__(256) void k_attnout() {
    __shared__ float As[16][64];
    __shared__ float Bs[16][64];
    __shared__ float mxs[256], rss[256];
    int e = blockIdx.z;
    int z = e & 7, h = (e >> 3) & 7, b = e >> 6;
    int i0 = blockIdx.x * 64;
    const float* Sb  = g_S  + (size_t)e * (NSEQ*NM*NSEQ);
    const float* Vb  = g_kv + (size_t)b * NSEQ * NM * (2*NINNER) + NINNER + h * NDH;
    const float* mxb = g_mx + (size_t)e * (NM*NSEQ);
    const float* rsb = g_rs + (size_t)e * (NM*NSEQ);
    const int tid = threadIdx.x;
    const int tx = tid & 15, ty = tid >> 4;
    float acc[4][4] = {};
    for (int m = 0; m < NM; m++) {
        __syncthreads();
        mxs[tid] = mxb[m*NSEQ + tid];
        rss[tid] = rsb[m*NSEQ + tid];
        __syncthreads();
        for (int j0 = 0; j0 < NSEQ; j0 += 16) {
            {   // A tile: exp-normalized S, 64 i-rows x 16 j
                int r  = tid >> 2;
                int kq = (tid & 3) << 2;
                float4 s4 = *(const float4*)(Sb + ((size_t)(i0 + r)*8 + m)*NSEQ + j0 + kq);
                As[kq+0][r] = __expf(s4.x - mxs[j0+kq+0]) * rss[j0+kq+0];
                As[kq+1][r] = __expf(s4.y - mxs[j0+kq+1]) * rss[j0+kq+1];
                As[kq+2][r] = __expf(s4.z - mxs[j0+kq+2]) * rss[j0+kq+2];
                As[kq+3][r] = __expf(s4.w - mxs[j0+kq+3]) * rss[j0+kq+3];
            }
            {   // B tile: V[(j,m), d], 16 j x 64 d
                int r = tid >> 4;
                int c = (tid & 15) << 2;
                *(float4*)&Bs[r][c] =
                    *(const float4*)(Vb + (size_t)(j0 + r)*(NM*2*NINNER) + m*(2*NINNER) + c);
            }
            __syncthreads();
            #pragma unroll
            for (int k = 0; k < 16; k++) {
                float4 av = *(const float4*)&As[k][ty << 2];
                float4 bv = *(const float4*)&Bs[k][tx << 2];
                float a[4] = {av.x, av.y, av.z, av.w};
                float bb[4] = {bv.x, bv.y, bv.z, bv.w};
                #pragma unroll
                for (int i = 0; i < 4; i++)
                    #pragma unroll
                    for (int jj = 0; jj < 4; jj++)
                        acc[i][jj] += a[i] * bb[jj];
            }
            __syncthreads();
        }
    }
    float* Ob = g_ao + (size_t)(b*NSEQ) * 4096 + z*512 + h*64;
    #pragma unroll
    for (int i = 0; i < 4; i++) {
        float4 o = make_float4(acc[i][0], acc[i][1], acc[i][2], acc[i][3]);
        *(float4*)&Ob[(size_t)(i0 + (ty<<2) + i) * 4096 + (tx<<2)] = o;
    }
}

__global__ __launch_bounds__(256) void k_gemm_wout(const float* __restrict__ W,
                                                   const float* __restrict__ bias) {
    gemm_body<false>(g_ao, 4096, W, 2048, g_y1, 2048, 4096,
                     blockIdx.y*64, blockIdx.x*64, bias, 1.f);
}

// residual + LayerNorm.  mode 1: y from g_y1[bn][m*256+d]; mode 2: y from g_y2[t][d]
__global__ __launch_bounds__(256) void k_ln(int mode,
                                            const float* __restrict__ g,
                                            const float* __restrict__ beta,
                                            float* __restrict__ out) {
    int t = blockIdx.x, d = threadIdx.x;
    float xv, yv;
    if (mode == 1) {
        int bn = t >> 3, m = t & 7;
        xv = g_xt[(size_t)t*ND + d];
        yv = g_y1[(size_t)bn*2048 + m*ND + d];
    } else {
        xv = g_x2[(size_t)t*ND + d];
        yv = g_y2[(size_t)t*ND + d];
    }
    float v = xv + yv;
    float s = v, s2 = v * v;
    #pragma unroll
    for (int o = 16; o; o >>= 1) {
        s  += __shfl_xor_sync(0xffffffffu, s,  o);
        s2 += __shfl_xor_sync(0xffffffffu, s2, o);
    }
    __shared__ float sh[16];
    int w = d >> 5, l = d & 31;
    if (l == 0) { sh[w] = s; sh[8 + w] = s2; }
    __syncthreads();
    if (d == 0) {
        float ts = 0.f, ts2 = 0.f;
        #pragma unroll
        for (int i = 0; i < 8; i++) { ts += sh[i]; ts2 += sh[8 + i]; }
        float mu  = ts * (1.f/256.f);
        float var = ts2 * (1.f/256.f) - mu*mu;
        sh[0] = mu;
        sh[1] = rsqrtf(var + 1e-5f);
    }
    __syncthreads();
    float mu = sh[0], rstd = sh[1];
    float r = (v - mu) * rstd * g[d] + beta[d];
    if (mode == 1) g_x2[(size_t)t*ND + d] = r;
    else           out[(size_t)t*ND + d] = r;
}

__global__ __launch_bounds__(256) void k_gemm_ff1(const float* __restrict__ W,
                                                  const float* __restrict__ bias) {
    gemm_body<false>(g_x2, ND, W, 2048, g_hf, 2048, ND,
                     blockIdx.y*64, blockIdx.x*64, bias, 1.f);
}

__global__ __launch_bounds__(256) void k_geglu() {
    int idx = blockIdx.x * 256 + threadIdx.x;   // t*1024 + c
    int t = idx >> 10, c = idx & 1023;
    float a = g_hf[(size_t)t*2048 + c];
    float gt = g_hf[(size_t)t*2048 + 1024 + c];
    g_fi[idx] = a * 0.5f * gt * (1.f + erff(gt * 0.70710678118654752f));
}

__global__ __launch_bounds__(256) void k_gemm_ff2(const float* __restrict__ W,
                                                  const float* __restrict__ bias) {
    gemm_body<false>(g_fi, 1024, W, ND, g_y2, ND, 1024,
                     blockIdx.y*64, blockIdx.x*64, bias, 1.f);
}

// ---------------- launch ----------------
extern "C" void kernel_launch(void* const* d_in, const int* in_sizes, int n_in,
                              void* d_out, int out_size) {
    const float* x     = (const float*)d_in[0];
    const float* Wq    = (const float*)d_in[1];
    const float* Wkv   = (const float*)d_in[2];
    const float* Wout  = (const float*)d_in[3];
    const float* bout  = (const float*)d_in[4];
    const float* g1    = (const float*)d_in[5];
    const float* beta1 = (const float*)d_in[6];
    const float* Wff1  = (const float*)d_in[7];
    const float* bff1  = (const float*)d_in[8];
    const float* Wff2  = (const float*)d_in[9];
    const float* bff2  = (const float*)d_in[10];
    const float* g2    = (const float*)d_in[11];
    const float* beta2 = (const float*)d_in[12];
    float* out = (float*)d_out;

    k_tr      <<<dim3(8, 8, 16),  dim3(32, 8)>>>(x);
    k_gemm_q  <<<dim3(8, 64),     256>>>(Wq);          // [4096,256]@[256,512]
    k_gemm_kv <<<dim3(16, 64),    256>>>(Wkv);         // [4096,256]@[256,1024]
    k_sim     <<<dim3(4, 32, 128),256>>>();            // 128 x [2048,64]@[64,256]^T
    k_stats   <<<1024,            256>>>();            // softmax over i
    k_attnout <<<dim3(4, 1, 128), 256>>>();            // 128 x fused exp-GEMM -> [256,64]
    k_gemm_wout<<<dim3(32, 8),    256>>>(Wout, bout);  // [512,4096]@[4096,2048]
    k_ln      <<<4096,            256>>>(1, g1, beta1, nullptr);
    k_gemm_ff1<<<dim3(32, 64),    256>>>(Wff1, bff1);  // [4096,256]@[256,2048]
    k_geglu   <<<16384,           256>>>();
    k_gemm_ff2<<<dim3(4, 64),     256>>>(Wff2, bff2);  // [4096,1024]@[1024,256]
    k_ln      <<<4096,            256>>>(2, g2, beta2, out);
}

// round 2
// speedup vs baseline: 1.3527x; 1.3527x over previous
#include <cuda_runtime.h>
#include <math.h>
#include <stdint.h>

#define NB     2
#define NSEQ   256
#define NM     8
#define ND     256
#define NH     8
#define NDH    64
#define NINNER 512
#define NTOK   (NB*NSEQ*NM)          // 4096
#define NBN    (NB*NSEQ)             // 512

// ---------------- scratch (static device globals; no allocation) ----------------
__device__ float g_xt[NTOK*ND];                                  // [token(b,n,m)][d]
__device__ float g_q [NTOK*NINNER];                              // [token][h*64+d]
__device__ float g_kv[NTOK*2*NINNER];                            // [token][k:512 | v:512]
__device__ float g_S [(size_t)NB*NH*NM*NSEQ*NM*NSEQ];            // [e=(b,h,z)][(i*8+m)*256+j]
__device__ float g_mx[NB*NH*NM*NM*NSEQ];                         // [e][m][j]  softmax max
__device__ float g_rs[NB*NH*NM*NM*NSEQ];                         // [e][m][j]  1/sum
__device__ float g_ao[(size_t)NBN*4096];                         // attn out [b*N+i][z*512+h*64+d]
__device__ float g_y1[(size_t)NBN*2048];                         // Wout result
__device__ float g_x2[NTOK*ND];                                  // post-LN1
__device__ float g_hf[(size_t)NTOK*2048];                        // FFN1 out
__device__ float g_fi[(size_t)NTOK*1024];                        // GEGLU out
__device__ float g_y2[NTOK*ND];                                  // FFN2 out

// ---------------- tf32 mma helpers ----------------
__device__ __forceinline__ uint32_t f2tf32(float x) {
    uint32_t r;
    asm("cvt.rna.tf32.f32 %0, %1;" : "=r"(r) : "f"(x));
    return r;
}

__device__ __forceinline__ void mma_tf32(float* c, const uint32_t* a, const uint32_t* b) {
    asm volatile(
        "mma.sync.aligned.m16n8k8.row.col.f32.tf32.tf32.f32 "
        "{%0,%1,%2,%3}, {%4,%5,%6,%7}, {%8,%9}, {%0,%1,%2,%3};\n"
        : "+f"(c[0]), "+f"(c[1]), "+f"(c[2]), "+f"(c[3])
        : "r"(a[0]), "r"(a[1]), "r"(a[2]), "r"(a[3]),
          "r"(b[0]), "r"(b[1]));
}

// ---------------- generic tf32 tensor-core GEMM body ----------------
// 256 threads. Block tile BM x BN, K chunk 16. Warps 2(m) x 4(n).
// C = alpha * A @ op(B) + bias. A row-major [*,K].
// BT=false: B row-major [K,N]. BT=true: B row-major [N,K] (C = A @ B^T).
template<int BM, int BN, bool BT>
__device__ __forceinline__ void mma_gemm(
    const float* __restrict__ A, int lda,
    const float* __restrict__ B, int ldb,
    float* __restrict__ C, int ldc,
    int K, int m0, int n0,
    const float* __restrict__ bias, float alpha)
{
    constexpr int AS = BM + 8;      // strides ≡ 8 (mod 32) -> conflict-free frag loads
    constexpr int BS = BN + 8;
    constexpr int MT = BM / 32;     // m16 tiles per warp   (warp tile m = BM/2)
    constexpr int NT = BN / 32;     // n8 tiles per warp    (warp tile n = BN/4)
    __shared__ uint32_t As[16 * AS];   // [k][m]
    __shared__ uint32_t Bs[16 * BS];   // [k][n]

    const int tid  = threadIdx.x;
    const int lane = tid & 31, warp = tid >> 5;
    const int lr = lane >> 2, lc = lane & 3;
    const int wm0 = (warp >> 2) * (BM / 2);
    const int wn0 = (warp & 3) * (BN / 4);

    float acc[MT][NT][4];
    #pragma unroll
    for (int mi = 0; mi < MT; mi++)
        #pragma unroll
        for (int ni = 0; ni < NT; ni++)
            #pragma unroll
            for (int q = 0; q < 4; q++) acc[mi][ni][q] = 0.f;

    for (int k0 = 0; k0 < K; k0 += 16) {
        // A tile: BM rows x 16 k -> As[k][m] (tf32)
        #pragma unroll
        for (int idx = tid; idx < BM * 4; idx += 256) {
            int r = idx >> 2, kq = (idx & 3) << 2;
            const float4 v = *(const float4*)(A + (size_t)(m0 + r) * lda + k0 + kq);
            As[(kq + 0) * AS + r] = f2tf32(v.x);
            As[(kq + 1) * AS + r] = f2tf32(v.y);
            As[(kq + 2) * AS + r] = f2tf32(v.z);
            As[(kq + 3) * AS + r] = f2tf32(v.w);
        }
        if (!BT) {
            #pragma unroll
            for (int idx = tid; idx < 4 * BN; idx += 256) {
                int r = idx / (BN / 4), c = (idx % (BN / 4)) * 4;
                const float4 v = *(const float4*)(B + (size_t)(k0 + r) * ldb + n0 + c);
                Bs[r * BS + c + 0] = f2tf32(v.x);
                Bs[r * BS + c + 1] = f2tf32(v.y);
                Bs[r * BS + c + 2] = f2tf32(v.z);
                Bs[r * BS + c + 3] = f2tf32(v.w);
            }
        } else {
            #pragma unroll
            for (int idx = tid; idx < BN * 4; idx += 256) {
                int c = idx >> 2, kq = (idx & 3) << 2;
                const float4 v = *(const float4*)(B + (size_t)(n0 + c) * ldb + k0 + kq);
                Bs[(kq + 0) * BS + c] = f2tf32(v.x);
                Bs[(kq + 1) * BS + c] = f2tf32(v.y);
                Bs[(kq + 2) * BS + c] = f2tf32(v.z);
                Bs[(kq + 3) * BS + c] = f2tf32(v.w);
            }
        }
        __syncthreads();
        #pragma unroll
        for (int ks = 0; ks < 2; ks++) {
            const uint32_t* A0 = As + (ks * 8 + lc) * AS + wm0 + lr;
            const uint32_t* B0 = Bs + (ks * 8 + lc) * BS + wn0 + lr;
            uint32_t af[MT][4], bf[NT][2];
            #pragma unroll
            for (int mi = 0; mi < MT; mi++) {
                af[mi][0] = A0[mi * 16];
                af[mi][1] = A0[mi * 16 + 8];
                af[mi][2] = A0[4 * AS + mi * 16];
                af[mi][3] = A0[4 * AS + mi * 16 + 8];
            }
            #pragma unroll
            for (int ni = 0; ni < NT; ni++) {
                bf[ni][0] = B0[ni * 8];
                bf[ni][1] = B0[4 * BS + ni * 8];
            }
            #pragma unroll
            for (int mi = 0; mi < MT; mi++)
                #pragma unroll
                for (int ni = 0; ni < NT; ni++)
                    mma_tf32(acc[mi][ni], af[mi], bf[ni]);
        }
        __syncthreads();
    }
    // epilogue
    #pragma unroll
    for (int mi = 0; mi < MT; mi++) {
        int row = m0 + wm0 + mi * 16 + lr;
        #pragma unroll
        for (int ni = 0; ni < NT; ni++) {
            int col = n0 + wn0 + ni * 8 + 2 * lc;
            float bx = 0.f, by = 0.f;
            if (bias) { bx = bias[col]; by = bias[col + 1]; }
            float* cp = C + (size_t)row * ldc + col;
            cp[0] = acc[mi][ni][0] * alpha + bx;
            cp[1] = acc[mi][ni][1] * alpha + by;
            float* cq = C + (size_t)(row + 8) * ldc + col;
            cq[0] = acc[mi][ni][2] * alpha + bx;
            cq[1] = acc[mi][ni][3] * alpha + by;
        }
    }
}

// ---------------- kernels ----------------

// x[b,d,m,n] -> g_xt[(b*N+n)*M+m][d]
__global__ __launch_bounds__(256) void k_tr(const float* __restrict__ x) {
    __shared__ float tile[32][33];
    int zi = blockIdx.z;
    int b = zi >> 3, m = zi & 7;
    int n0 = blockIdx.x * 32, d0 = blockIdx.y * 32;
    #pragma unroll
    for (int r = 0; r < 4; r++) {
        int d = d0 + threadIdx.y + r * 8;
        int n = n0 + threadIdx.x;
        tile[threadIdx.y + r * 8][threadIdx.x] =
            x[((size_t)(b * ND + d) * NM + m) * NSEQ + n];
    }
    __syncthreads();
    #pragma unroll
    for (int r = 0; r < 4; r++) {
        int n = n0 + threadIdx.y + r * 8;
        int d = d0 + threadIdx.x;
        g_xt[((size_t)(b * NSEQ + n) * NM + m) * ND + d] = tile[threadIdx.x][threadIdx.y + r * 8];
    }
}

__global__ __launch_bounds__(256) void k_gemm_q(const float* __restrict__ Wq) {
    mma_gemm<128, 128, false>(g_xt, ND, Wq, NINNER, g_q, NINNER, ND,
                              blockIdx.y * 128, blockIdx.x * 128, nullptr, 1.f);
}
__global__ __launch_bounds__(256) void k_gemm_kv(const float* __restrict__ Wkv) {
    mma_gemm<128, 128, false>(g_xt, ND, Wkv, 2 * NINNER, g_kv, 2 * NINNER, ND,
                              blockIdx.y * 128, blockIdx.x * 128, nullptr, 1.f);
}

// S[e=(b,h,z)][(i,m), j] = 0.125 * Q'[(i,m),d] @ K_z[j,d]^T
__global__ __launch_bounds__(256) void k_sim() {
    int e = blockIdx.z;
    int z = e & 7, h = (e >> 3) & 7, b = e >> 6;
    const float* A = g_q  + (size_t)b * NSEQ * NM * NINNER + h * NDH;
    const float* B = g_kv + (size_t)b * NSEQ * NM * (2 * NINNER)
                   + (size_t)z * (2 * NINNER) + h * NDH;
    float* C = g_S + (size_t)e * (NSEQ * NM) * NSEQ;
    mma_gemm<128, 128, true>(A, NINNER, B, NM * 2 * NINNER, C, NSEQ, NDH,
                             blockIdx.y * 128, blockIdx.x * 128, nullptr, 0.125f);
}

// online softmax stats over i (stride 2048) for each (e, m, j)
__global__ __launch_bounds__(256) void k_stats() {
    int idx = blockIdx.x * 256 + threadIdx.x;
    int j = idx & 255, m = (idx >> 8) & 7, e = idx >> 11;
    const float* p = g_S + (size_t)e * (NSEQ * NM * NSEQ) + m * NSEQ + j;
    float mx = -3.4e38f, sm = 0.f;
    #pragma unroll 4
    for (int i = 0; i < NSEQ; i++) {
        float s = p[(size_t)i * (NM * NSEQ)];
        if (s > mx) { sm *= __expf(mx - s); mx = s; }
        sm += __expf(s - mx);
    }
    g_mx[idx] = mx;
    g_rs[idx] = 1.f / sm;
}

// O_z[i,d] = sum_{m,j} exp(S-mx[m,j])*rs[m,j] * V[(j,m),d]   (tf32 MMA, fused exp)
__global__ __launch_bounds__(256) void k_attnout() {
    constexpr int AS = 136, BS = 72;   // strides ≡ 8 (mod 32)
    __shared__ uint32_t As[16 * AS];   // [k=j][i]
    __shared__ uint32_t Bs[16 * BS];   // [k=j][d]
    __shared__ float mxs[256], rss[256];

    int e = blockIdx.z;
    int z = e & 7, h = (e >> 3) & 7, b = e >> 6;
    int i0 = blockIdx.x * 128;
    const float* Sb  = g_S  + (size_t)e * (NSEQ * NM * NSEQ);
    const float* Vb  = g_kv + (size_t)b * NSEQ * NM * (2 * NINNER) + NINNER + h * NDH;
    const float* mxb = g_mx + (size_t)e * (NM * NSEQ);
    const float* rsb = g_rs + (size_t)e * (NM * NSEQ);

    const int tid  = threadIdx.x;
    const int lane = tid & 31, warp = tid >> 5;
    const int lr = lane >> 2, lc = lane & 3;
    const int wm0 = (warp >> 2) * 64;   // i within block tile
    const int wn0 = (warp & 3) * 16;    // d within 64
    constexpr int MT = 4, NT = 2;

    float acc[MT][NT][4] = {};
    for (int m = 0; m < NM; m++) {
        mxs[tid] = mxb[m * NSEQ + tid];
        rss[tid] = rsb[m * NSEQ + tid];
        __syncthreads();
        for (int j0 = 0; j0 < NSEQ; j0 += 16) {
            // A: 128 i-rows x 16 j, exp-normalized, transposed to As[j][i]
            #pragma unroll
            for (int idx = tid; idx < 512; idx += 256) {
                int r = idx >> 2, kq = (idx & 3) << 2;
                const float4 s4 = *(const float4*)(Sb + ((size_t)(i0 + r) * 8 + m) * NSEQ + j0 + kq);
                As[(kq + 0) * AS + r] = f2tf32(__expf(s4.x - mxs[j0 + kq + 0]) * rss[j0 + kq + 0]);
                As[(kq + 1) * AS + r] = f2tf32(__expf(s4.y - mxs[j0 + kq + 1]) * rss[j0 + kq + 1]);
                As[(kq + 2) * AS + r] = f2tf32(__expf(s4.z - mxs[j0 + kq + 2]) * rss[j0 + kq + 2]);
                As[(kq + 3) * AS + r] = f2tf32(__expf(s4.w - mxs[j0 + kq + 3]) * rss[j0 + kq + 3]);
            }
            {   // B: 16 j x 64 d
                int r = tid >> 4, c = (tid & 15) << 2;
                const float4 v = *(const float4*)(Vb + (size_t)(j0 + r) * (NM * 2 * NINNER)
                                                  + m * (2 * NINNER) + c);
                Bs[r * BS + c + 0] = f2tf32(v.x);
                Bs[r * BS + c + 1] = f2tf32(v.y);
                Bs[r * BS + c + 2] = f2tf32(v.z);
                Bs[r * BS + c + 3] = f2tf32(v.w);
            }
            __syncthreads();
            #pragma unroll
            for (int ks = 0; ks < 2; ks++) {
                const uint32_t* A0 = As + (ks * 8 + lc) * AS + wm0 + lr;
                const uint32_t* B0 = Bs + (ks * 8 + lc) * BS + wn0 + lr;
                uint32_t af[MT][4], bf[NT][2];
                #pragma unroll
                for (int mi = 0; mi < MT; mi++) {
                    af[mi][0] = A0[mi * 16];
                    af[mi][1] = A0[mi * 16 + 8];
                    af[mi][2] = A0[4 * AS + mi * 16];
                    af[mi][3] = A0[4 * AS + mi * 16 + 8];
                }
                #pragma unroll
                for (int ni = 0; ni < NT; ni++) {
                    bf[ni][0] = B0[ni * 8];
                    bf[ni][1] = B0[4 * BS + ni * 8];
                }
                #pragma unroll
                for (int mi = 0; mi < MT; mi++)
                    #pragma unroll
                    for (int ni = 0; ni < NT; ni++)
                        mma_tf32(acc[mi][ni], af[mi], bf[ni]);
            }
            __syncthreads();
        }
    }
    float* Ob = g_ao + (size_t)(b * NSEQ) * 4096 + z * 512 + h * 64;
    #pragma unroll
    for (int mi = 0; mi < MT; mi++) {
        int row = i0 + wm0 + mi * 16 + lr;
        #pragma unroll
        for (int ni = 0; ni < NT; ni++) {
            int col = wn0 + ni * 8 + 2 * lc;
            float* cp = Ob + (size_t)row * 4096 + col;
            cp[0] = acc[mi][ni][0];
            cp[1] = acc[mi][ni][1];
            float* cq = Ob + (size_t)(row + 8) * 4096 + col;
            cq[0] = acc[mi][ni][2];
            cq[1] = acc[mi][ni][3];
        }
    }
}

__global__ __launch_bounds__(256) void k_gemm_wout(const float* __restrict__ W,
                                                   const float* __restrict__ bias) {
    mma_gemm<128, 128, false>(g_ao, 4096, W, 2048, g_y1, 2048, 4096,
                              blockIdx.y * 128, blockIdx.x * 128, bias, 1.f);
}

// residual + LayerNorm. mode 1: y from g_y1; mode 2: y from g_y2 -> out
__global__ __launch_bounds__(256) void k_ln(int mode,
                                            const float* __restrict__ g,
                                            const float* __restrict__ beta,
                                            float* __restrict__ out) {
    int t = blockIdx.x, d = threadIdx.x;
    float xv, yv;
    if (mode == 1) {
        int bn = t >> 3, m = t & 7;
        xv = g_xt[(size_t)t * ND + d];
        yv = g_y1[(size_t)bn * 2048 + m * ND + d];
    } else {
        xv = g_x2[(size_t)t * ND + d];
        yv = g_y2[(size_t)t * ND + d];
    }
    float v = xv + yv;
    float s = v, s2 = v * v;
    #pragma unroll
    for (int o = 16; o; o >>= 1) {
        s  += __shfl_xor_sync(0xffffffffu, s,  o);
        s2 += __shfl_xor_sync(0xffffffffu, s2, o);
    }
    __shared__ float sh[16];
    int w = d >> 5, l = d & 31;
    if (l == 0) { sh[w] = s; sh[8 + w] = s2; }
    __syncthreads();
    if (d == 0) {
        float ts = 0.f, ts2 = 0.f;
        #pragma unroll
        for (int i = 0; i < 8; i++) { ts += sh[i]; ts2 += sh[8 + i]; }
        float mu  = ts * (1.f / 256.f);
        float var = ts2 * (1.f / 256.f) - mu * mu;
        sh[0] = mu;
        sh[1] = rsqrtf(var + 1e-5f);
    }
    __syncthreads();
    float mu = sh[0], rstd = sh[1];
    float r = (v - mu) * rstd * g[d] + beta[d];
    if (mode == 1) g_x2[(size_t)t * ND + d] = r;
    else           out[(size_t)t * ND + d] = r;
}

__global__ __launch_bounds__(256) void k_gemm_ff1(const float* __restrict__ W,
                                                  const float* __restrict__ bias) {
    mma_gemm<128, 128, false>(g_x2, ND, W, 2048, g_hf, 2048, ND,
                              blockIdx.y * 128, blockIdx.x * 128, bias, 1.f);
}

__global__ __launch_bounds__(256) void k_geglu() {
    int idx = blockIdx.x * 256 + threadIdx.x;
    int t = idx >> 10, c = idx & 1023;
    float a = g_hf[(size_t)t * 2048 + c];
    float gt = g_hf[(size_t)t * 2048 + 1024 + c];
    g_fi[idx] = a * 0.5f * gt * (1.f + erff(gt * 0.70710678118654752f));
}

__global__ __launch_bounds__(256) void k_gemm_ff2(const float* __restrict__ W,
                                                  const float* __restrict__ bias) {
    mma_gemm<128, 128, false>(g_fi, 1024, W, ND, g_y2, ND, 1024,
                              blockIdx.y * 128, blockIdx.x * 128, bias, 1.f);
}

// ---------------- launch ----------------
extern "C" void kernel_launch(void* const* d_in, const int* in_sizes, int n_in,
                              void* d_out, int out_size) {
    const float* x     = (const float*)d_in[0];
    const float* Wq    = (const float*)d_in[1];
    const float* Wkv   = (const float*)d_in[2];
    const float* Wout  = (const float*)d_in[3];
    const float* bout  = (const float*)d_in[4];
    const float* g1    = (const float*)d_in[5];
    const float* beta1 = (const float*)d_in[6];
    const float* Wff1  = (const float*)d_in[7];
    const float* bff1  = (const float*)d_in[8];
    const float* Wff2  = (const float*)d_in[9];
    const float* bff2  = (const float*)d_in[10];
    const float* g2    = (const float*)d_in[11];
    const float* beta2 = (const float*)d_in[12];
    float* out = (float*)d_out;

    k_tr       <<<dim3(8, 8, 16),   dim3(32, 8)>>>(x);
    k_gemm_q   <<<dim3(4, 32),      256>>>(Wq);           // [4096,256]@[256,512]
    k_gemm_kv  <<<dim3(8, 32),      256>>>(Wkv);          // [4096,256]@[256,1024]
    k_sim      <<<dim3(2, 16, 128), 256>>>();             // 128 x [2048,64]@[64,256]^T
    k_stats    <<<1024,             256>>>();             // softmax over i
    k_attnout  <<<dim3(2, 1, 128),  256>>>();             // fused exp-GEMM -> [256,64] x128
    k_gemm_wout<<<dim3(16, 4),      256>>>(Wout, bout);   // [512,4096]@[4096,2048]
    k_ln       <<<4096,             256>>>(1, g1, beta1, nullptr);
    k_gemm_ff1 <<<dim3(16, 32),     256>>>(Wff1, bff1);   // [4096,256]@[256,2048]
    k_geglu    <<<16384,            256>>>();
    k_gemm_ff2 <<<dim3(2, 32),      256>>>(Wff2, bff2);   // [4096,1024]@[1024,256]
    k_ln       <<<4096,             256>>>(2, g2, beta2, out);
}

// round 3
// speedup vs baseline: 3.3596x; 2.4836x over previous
#include <cuda_runtime.h>
#include <cuda_bf16.h>
#include <math.h>
#include <stdint.h>

#define NB     2
#define NSEQ   256
#define NM     8
#define ND     256
#define NH     8
#define NDH    64
#define NINNER 512
#define NTOK   (NB*NSEQ*NM)          // 4096
#define NBN    (NB*NSEQ)             // 512
typedef __nv_bfloat16 bf16;
typedef __nv_bfloat162 bf162;

// ---------------- scratch ----------------
__device__ float g_xt [NTOK*ND];                       // fp32 (residual)
__device__ bf16  g_xtb[NTOK*ND];
__device__ bf16  g_qb [NTOK*NINNER];
__device__ bf16  g_kvb[NTOK*2*NINNER];
__device__ bf16  g_P  [(size_t)128*2048*256];          // exp(S) unnormalized, 134MB
__device__ float g_sum[128*2048];                      // per (e,m,j) exp-sum
__device__ bf16  g_aob[(size_t)NBN*4096];
__device__ float g_y1 [(size_t)NBN*2048];
__device__ float g_x2 [NTOK*ND];
__device__ bf16  g_x2b[NTOK*ND];
__device__ float g_hf [(size_t)NTOK*2048];
__device__ bf16  g_fib[(size_t)NTOK*1024];
__device__ float g_y2 [NTOK*ND];
// bf16 weights
__device__ bf16  g_Wq  [256*512];
__device__ bf16  g_Wkv [256*1024];
__device__ bf16  g_Wout[(size_t)4096*2048];
__device__ bf16  g_Wff1[256*2048];
__device__ bf16  g_Wff2[1024*256];

// ---------------- ptx helpers ----------------
__device__ __forceinline__ uint32_t smaddr(const void* p) {
    return (uint32_t)__cvta_generic_to_shared(p);
}
__device__ __forceinline__ void cpa16(uint32_t dst, const void* src) {
    asm volatile("cp.async.cg.shared.global [%0], [%1], 16;\n" :: "r"(dst), "l"(src) : "memory");
}
__device__ __forceinline__ void cpa_commit() { asm volatile("cp.async.commit_group;\n" ::: "memory"); }
__device__ __forceinline__ void cpa_wait0()  { asm volatile("cp.async.wait_group 0;\n" ::: "memory"); }

__device__ __forceinline__ void ldsm4(uint32_t& r0, uint32_t& r1, uint32_t& r2, uint32_t& r3, uint32_t a) {
    asm volatile("ldmatrix.sync.aligned.m8n8.x4.shared.b16 {%0,%1,%2,%3}, [%4];"
                 : "=r"(r0), "=r"(r1), "=r"(r2), "=r"(r3) : "r"(a));
}
__device__ __forceinline__ void ldsm2(uint32_t& r0, uint32_t& r1, uint32_t a) {
    asm volatile("ldmatrix.sync.aligned.m8n8.x2.shared.b16 {%0,%1}, [%2];"
                 : "=r"(r0), "=r"(r1) : "r"(a));
}
__device__ __forceinline__ void ldsm2t(uint32_t& r0, uint32_t& r1, uint32_t a) {
    asm volatile("ldmatrix.sync.aligned.m8n8.x2.trans.shared.b16 {%0,%1}, [%2];"
                 : "=r"(r0), "=r"(r1) : "r"(a));
}
__device__ __forceinline__ void mma_bf16(float* c, const uint32_t* a, const uint32_t* b) {
    asm volatile(
        "mma.sync.aligned.m16n8k16.row.col.f32.bf16.bf16.f32 "
        "{%0,%1,%2,%3}, {%4,%5,%6,%7}, {%8,%9}, {%0,%1,%2,%3};\n"
        : "+f"(c[0]), "+f"(c[1]), "+f"(c[2]), "+f"(c[3])
        : "r"(a[0]), "r"(a[1]), "r"(a[2]), "r"(a[3]), "r"(b[0]), "r"(b[1]));
}

// exp via FMA-pipe polynomial (avoids MUFU bottleneck). |x| small here.
__device__ __forceinline__ float fexp(float x) {
    float n = rintf(x * 1.4426950408889634f);
    n = fminf(fmaxf(n, -80.f), 80.f);
    float f = fmaf(n, -0.6931471805599453f, x);   // x - n*ln2, |f| <= 0.3466
    float p = fmaf(f, 1.f/120.f, 1.f/24.f);
    p = fmaf(f, p, 1.f/6.f);
    p = fmaf(f, p, 0.5f);
    p = fmaf(f, p, 1.0f);
    p = fmaf(f, p, 1.0f);
    float s = __int_as_float(((int)n + 127) << 23);
    return p * s;
}

// ---------------- GEMM building blocks ----------------
// A smem: [BM rows][80B]  (32 bf16 + pad).  B smem: BT ? [BN][80B] : [32][BN*2+16].
// Strides 80/144/272 = 16*odd  -> 8 consecutive ldmatrix rows hit distinct 16B groups.

template<int BM, int BN, bool BT>
__device__ __forceinline__ void g2s(const bf16* __restrict__ A, int lda,
                                    const bf16* __restrict__ B, int ldb,
                                    int m0, int n0, int k0,
                                    uint32_t aB, uint32_t bB, int tid)
{
    #pragma unroll
    for (int i = tid; i < BM * 4; i += 256) {
        int r = i >> 2, c = i & 3;
        cpa16(aB + r * 80 + c * 16, A + (size_t)(m0 + r) * lda + k0 + c * 8);
    }
    if (BT) {
        #pragma unroll
        for (int i = tid; i < BN * 4; i += 256) {
            int r = i >> 2, c = i & 3;
            cpa16(bB + r * 80 + c * 16, B + (size_t)(n0 + r) * ldb + k0 + c * 8);
        }
    } else {
        constexpr int NC = BN / 8, SBv = BN * 2 + 16;
        #pragma unroll
        for (int i = tid; i < 32 * NC; i += 256) {
            int kr = i / NC, c = i % NC;
            cpa16(bB + kr * SBv + c * 16, B + (size_t)(k0 + kr) * ldb + n0 + c * 8);
        }
    }
    cpa_commit();
}

template<int BM, int BN, bool BT>
__device__ __forceinline__ void smma(uint32_t aB, uint32_t bB, int lane,
                                     int wm0, int wn0, float acc[][BN/32][4])
{
    constexpr int MT = BM / 32, NT = BN / 32, SBv = BT ? 80 : (BN * 2 + 16);
    #pragma unroll
    for (int s = 0; s < 2; s++) {
        uint32_t af[MT][4], bf2[NT][2];
        #pragma unroll
        for (int mi = 0; mi < MT; mi++)
            ldsm4(af[mi][0], af[mi][1], af[mi][2], af[mi][3],
                  aB + (wm0 + mi * 16 + (lane & 15)) * 80 + s * 32 + (lane & 16));
        #pragma unroll
        for (int ni = 0; ni < NT; ni++) {
            if (BT)
                ldsm2(bf2[ni][0], bf2[ni][1],
                      bB + (wn0 + ni * 8 + (lane & 7)) * 80 + s * 32 + ((lane >> 3) & 1) * 16);
            else
                ldsm2t(bf2[ni][0], bf2[ni][1],
                       bB + (s * 16 + (lane & 15)) * SBv + (wn0 + ni * 8) * 2);
        }
        #pragma unroll
        for (int mi = 0; mi < MT; mi++)
            #pragma unroll
            for (int ni = 0; ni < NT; ni++)
                mma_bf16(acc[mi][ni], af[mi], bf2[ni]);
    }
}

// full pipelined mainloop: acc += A[m0: ,:K] @ op(B)
template<int BM, int BN, bool BT>
__device__ __forceinline__ void mma_loop(const bf16* __restrict__ A, int lda,
                                         const bf16* __restrict__ B, int ldb,
                                         int K, int m0, int n0,
                                         float acc[][BN/32][4])
{
    constexpr int SBv  = BT ? 80 : (BN * 2 + 16);
    constexpr int BROW = BT ? BN : 32;
    __shared__ alignas(16) unsigned char sA[2][BM * 80];
    __shared__ alignas(16) unsigned char sB[2][BROW * SBv];
    const int tid = threadIdx.x, lane = tid & 31, warp = tid >> 5;
    const int wm0 = (warp >> 2) * (BM / 2), wn0 = (warp & 3) * (BN / 4);
    uint32_t aB0 = smaddr(sA[0]), aB1 = smaddr(sA[1]);
    uint32_t bB0 = smaddr(sB[0]), bB1 = smaddr(sB[1]);

    g2s<BM, BN, BT>(A, lda, B, ldb, m0, n0, 0, aB0, bB0, tid);
    const int nch = K >> 5;
    for (int i = 0; i < nch; i++) {
        cpa_wait0();
        __syncthreads();
        uint32_t aB = (i & 1) ? aB1 : aB0, bB = (i & 1) ? bB1 : bB0;
        if (i + 1 < nch)
            g2s<BM, BN, BT>(A, lda, B, ldb, m0, n0, (i + 1) * 32,
                            (i & 1) ? aB0 : aB1, (i & 1) ? bB0 : bB1, tid);
        smma<BM, BN, BT>(aB, bB, lane, wm0, wn0, acc);
        __syncthreads();
    }
}

// ---------------- epilogue helpers ----------------
template<int BM, int BN>
__device__ __forceinline__ void epi_f32(float acc[][BN/32][4], float* C, int ldc,
                                        int m0, int n0, const float* bias)
{
    const int lane = threadIdx.x & 31, warp = threadIdx.x >> 5;
    const int lr = lane >> 2, lc = lane & 3;
    const int wm0 = (warp >> 2) * (BM / 2), wn0 = (warp & 3) * (BN / 4);
    #pragma unroll
    for (int mi = 0; mi < BM / 32; mi++) {
        int row = m0 + wm0 + mi * 16 + lr;
        #pragma unroll
        for (int ni = 0; ni < BN / 32; ni++) {
            int col = n0 + wn0 + ni * 8 + 2 * lc;
            float bx = 0.f, by = 0.f;
            if (bias) { bx = bias[col]; by = bias[col + 1]; }
            *(float2*)(C + (size_t)row * ldc + col) =
                make_float2(acc[mi][ni][0] + bx, acc[mi][ni][1] + by);
            *(float2*)(C + (size_t)(row + 8) * ldc + col) =
                make_float2(acc[mi][ni][2] + bx, acc[mi][ni][3] + by);
        }
    }
}

template<int BM, int BN>
__device__ __forceinline__ void epi_bf16(float acc[][BN/32][4], bf16* C, int ldc,
                                         int m0, int n0)
{
    const int lane = threadIdx.x & 31, warp = threadIdx.x >> 5;
    const int lr = lane >> 2, lc = lane & 3;
    const int wm0 = (warp >> 2) * (BM / 2), wn0 = (warp & 3) * (BN / 4);
    #pragma unroll
    for (int mi = 0; mi < BM / 32; mi++) {
        int row = m0 + wm0 + mi * 16 + lr;
        #pragma unroll
        for (int ni = 0; ni < BN / 32; ni++) {
            int col = n0 + wn0 + ni * 8 + 2 * lc;
            *(bf162*)(C + (size_t)row * ldc + col) =
                __floats2bfloat162_rn(acc[mi][ni][0], acc[mi][ni][1]);
            *(bf162*)(C + (size_t)(row + 8) * ldc + col) =
                __floats2bfloat162_rn(acc[mi][ni][2], acc[mi][ni][3]);
        }
    }
}

// ---------------- kernels ----------------

__global__ __launch_bounds__(256) void k_cvt(const float4* __restrict__ src,
                                             bf162* __restrict__ dst, int n4) {
    int i = blockIdx.x * 256 + threadIdx.x;
    if (i < n4) {
        float4 v = src[i];
        dst[2 * i]     = __floats2bfloat162_rn(v.x, v.y);
        dst[2 * i + 1] = __floats2bfloat162_rn(v.z, v.w);
    }
}

__global__ __launch_bounds__(256) void k_zero() {
    int i = blockIdx.x * 256 + threadIdx.x;
    ((float4*)g_sum)[i] = make_float4(0.f, 0.f, 0.f, 0.f);
}

// x[b,d,m,n] -> g_xt / g_xtb [(b*N+n)*M+m][d]
__global__ __launch_bounds__(256) void k_tr(const float* __restrict__ x) {
    __shared__ float tile[32][33];
    int zi = blockIdx.z;
    int b = zi >> 3, m = zi & 7;
    int n0 = blockIdx.x * 32, d0 = blockIdx.y * 32;
    #pragma unroll
    for (int r = 0; r < 4; r++) {
        int d = d0 + threadIdx.y + r * 8;
        tile[threadIdx.y + r * 8][threadIdx.x] =
            x[((size_t)(b * ND + d) * NM + m) * NSEQ + n0 + threadIdx.x];
    }
    __syncthreads();
    #pragma unroll
    for (int r = 0; r < 4; r++) {
        int n = n0 + threadIdx.y + r * 8;
        int d = d0 + threadIdx.x;
        float v = tile[threadIdx.x][threadIdx.y + r * 8];
        size_t o = ((size_t)(b * NSEQ + n) * NM + m) * ND + d;
        g_xt[o]  = v;
        g_xtb[o] = __float2bfloat16(v);
    }
}

__global__ __launch_bounds__(256) void k_q() {
    float acc[4][4][4] = {};
    int m0 = blockIdx.y * 128, n0 = blockIdx.x * 128;
    mma_loop<128, 128, false>(g_xtb, ND, g_Wq, NINNER, ND, m0, n0, acc);
    epi_bf16<128, 128>(acc, g_qb, NINNER, m0, n0);
}
__global__ __launch_bounds__(256) void k_kv() {
    float acc[4][4][4] = {};
    int m0 = blockIdx.y * 128, n0 = blockIdx.x * 128;
    mma_loop<128, 128, false>(g_xtb, ND, g_Wkv, 2 * NINNER, ND, m0, n0, acc);
    epi_bf16<128, 128>(acc, g_kvb, 2 * NINNER, m0, n0);
}

// P[e][(i*8+m)*256+j] = exp(0.125*Q'K^T), plus atomic exp-sums per (e,m,j)
__global__ __launch_bounds__(256) void k_sim() {
    float acc[4][4][4] = {};
    int e = blockIdx.z;
    int z = e & 7, h = (e >> 3) & 7, b = e >> 6;
    int m0 = blockIdx.y * 128, n0 = blockIdx.x * 128;
    const bf16* A = g_qb  + (size_t)b * 2048 * NINNER + h * NDH;
    const bf16* B = g_kvb + ((size_t)b * 2048 + z) * (2 * NINNER) + h * NDH;
    mma_loop<128, 128, true>(A, NINNER, B, NM * 2 * NINNER, NDH, m0, n0, acc);

    const int lane = threadIdx.x & 31, warp = threadIdx.x >> 5;
    const int lr = lane >> 2, lc = lane & 3;
    const int wm0 = (warp >> 2) * 64, wn0 = (warp & 3) * 32;
    bf16* Pb = g_P + (size_t)e * 524288;
    float* sumb = g_sum + (size_t)e * 2048 + lr * 256;   // m == lr for this thread
    #pragma unroll
    for (int ni = 0; ni < 4; ni++) {
        int col = n0 + wn0 + ni * 8 + 2 * lc;
        float s0 = 0.f, s1 = 0.f;
        #pragma unroll
        for (int mi = 0; mi < 4; mi++) {
            int row = m0 + wm0 + mi * 16 + lr;
            float p0 = fexp(0.125f * acc[mi][ni][0]);
            float p1 = fexp(0.125f * acc[mi][ni][1]);
            float p2 = fexp(0.125f * acc[mi][ni][2]);
            float p3 = fexp(0.125f * acc[mi][ni][3]);
            s0 += p0 + p2; s1 += p1 + p3;
            *(bf162*)(Pb + (size_t)row * 256 + col)       = __floats2bfloat162_rn(p0, p1);
            *(bf162*)(Pb + (size_t)(row + 8) * 256 + col) = __floats2bfloat162_rn(p2, p3);
        }
        atomicAdd(sumb + col, s0);
        atomicAdd(sumb + col + 1, s1);
    }
}

// O = (P * rs) @ V   fused normalize, bf16 MMA
__global__ __launch_bounds__(256) void k_attnout() {
    constexpr int SBv = 144;
    __shared__ alignas(16) unsigned char sA[2][128 * 80];
    __shared__ alignas(16) unsigned char sB[2][32 * SBv];
    __shared__ float rsAll[2048];
    int e = blockIdx.y;
    int z = e & 7, h = (e >> 3) & 7, b = e >> 6;
    int i0 = blockIdx.x * 128;
    const bf16* Pb = g_P + (size_t)e * 524288;
    const bf16* Vb = g_kvb + (size_t)b * 2048 * 1024 + 512 + h * 64;
    const int tid = threadIdx.x, lane = tid & 31, warp = tid >> 5;
    const int wm0 = (warp >> 2) * 64, wn0 = (warp & 3) * 16;
    uint32_t aB[2] = { smaddr(sA[0]), smaddr(sA[1]) };
    uint32_t bB[2] = { smaddr(sB[0]), smaddr(sB[1]) };

    for (int i = tid; i < 2048; i += 256)
        rsAll[i] = 1.0f / g_sum[(size_t)e * 2048 + i];

    // A reg staging: thread covers ops {tid, tid+256}: r = idx>>2, c = idx&3
    uint4 ar[2];
    auto gloadA = [&](int m, int j0, uint4* dst) {
        #pragma unroll
        for (int o = 0; o < 2; o++) {
            int idx = tid + o * 256;
            int r = idx >> 2, c = idx & 3;
            dst[o] = *(const uint4*)(Pb + ((size_t)(i0 + r) * 8 + m) * 256 + j0 + c * 8);
        }
    };
    auto loadB = [&](int m, int j0, uint32_t bb) {
        int kr = tid >> 3, c = tid & 7;   // 32 rows x 8 chunks = 256 ops
        cpa16(bb + kr * SBv + c * 16,
              Vb + ((size_t)(j0 + kr) * 8 + m) * 1024 + c * 8);
        cpa_commit();
    };
    auto storeA = [&](int m, int j0, const uint4* src, uint32_t ab) {
        #pragma unroll
        for (int o = 0; o < 2; o++) {
            int idx = tid + o * 256;
            int r = idx >> 2, c = idx & 3;
            const bf162* pp = (const bf162*)&src[o];
            uint4 outv;
            bf162* oo = (bf162*)&outv;
            #pragma unroll
            for (int q = 0; q < 4; q++) {
                float2 f = __bfloat1622float2(pp[q]);
                f.x *= rsAll[m * 256 + j0 + c * 8 + 2 * q];
                f.y *= rsAll[m * 256 + j0 + c * 8 + 2 * q + 1];
                oo[q] = __float22bfloat162_rn(f);
            }
            *(uint4*)((unsigned char*)nullptr + 0) = outv;  // placeholder (replaced below)
        }
    };
    (void)storeA;  // not used; inline below for smem addressing

    float acc[4][2][4] = {};
    gloadA(0, 0, ar);
    loadB(0, 0, bB[0]);
    for (int i = 0; i < 64; i++) {
        int m = i >> 3, j0 = (i & 7) * 32;
        cpa_wait0();
        __syncthreads();
        // store staged A (with rs fold) into smem buffer i&1
        {
            uint32_t ab = aB[i & 1];
            #pragma unroll
            for (int o = 0; o < 2; o++) {
                int idx = tid + o * 256;
                int r = idx >> 2, c = idx & 3;
                const bf162* pp = (const bf162*)&ar[o];
                uint32_t outv[4];
                #pragma unroll
                for (int q = 0; q < 4; q++) {
                    float2 f = __bfloat1622float2(pp[q]);
                    f.x *= rsAll[m * 256 + j0 + c * 8 + 2 * q];
                    f.y *= rsAll[m * 256 + j0 + c * 8 + 2 * q + 1];
                    bf162 bb2 = __float22bfloat162_rn(f);
                    outv[q] = *(uint32_t*)&bb2;
                }
                asm volatile("st.shared.v4.b32 [%0], {%1,%2,%3,%4};\n"
                             :: "r"(ab + r * 80 + c * 16),
                                "r"(outv[0]), "r"(outv[1]), "r"(outv[2]), "r"(outv[3]) : "memory");
            }
        }
        if (i + 1 < 64) {
            int m2 = (i + 1) >> 3, j02 = ((i + 1) & 7) * 32;
            gloadA(m2, j02, ar);
            loadB(m2, j02, bB[(i + 1) & 1]);
        }
        __syncthreads();
        // compute chunk i
        {
            uint32_t a = aB[i & 1], bb = bB[i & 1];
            #pragma unroll
            for (int s = 0; s < 2; s++) {
                uint32_t af[4][4], bf2[2][2];
                #pragma unroll
                for (int mi = 0; mi < 4; mi++)
                    ldsm4(af[mi][0], af[mi][1], af[mi][2], af[mi][3],
                          a + (wm0 + mi * 16 + (lane & 15)) * 80 + s * 32 + (lane & 16));
                #pragma unroll
                for (int ni = 0; ni < 2; ni++)
                    ldsm2t(bf2[ni][0], bf2[ni][1],
                           bb + (s * 16 + (lane & 15)) * SBv + (wn0 + ni * 8) * 2);
                #pragma unroll
                for (int mi = 0; mi < 4; mi++)
                    #pragma unroll
                    for (int ni = 0; ni < 2; ni++)
                        mma_bf16(acc[mi][ni], af[mi], bf2[ni]);
            }
        }
    }
    // epilogue -> g_aob bf16
    const int lr = lane >> 2, lc = lane & 3;
    bf16* Ob = g_aob + (size_t)(b * 256) * 4096 + z * 512 + h * 64;
    #pragma unroll
    for (int mi = 0; mi < 4; mi++) {
        int row = i0 + wm0 + mi * 16 + lr;
        #pragma unroll
        for (int ni = 0; ni < 2; ni++) {
            int col = wn0 + ni * 8 + 2 * lc;
            *(bf162*)(Ob + (size_t)row * 4096 + col) =
                __floats2bfloat162_rn(acc[mi][ni][0], acc[mi][ni][1]);
            *(bf162*)(Ob + (size_t)(row + 8) * 4096 + col) =
                __floats2bfloat162_rn(acc[mi][ni][2], acc[mi][ni][3]);
        }
    }
}

__global__ __launch_bounds__(256) void k_wout(const float* __restrict__ bias) {
    float acc[4][2][4] = {};
    int m0 = blockIdx.y * 128, n0 = blockIdx.x * 64;
    mma_loop<128, 64, false>(g_aob, 4096, g_Wout, 2048, 4096, m0, n0, acc);
    epi_f32<128, 64>(acc, g_y1, 2048, m0, n0, bias);
}

__global__ __launch_bounds__(256) void k_ln(int mode,
                                            const float* __restrict__ g,
                                            const float* __restrict__ beta,
                                            float* __restrict__ out) {
    int t = blockIdx.x, d = threadIdx.x;
    float xv, yv;
    if (mode == 1) {
        int bn = t >> 3, m = t & 7;
        xv = g_xt[(size_t)t * ND + d];
        yv = g_y1[(size_t)bn * 2048 + m * ND + d];
    } else {
        xv = g_x2[(size_t)t * ND + d];
        yv = g_y2[(size_t)t * ND + d];
    }
    float v = xv + yv;
    float s = v, s2 = v * v;
    #pragma unroll
    for (int o = 16; o; o >>= 1) {
        s  += __shfl_xor_sync(0xffffffffu, s,  o);
        s2 += __shfl_xor_sync(0xffffffffu, s2, o);
    }
    __shared__ float sh[16];
    int w = d >> 5, l = d & 31;
    if (l == 0) { sh[w] = s; sh[8 + w] = s2; }
    __syncthreads();
    if (d == 0) {
        float ts = 0.f, ts2 = 0.f;
        #pragma unroll
        for (int i = 0; i < 8; i++) { ts += sh[i]; ts2 += sh[8 + i]; }
        float mu  = ts * (1.f / 256.f);
        float var = ts2 * (1.f / 256.f) - mu * mu;
        sh[0] = mu;
        sh[1] = rsqrtf(var + 1e-5f);
    }
    __syncthreads();
    float r = (v - sh[0]) * sh[1] * g[d] + beta[d];
    if (mode == 1) {
        g_x2 [(size_t)t * ND + d] = r;
        g_x2b[(size_t)t * ND + d] = __float2bfloat16(r);
    } else {
        out[(size_t)t * ND + d] = r;
    }
}

__global__ __launch_bounds__(256) void k_ff1(const float* __restrict__ bias) {
    float acc[4][4][4] = {};
    int m0 = blockIdx.y * 128, n0 = blockIdx.x * 128;
    mma_loop<128, 128, false>(g_x2b, ND, g_Wff1, 2048, ND, m0, n0, acc);
    epi_f32<128, 128>(acc, g_hf, 2048, m0, n0, bias);
}

__global__ __launch_bounds__(256) void k_geglu() {
    int idx = blockIdx.x * 256 + threadIdx.x;
    int t = idx >> 10, c = idx & 1023;
    float a  = g_hf[(size_t)t * 2048 + c];
    float gt = g_hf[(size_t)t * 2048 + 1024 + c];
    float v = a * 0.5f * gt * (1.f + erff(gt * 0.70710678118654752f));
    g_fib[idx] = __float2bfloat16(v);
}

__global__ __launch_bounds__(256) void k_ff2(const float* __restrict__ bias) {
    float acc[4][2][4] = {};
    int m0 = blockIdx.y * 128, n0 = blockIdx.x * 64;
    mma_loop<128, 64, false>(g_fib, 1024, g_Wff2, ND, 1024, m0, n0, acc);
    epi_f32<128, 64>(acc, g_y2, ND, m0, n0, bias);
}

// ---------------- launch ----------------
extern "C" void kernel_launch(void* const* d_in, const int* in_sizes, int n_in,
                              void* d_out, int out_size) {
    const float* x     = (const float*)d_in[0];
    const float* Wq    = (const float*)d_in[1];
    const float* Wkv   = (const float*)d_in[2];
    const float* Wout  = (const float*)d_in[3];
    const float* bout  = (const float*)d_in[4];
    const float* g1    = (const float*)d_in[5];
    const float* beta1 = (const float*)d_in[6];
    const float* Wff1  = (const float*)d_in[7];
    const float* bff1  = (const float*)d_in[8];
    const float* Wff2  = (const float*)d_in[9];
    const float* bff2  = (const float*)d_in[10];
    const float* g2    = (const float*)d_in[11];
    const float* beta2 = (const float*)d_in[12];
    float* out = (float*)d_out;

    bf162* wq_d;   cudaGetSymbolAddress((void**)&wq_d,  g_Wq);
    bf162* wkv_d;  cudaGetSymbolAddress((void**)&wkv_d, g_Wkv);
    bf162* wo_d;   cudaGetSymbolAddress((void**)&wo_d,  g_Wout);
    bf162* w1_d;   cudaGetSymbolAddress((void**)&w1_d,  g_Wff1);
    bf162* w2_d;   cudaGetSymbolAddress((void**)&w2_d,  g_Wff2);

    k_cvt<<<(256*512/4 + 255)/256, 256>>>((const float4*)Wq,   wq_d,  256*512/4);
    k_cvt<<<(256*1024/4 + 255)/256, 256>>>((const float4*)Wkv, wkv_d, 256*1024/4);
    k_cvt<<<(4096*2048/4 + 255)/256, 256>>>((const float4*)Wout, wo_d, 4096*2048/4);
    k_cvt<<<(256*2048/4 + 255)/256, 256>>>((const float4*)Wff1, w1_d, 256*2048/4);
    k_cvt<<<(1024*256/4 + 255)/256, 256>>>((const float4*)Wff2, w2_d, 1024*256/4);
    k_zero<<<256, 256>>>();
    k_tr<<<dim3(8, 8, 16), dim3(32, 8)>>>(x);

    k_q   <<<dim3(4, 32),       256>>>();
    k_kv  <<<dim3(8, 32),       256>>>();
    k_sim <<<dim3(2, 16, 128),  256>>>();
    k_attnout<<<dim3(2, 128),   256>>>();
    k_wout<<<dim3(32, 4),       256>>>(bout);
    k_ln  <<<4096, 256>>>(1, g1, beta1, nullptr);
    k_ff1 <<<dim3(16, 32),      256>>>(bff1);
    k_geglu<<<16384, 256>>>();
    k_ff2 <<<dim3(4, 32),       256>>>(bff2);
    k_ln  <<<4096, 256>>>(2, g2, beta2, out);
}

// round 6
// speedup vs baseline: 3.7054x; 1.1029x over previous
#include <cuda_runtime.h>
#include <cuda_bf16.h>
#include <math.h>
#include <stdint.h>

#define NB     2
#define NSEQ   256
#define NM     8
#define ND     256
#define NH     8
#define NDH    64
#define NINNER 512
#define NTOK   (NB*NSEQ*NM)          // 4096
#define NBN    (NB*NSEQ)             // 512
typedef __nv_bfloat16 bf16;
typedef __nv_bfloat162 bf162;

// ---------------- scratch ----------------
__device__ float g_xt [NTOK*ND];                       // fp32 (residual)
__device__ bf16  g_xtb[NTOK*ND];
__device__ bf16  g_qb [NTOK*NINNER];
__device__ bf16  g_kvb[NTOK*2*NINNER];
__device__ bf16  g_P  [(size_t)128*256*2048];          // exp(S): [e][i][m*256+j], 134MB
__device__ float g_sum[128*2048];                      // per (e, m*256+j) exp-sum
__device__ bf16  g_vp [(size_t)128*2048*64];           // rs-scaled V': [e][m*256+j][d], 33.5MB
__device__ bf16  g_aob[(size_t)NBN*4096];
__device__ float g_y1 [(size_t)NBN*2048];
__device__ float g_x2 [NTOK*ND];
__device__ bf16  g_x2b[NTOK*ND];
__device__ bf16  g_fib[(size_t)NTOK*1024];
__device__ float g_y2 [NTOK*ND];
// bf16 weights
__device__ bf16  g_Wq  [256*512];
__device__ bf16  g_Wkv [256*1024];
__device__ bf16  g_Wout[(size_t)4096*2048];
__device__ bf16  g_Wff1[256*2048];
__device__ bf16  g_Wff2[1024*256];

// ---------------- ptx helpers ----------------
__device__ __forceinline__ uint32_t smaddr(const void* p) {
    return (uint32_t)__cvta_generic_to_shared(p);
}
__device__ __forceinline__ void cpa16(uint32_t dst, const void* src) {
    asm volatile("cp.async.cg.shared.global [%0], [%1], 16;\n" :: "r"(dst), "l"(src) : "memory");
}
__device__ __forceinline__ void cpa_commit() { asm volatile("cp.async.commit_group;\n" ::: "memory"); }
__device__ __forceinline__ void cpa_wait0()  { asm volatile("cp.async.wait_group 0;\n" ::: "memory"); }

__device__ __forceinline__ void ldsm4(uint32_t& r0, uint32_t& r1, uint32_t& r2, uint32_t& r3, uint32_t a) {
    asm volatile("ldmatrix.sync.aligned.m8n8.x4.shared.b16 {%0,%1,%2,%3}, [%4];"
                 : "=r"(r0), "=r"(r1), "=r"(r2), "=r"(r3) : "r"(a));
}
__device__ __forceinline__ void ldsm2(uint32_t& r0, uint32_t& r1, uint32_t a) {
    asm volatile("ldmatrix.sync.aligned.m8n8.x2.shared.b16 {%0,%1}, [%2];"
                 : "=r"(r0), "=r"(r1) : "r"(a));
}
__device__ __forceinline__ void ldsm2t(uint32_t& r0, uint32_t& r1, uint32_t a) {
    asm volatile("ldmatrix.sync.aligned.m8n8.x2.trans.shared.b16 {%0,%1}, [%2];"
                 : "=r"(r0), "=r"(r1) : "r"(a));
}
__device__ __forceinline__ void mma_bf16(float* c, const uint32_t* a, const uint32_t* b) {
    asm volatile(
        "mma.sync.aligned.m16n8k16.row.col.f32.bf16.bf16.f32 "
        "{%0,%1,%2,%3}, {%4,%5,%6,%7}, {%8,%9}, {%0,%1,%2,%3};\n"
        : "+f"(c[0]), "+f"(c[1]), "+f"(c[2]), "+f"(c[3])
        : "r"(a[0]), "r"(a[1]), "r"(a[2]), "r"(a[3]), "r"(b[0]), "r"(b[1]));
}

// exp via FMA-pipe polynomial (avoids MUFU). |x| is small here.
__device__ __forceinline__ float fexp(float x) {
    float n = rintf(x * 1.4426950408889634f);
    n = fminf(fmaxf(n, -80.f), 80.f);
    float f = fmaf(n, -0.6931471805599453f, x);
    float p = fmaf(f, 1.f/120.f, 1.f/24.f);
    p = fmaf(f, p, 1.f/6.f);
    p = fmaf(f, p, 0.5f);
    p = fmaf(f, p, 1.0f);
    p = fmaf(f, p, 1.0f);
    float s = __int_as_float(((int)n + 127) << 23);
    return p * s;
}

// ---------------- GEMM building blocks ----------------
// A smem: [BM rows][80B]. B smem: BT ? [BN][80B] : [32][BN*2+16].
// Strides 80/144/272 = 16*odd -> conflict-free ldmatrix.

template<int BM, int BN, bool BT>
__device__ __forceinline__ void g2s(const bf16* __restrict__ A, int lda,
                                    const bf16* __restrict__ B, int ldb,
                                    int m0, int n0, int k0,
                                    uint32_t aB, uint32_t bB, int tid)
{
    #pragma unroll
    for (int i = tid; i < BM * 4; i += 256) {
        int r = i >> 2, c = i & 3;
        cpa16(aB + r * 80 + c * 16, A + (size_t)(m0 + r) * lda + k0 + c * 8);
    }
    if (BT) {
        #pragma unroll
        for (int i = tid; i < BN * 4; i += 256) {
            int r = i >> 2, c = i & 3;
            cpa16(bB + r * 80 + c * 16, B + (size_t)(n0 + r) * ldb + k0 + c * 8);
        }
    } else {
        constexpr int NC = BN / 8, SBv = BN * 2 + 16;
        #pragma unroll
        for (int i = tid; i < 32 * NC; i += 256) {
            int kr = i / NC, c = i % NC;
            cpa16(bB + kr * SBv + c * 16, B + (size_t)(k0 + kr) * ldb + n0 + c * 8);
        }
    }
    cpa_commit();
}

template<int BM, int BN, bool BT>
__device__ __forceinline__ void smma(uint32_t aB, uint32_t bB, int lane,
                                     int wm0, int wn0, float acc[][BN/32][4])
{
    constexpr int MT = BM / 32, NT = BN / 32, SBv = BT ? 80 : (BN * 2 + 16);
    #pragma unroll
    for (int s = 0; s < 2; s++) {
        uint32_t af[MT][4], bf2[NT][2];
        #pragma unroll
        for (int mi = 0; mi < MT; mi++)
            ldsm4(af[mi][0], af[mi][1], af[mi][2], af[mi][3],
                  aB + (wm0 + mi * 16 + (lane & 15)) * 80 + s * 32 + (lane & 16));
        #pragma unroll
        for (int ni = 0; ni < NT; ni++) {
            if (BT)
                ldsm2(bf2[ni][0], bf2[ni][1],
                      bB + (wn0 + ni * 8 + (lane & 7)) * 80 + s * 32 + ((lane >> 3) & 1) * 16);
            else
                ldsm2t(bf2[ni][0], bf2[ni][1],
                       bB + (s * 16 + (lane & 15)) * SBv + (wn0 + ni * 8) * 2);
        }
        #pragma unroll
        for (int mi = 0; mi < MT; mi++)
            #pragma unroll
            for (int ni = 0; ni < NT; ni++)
                mma_bf16(acc[mi][ni], af[mi], bf2[ni]);
    }
}

// pipelined mainloop with caller-provided smem: acc += A[m0:,:K] @ op(B)
template<int BM, int BN, bool BT>
__device__ __forceinline__ void mma_loop(const bf16* __restrict__ A, int lda,
                                         const bf16* __restrict__ B, int ldb,
                                         int K, int m0, int n0,
                                         float acc[][BN/32][4],
                                         unsigned char* sAbuf, unsigned char* sBbuf)
{
    constexpr int SBv  = BT ? 80 : (BN * 2 + 16);
    constexpr int BROW = BT ? BN : 32;
    const int tid = threadIdx.x, lane = tid & 31, warp = tid >> 5;
    const int wm0 = (warp >> 2) * (BM / 2), wn0 = (warp & 3) * (BN / 4);
    uint32_t aB0 = smaddr(sAbuf), aB1 = aB0 + BM * 80;
    uint32_t bB0 = smaddr(sBbuf), bB1 = bB0 + BROW * SBv;

    g2s<BM, BN, BT>(A, lda, B, ldb, m0, n0, 0, aB0, bB0, tid);
    const int nch = K >> 5;
    for (int i = 0; i < nch; i++) {
        cpa_wait0();
        __syncthreads();
        uint32_t aB = (i & 1) ? aB1 : aB0, bB = (i & 1) ? bB1 : bB0;
        if (i + 1 < nch)
            g2s<BM, BN, BT>(A, lda, B, ldb, m0, n0, (i + 1) * 32,
                            (i & 1) ? aB0 : aB1, (i & 1) ? bB0 : bB1, tid);
        smma<BM, BN, BT>(aB, bB, lane, wm0, wn0, acc);
        __syncthreads();
    }
}

// ---------------- epilogue helpers ----------------
template<int BM, int BN>
__device__ __forceinline__ void epi_f32(float acc[][BN/32][4], float* C, int ldc,
                                        int m0, int n0, const float* bias)
{
    const int lane = threadIdx.x & 31, warp = threadIdx.x >> 5;
    const int lr = lane >> 2, lc = lane & 3;
    const int wm0 = (warp >> 2) * (BM / 2), wn0 = (warp & 3) * (BN / 4);
    #pragma unroll
    for (int mi = 0; mi < BM / 32; mi++) {
        int row = m0 + wm0 + mi * 16 + lr;
        #pragma unroll
        for (int ni = 0; ni < BN / 32; ni++) {
            int col = n0 + wn0 + ni * 8 + 2 * lc;
            float bx = 0.f, by = 0.f;
            if (bias) { bx = bias[col]; by = bias[col + 1]; }
            *(float2*)(C + (size_t)row * ldc + col) =
                make_float2(acc[mi][ni][0] + bx, acc[mi][ni][1] + by);
            *(float2*)(C + (size_t)(row + 8) * ldc + col) =
                make_float2(acc[mi][ni][2] + bx, acc[mi][ni][3] + by);
        }
    }
}

template<int BM, int BN>
__device__ __forceinline__ void epi_bf16(float acc[][BN/32][4], bf16* C, int ldc,
                                         int m0, int n0, float alpha)
{
    const int lane = threadIdx.x & 31, warp = threadIdx.x >> 5;
    const int lr = lane >> 2, lc = lane & 3;
    const int wm0 = (warp >> 2) * (BM / 2), wn0 = (warp & 3) * (BN / 4);
    #pragma unroll
    for (int mi = 0; mi < BM / 32; mi++) {
        int row = m0 + wm0 + mi * 16 + lr;
        #pragma unroll
        for (int ni = 0; ni < BN / 32; ni++) {
            int col = n0 + wn0 + ni * 8 + 2 * lc;
            *(bf162*)(C + (size_t)row * ldc + col) =
                __floats2bfloat162_rn(acc[mi][ni][0] * alpha, acc[mi][ni][1] * alpha);
            *(bf162*)(C + (size_t)(row + 8) * ldc + col) =
                __floats2bfloat162_rn(acc[mi][ni][2] * alpha, acc[mi][ni][3] * alpha);
        }
    }
}

// ---------------- kernels ----------------

// one kernel: all 5 weight conversions + g_sum zeroing
__global__ __launch_bounds__(256) void k_prep(const float4* __restrict__ Wq,
                                              const float4* __restrict__ Wkv,
                                              const float4* __restrict__ Wout,
                                              const float4* __restrict__ Wff1,
                                              const float4* __restrict__ Wff2)
{
    int i = blockIdx.x * 256 + threadIdx.x;
    const float4* src; bf162* dst; int off;
    if      (i < 32768)   { src = Wq;   dst = (bf162*)g_Wq;   off = 0; }
    else if (i < 98304)   { src = Wkv;  dst = (bf162*)g_Wkv;  off = 32768; }
    else if (i < 2195456) { src = Wout; dst = (bf162*)g_Wout; off = 98304; }
    else if (i < 2326528) { src = Wff1; dst = (bf162*)g_Wff1; off = 2195456; }
    else if (i < 2392064) { src = Wff2; dst = (bf162*)g_Wff2; off = 2326528; }
    else { ((float4*)g_sum)[i - 2392064] = make_float4(0.f, 0.f, 0.f, 0.f); return; }
    int j = i - off;
    float4 v = src[j];
    dst[2 * j]     = __floats2bfloat162_rn(v.x, v.y);
    dst[2 * j + 1] = __floats2bfloat162_rn(v.z, v.w);
}

// x[b,d,m,n] -> g_xt / g_xtb [(b*N+n)*M+m][d]
__global__ __launch_bounds__(256) void k_tr(const float* __restrict__ x) {
    __shared__ float tile[32][33];
    int zi = blockIdx.z;
    int b = zi >> 3, m = zi & 7;
    int n0 = blockIdx.x * 32, d0 = blockIdx.y * 32;
    #pragma unroll
    for (int r = 0; r < 4; r++) {
        int d = d0 + threadIdx.y + r * 8;
        tile[threadIdx.y + r * 8][threadIdx.x] =
            x[((size_t)(b * ND + d) * NM + m) * NSEQ + n0 + threadIdx.x];
    }
    __syncthreads();
    #pragma unroll
    for (int r = 0; r < 4; r++) {
        int n = n0 + threadIdx.y + r * 8;
        int d = d0 + threadIdx.x;
        float v = tile[threadIdx.x][threadIdx.y + r * 8];
        size_t o = ((size_t)(b * NSEQ + n) * NM + m) * ND + d;
        g_xt[o]  = v;
        g_xtb[o] = __float2bfloat16(v);
    }
}

// fused Q + KV projection. blockIdx.x<4 -> Q tile (x0.125), else KV tile.
__global__ __launch_bounds__(256) void k_qkv() {
    __shared__ alignas(16) unsigned char sA[2 * 128 * 80];
    __shared__ alignas(16) unsigned char sB[2 * 32 * 272];
    float acc[4][4][4] = {};
    int m0 = blockIdx.y * 128;
    if (blockIdx.x < 4) {
        int n0 = blockIdx.x * 128;
        mma_loop<128, 128, false>(g_xtb, ND, g_Wq, NINNER, ND, m0, n0, acc, sA, sB);
        epi_bf16<128, 128>(acc, g_qb, NINNER, m0, n0, 0.125f);   // fold attn scale (exact)
    } else {
        int n0 = (blockIdx.x - 4) * 128;
        mma_loop<128, 128, false>(g_xtb, ND, g_Wkv, 2 * NINNER, ND, m0, n0, acc, sA, sB);
        epi_bf16<128, 128>(acc, g_kvb, 2 * NINNER, m0, n0, 1.f);
    }
}

// P[e][i*2048 + m*256 + j] = exp(Q'K^T) (Q pre-scaled), plus atomic exp-sums per (e,m,j)
__global__ __launch_bounds__(256) void k_sim() {
    __shared__ alignas(16) unsigned char sA[2 * 128 * 80];
    __shared__ alignas(16) unsigned char sB[2 * 128 * 80];
    float acc[4][4][4] = {};
    int e = blockIdx.z;
    int z = e & 7, h = (e >> 3) & 7, b = e >> 6;
    int m0 = blockIdx.y * 128, n0 = blockIdx.x * 128;
    const bf16* A = g_qb  + (size_t)b * 2048 * NINNER + h * NDH;
    const bf16* B = g_kvb + ((size_t)b * 2048 + z) * (2 * NINNER) + h * NDH;
    mma_loop<128, 128, true>(A, NINNER, B, NM * 2 * NINNER, NDH, m0, n0, acc, sA, sB);

    const int lane = threadIdx.x & 31, warp = threadIdx.x >> 5;
    const int lr = lane >> 2, lc = lane & 3;
    const int wm0 = (warp >> 2) * 64, wn0 = (warp & 3) * 32;
    bf16* Pb = g_P + (size_t)e * 524288;
    float* sumb = g_sum + (size_t)e * 2048 + lr * 256;   // row&7 == lr == m
    #pragma unroll
    for (int ni = 0; ni < 4; ni++) {
        int col = n0 + wn0 + ni * 8 + 2 * lc;
        float s0 = 0.f, s1 = 0.f;
        #pragma unroll
        for (int mi = 0; mi < 4; mi++) {
            int row = m0 + wm0 + mi * 16 + lr;
            float p0 = fexp(acc[mi][ni][0]);
            float p1 = fexp(acc[mi][ni][1]);
            float p2 = fexp(acc[mi][ni][2]);
            float p3 = fexp(acc[mi][ni][3]);
            s0 += p0 + p2; s1 += p1 + p3;
            *(bf162*)(Pb + (size_t)row * 256 + col)       = __floats2bfloat162_rn(p0, p1);
            *(bf162*)(Pb + (size_t)(row + 8) * 256 + col) = __floats2bfloat162_rn(p2, p3);
        }
        atomicAdd(sumb + col, s0);
        atomicAdd(sumb + col + 1, s1);
    }
}

// V'[e][k=(m*256+j)][d] = (1/sum[e][k]) * V[b][(j,m)][h*64+d]
__global__ __launch_bounds__(256) void k_vprime() {
    int e = blockIdx.y;
    int idx = blockIdx.x * 256 + threadIdx.x;     // 64 blocks/e * 256 = 16384 = 2048k * 8dc
    int k = idx >> 3, dc = idx & 7;
    int z = e & 7, h = (e >> 3) & 7, b = e >> 6;  (void)z;
    int j = k & 255, m = k >> 8;
    float rs = 1.f / g_sum[(size_t)e * 2048 + k];
    const bf16* vp = g_kvb + ((size_t)(b * 2048) + j * 8 + m) * 1024 + 512 + h * 64 + dc * 8;
    uint4 raw = *(const uint4*)vp;
    bf162* pr = (bf162*)&raw;
    uint4 outv;
    bf162* po = (bf162*)&outv;
    #pragma unroll
    for (int q = 0; q < 4; q++) {
        float2 f = __bfloat1622float2(pr[q]);
        f.x *= rs; f.y *= rs;
        po[q] = __float22bfloat162_rn(f);
    }
    *(uint4*)(g_vp + ((size_t)e * 2048 + k) * 64 + dc * 8) = outv;
}

// O[e][i][d] = P[e] @ V'[e]   — plain pipelined GEMM, K=2048
__global__ __launch_bounds__(256) void k_av() {
    __shared__ alignas(16) unsigned char sA[2 * 128 * 80];
    __shared__ alignas(16) unsigned char sB[2 * 32 * 144];
    float acc[4][2][4] = {};
    int e = blockIdx.y;
    int z = e & 7, h = (e >> 3) & 7, b = e >> 6;
    int m0 = blockIdx.x * 128;
    const bf16* A = g_P  + (size_t)e * 524288;    // [256 i][2048 k]
    const bf16* B = g_vp + (size_t)e * 2048 * 64; // [2048 k][64 d]
    mma_loop<128, 64, false>(A, 2048, B, 64, 2048, m0, 0, acc, sA, sB);
    bf16* Ob = g_aob + (size_t)(b * 256) * 4096 + z * 512 + h * 64;
    epi_bf16<128, 64>(acc, Ob, 4096, m0, 0, 1.f);
}

__global__ __launch_bounds__(256) void k_wout(const float* __restrict__ bias) {
    __shared__ alignas(16) unsigned char sA[2 * 64 * 80];
    __shared__ alignas(16) unsigned char sB[2 * 32 * 144];
    float acc[2][2][4] = {};
    int m0 = blockIdx.y * 64, n0 = blockIdx.x * 64;
    mma_loop<64, 64, false>(g_aob, 4096, g_Wout, 2048, 4096, m0, n0, acc, sA, sB);
    epi_f32<64, 64>(acc, g_y1, 2048, m0, n0, bias);
}

__global__ __launch_bounds__(256) void k_ln(int mode,
                                            const float* __restrict__ g,
                                            const float* __restrict__ beta,
                                            float* __restrict__ out) {
    int t = blockIdx.x, d = threadIdx.x;
    float xv, yv;
    if (mode == 1) {
        int bn = t >> 3, m = t & 7;
        xv = g_xt[(size_t)t * ND + d];
        yv = g_y1[(size_t)bn * 2048 + m * ND + d];
    } else {
        xv = g_x2[(size_t)t * ND + d];
        yv = g_y2[(size_t)t * ND + d];
    }
    float v = xv + yv;
    float s = v, s2 = v * v;
    #pragma unroll
    for (int o = 16; o; o >>= 1) {
        s  += __shfl_xor_sync(0xffffffffu, s,  o);
        s2 += __shfl_xor_sync(0xffffffffu, s2, o);
    }
    __shared__ float sh[16];
    int w = d >> 5, l = d & 31;
    if (l == 0) { sh[w] = s; sh[8 + w] = s2; }
    __syncthreads();
    if (d == 0) {
        float ts = 0.f, ts2 = 0.f;
        #pragma unroll
        for (int i = 0; i < 8; i++) { ts += sh[i]; ts2 += sh[8 + i]; }
        float mu  = ts * (1.f / 256.f);
        float var = ts2 * (1.f / 256.f) - mu * mu;
        sh[0] = mu;
        sh[1] = rsqrtf(var + 1e-5f);
    }
    __syncthreads();
    float r = (v - sh[0]) * sh[1] * g[d] + beta[d];
    if (mode == 1) {
        g_x2 [(size_t)t * ND + d] = r;
        g_x2b[(size_t)t * ND + d] = __float2bfloat16(r);
    } else {
        out[(size_t)t * ND + d] = r;
    }
}

// FFN1 + GEGLU fused: per block, compute matching a-tile and gate-tile, emit bf16 activations
__global__ __launch_bounds__(256) void k_ff1g(const float* __restrict__ bias) {
    __shared__ alignas(16) unsigned char sA[2 * 128 * 80];
    __shared__ alignas(16) unsigned char sB[2 * 32 * 144];
    float aA[4][2][4] = {};
    float aG[4][2][4] = {};
    int m0 = blockIdx.y * 128, n0 = blockIdx.x * 64;
    mma_loop<128, 64, false>(g_x2b, ND, g_Wff1, 2048, ND, m0, n0,        aA, sA, sB);
    mma_loop<128, 64, false>(g_x2b, ND, g_Wff1, 2048, ND, m0, n0 + 1024, aG, sA, sB);

    const int lane = threadIdx.x & 31, warp = threadIdx.x >> 5;
    const int lr = lane >> 2, lc = lane & 3;
    const int wm0 = (warp >> 2) * 64, wn0 = (warp & 3) * 16;
    #pragma unroll
    for (int mi = 0; mi < 4; mi++) {
        int row = m0 + wm0 + mi * 16 + lr;
        #pragma unroll
        for (int ni = 0; ni < 2; ni++) {
            int col = n0 + wn0 + ni * 8 + 2 * lc;
            float ba0 = bias[col],       ba1 = bias[col + 1];
            float bg0 = bias[1024 + col], bg1 = bias[1024 + col + 1];
            #pragma unroll
            for (int half = 0; half < 2; half++) {
                int r = row + half * 8;
                float a0 = aA[mi][ni][2 * half + 0] + ba0;
                float a1 = aA[mi][ni][2 * half + 1] + ba1;
                float gt0 = aG[mi][ni][2 * half + 0] + bg0;
                float gt1 = aG[mi][ni][2 * half + 1] + bg1;
                float v0 = a0 * 0.5f * gt0 * (1.f + erff(gt0 * 0.70710678118654752f));
                float v1 = a1 * 0.5f * gt1 * (1.f + erff(gt1 * 0.70710678118654752f));
                *(bf162*)(g_fib + (size_t)r * 1024 + col) = __floats2bfloat162_rn(v0, v1);
            }
        }
    }
}

__global__ __launch_bounds__(256) void k_ff2(const float* __restrict__ bias) {
    __shared__ alignas(16) unsigned char sA[2 * 128 * 80];
    __shared__ alignas(16) unsigned char sB[2 * 32 * 144];
    float acc[4][2][4] = {};
    int m0 = blockIdx.y * 128, n0 = blockIdx.x * 64;
    mma_loop<128, 64, false>(g_fib, 1024, g_Wff2, ND, 1024, m0, n0, acc, sA, sB);
    epi_f32<128, 64>(acc, g_y2, ND, m0, n0, bias);
}

// ---------------- launch ----------------
extern "C" void kernel_launch(void* const* d_in, const int* in_sizes, int n_in,
                              void* d_out, int out_size) {
    const float* x     = (const float*)d_in[0];
    const float* Wq    = (const float*)d_in[1];
    const float* Wkv   = (const float*)d_in[2];
    const float* Wout  = (const float*)d_in[3];
    const float* bout  = (const float*)d_in[4];
    const float* g1    = (const float*)d_in[5];
    const float* beta1 = (const float*)d_in[6];
    const float* Wff1  = (const float*)d_in[7];
    const float* bff1  = (const float*)d_in[8];
    const float* Wff2  = (const float*)d_in[9];
    const float* bff2  = (const float*)d_in[10];
    const float* g2    = (const float*)d_in[11];
    const float* beta2 = (const float*)d_in[12];
    float* out = (float*)d_out;

    k_prep   <<<9600, 256>>>((const float4*)Wq, (const float4*)Wkv, (const float4*)Wout,
                             (const float4*)Wff1, (const float4*)Wff2);
    k_tr     <<<dim3(8, 8, 16), dim3(32, 8)>>>(x);
    k_qkv    <<<dim3(12, 32),      256>>>();
    k_sim    <<<dim3(2, 16, 128),  256>>>();
    k_vprime <<<dim3(64, 128),     256>>>();
    k_av     <<<dim3(2, 128),      256>>>();
    k_wout   <<<dim3(32, 8),       256>>>(bout);
    k_ln     <<<4096, 256>>>(1, g1, beta1, nullptr);
    k_ff1g   <<<dim3(16, 32),      256>>>(bff1);
    k_ff2    <<<dim3(4, 32),       256>>>(bff2);
    k_ln     <<<4096, 256>>>(2, g2, beta2, out);
}

// round 7
// speedup vs baseline: 3.9562x; 1.0677x over previous
#include <cuda_runtime.h>
#include <cuda_bf16.h>
#include <math.h>
#include <stdint.h>

#define NB     2
#define NSEQ   256
#define NM     8
#define ND     256
#define NH     8
#define NDH    64
#define NINNER 512
#define NTOK   (NB*NSEQ*NM)          // 4096
#define NBN    (NB*NSEQ)             // 512
typedef __nv_bfloat16 bf16;
typedef __nv_bfloat162 bf162;

// ---------------- scratch ----------------
__device__ float g_xt [NTOK*ND];                       // fp32 (residual)
__device__ bf16  g_xtb[NTOK*ND];
__device__ bf16  g_qb [NTOK*NINNER];
__device__ bf16  g_kvb[NTOK*2*NINNER];
__device__ bf16  g_P  [(size_t)128*256*2048];          // exp(S): [e][i][m*256+j], 134MB
__device__ float g_psum[(size_t)128*16*2048];          // per-block partial sums, 16.8MB
__device__ bf16  g_vp [(size_t)128*2048*64];           // rs-scaled V': [e][m*256+j][d], 33.5MB
__device__ bf16  g_aob[(size_t)NBN*4096];
__device__ float g_y1 [(size_t)NBN*2048];
__device__ float g_x2 [NTOK*ND];
__device__ bf16  g_x2b[NTOK*ND];
__device__ bf16  g_fib[(size_t)NTOK*1024];
__device__ float g_y2 [NTOK*ND];
// bf16 weights
__device__ bf16  g_Wq  [256*512];
__device__ bf16  g_Wkv [256*1024];
__device__ bf16  g_Wout[(size_t)4096*2048];
__device__ bf16  g_Wff1[256*2048];
__device__ bf16  g_Wff2[1024*256];

// ---------------- ptx helpers ----------------
__device__ __forceinline__ uint32_t smaddr(const void* p) {
    return (uint32_t)__cvta_generic_to_shared(p);
}
__device__ __forceinline__ void cpa16(uint32_t dst, const void* src) {
    asm volatile("cp.async.cg.shared.global [%0], [%1], 16;\n" :: "r"(dst), "l"(src) : "memory");
}
__device__ __forceinline__ void cpa_commit() { asm volatile("cp.async.commit_group;\n" ::: "memory"); }
__device__ __forceinline__ void cpa_wait0()  { asm volatile("cp.async.wait_group 0;\n" ::: "memory"); }

__device__ __forceinline__ void ldsm4(uint32_t& r0, uint32_t& r1, uint32_t& r2, uint32_t& r3, uint32_t a) {
    asm volatile("ldmatrix.sync.aligned.m8n8.x4.shared.b16 {%0,%1,%2,%3}, [%4];"
                 : "=r"(r0), "=r"(r1), "=r"(r2), "=r"(r3) : "r"(a));
}
__device__ __forceinline__ void ldsm2(uint32_t& r0, uint32_t& r1, uint32_t a) {
    asm volatile("ldmatrix.sync.aligned.m8n8.x2.shared.b16 {%0,%1}, [%2];"
                 : "=r"(r0), "=r"(r1) : "r"(a));
}
__device__ __forceinline__ void ldsm2t(uint32_t& r0, uint32_t& r1, uint32_t a) {
    asm volatile("ldmatrix.sync.aligned.m8n8.x2.trans.shared.b16 {%0,%1}, [%2];"
                 : "=r"(r0), "=r"(r1) : "r"(a));
}
__device__ __forceinline__ void mma_bf16(float* c, const uint32_t* a, const uint32_t* b) {
    asm volatile(
        "mma.sync.aligned.m16n8k16.row.col.f32.bf16.bf16.f32 "
        "{%0,%1,%2,%3}, {%4,%5,%6,%7}, {%8,%9}, {%0,%1,%2,%3};\n"
        : "+f"(c[0]), "+f"(c[1]), "+f"(c[2]), "+f"(c[3])
        : "r"(a[0]), "r"(a[1]), "r"(a[2]), "r"(a[3]), "r"(b[0]), "r"(b[1]));
}

// ---------------- GEMM building blocks ----------------
// A smem: [BM rows][80B]. B smem: BT ? [BN][80B] : [32][BN*2+16].
// Strides 80/144/272 = 16*odd -> conflict-free ldmatrix.

template<int BM, int BN, bool BT>
__device__ __forceinline__ void g2s(const bf16* __restrict__ A, int lda,
                                    const bf16* __restrict__ B, int ldb,
                                    int m0, int n0, int k0,
                                    uint32_t aB, uint32_t bB, int tid)
{
    #pragma unroll
    for (int i = tid; i < BM * 4; i += 256) {
        int r = i >> 2, c = i & 3;
        cpa16(aB + r * 80 + c * 16, A + (size_t)(m0 + r) * lda + k0 + c * 8);
    }
    if (BT) {
        #pragma unroll
        for (int i = tid; i < BN * 4; i += 256) {
            int r = i >> 2, c = i & 3;
            cpa16(bB + r * 80 + c * 16, B + (size_t)(n0 + r) * ldb + k0 + c * 8);
        }
    } else {
        constexpr int NC = BN / 8, SBv = BN * 2 + 16;
        #pragma unroll
        for (int i = tid; i < 32 * NC; i += 256) {
            int kr = i / NC, c = i % NC;
            cpa16(bB + kr * SBv + c * 16, B + (size_t)(k0 + kr) * ldb + n0 + c * 8);
        }
    }
    cpa_commit();
}

template<int BM, int BN, bool BT>
__device__ __forceinline__ void smma(uint32_t aB, uint32_t bB, int lane,
                                     int wm0, int wn0, float acc[][BN/32][4])
{
    constexpr int MT = BM / 32, NT = BN / 32, SBv = BT ? 80 : (BN * 2 + 16);
    #pragma unroll
    for (int s = 0; s < 2; s++) {
        uint32_t af[MT][4], bf2[NT][2];
        #pragma unroll
        for (int mi = 0; mi < MT; mi++)
            ldsm4(af[mi][0], af[mi][1], af[mi][2], af[mi][3],
                  aB + (wm0 + mi * 16 + (lane & 15)) * 80 + s * 32 + (lane & 16));
        #pragma unroll
        for (int ni = 0; ni < NT; ni++) {
            if (BT)
                ldsm2(bf2[ni][0], bf2[ni][1],
                      bB + (wn0 + ni * 8 + (lane & 7)) * 80 + s * 32 + ((lane >> 3) & 1) * 16);
            else
                ldsm2t(bf2[ni][0], bf2[ni][1],
                       bB + (s * 16 + (lane & 15)) * SBv + (wn0 + ni * 8) * 2);
        }
        #pragma unroll
        for (int mi = 0; mi < MT; mi++)
            #pragma unroll
            for (int ni = 0; ni < NT; ni++)
                mma_bf16(acc[mi][ni], af[mi], bf2[ni]);
    }
}

// pipelined mainloop with caller-provided smem: acc += A[m0:,:K] @ op(B)
template<int BM, int BN, bool BT>
__device__ __forceinline__ void mma_loop(const bf16* __restrict__ A, int lda,
                                         const bf16* __restrict__ B, int ldb,
                                         int K, int m0, int n0,
                                         float acc[][BN/32][4],
                                         unsigned char* sAbuf, unsigned char* sBbuf)
{
    constexpr int SBv  = BT ? 80 : (BN * 2 + 16);
    constexpr int BROW = BT ? BN : 32;
    const int tid = threadIdx.x, lane = tid & 31, warp = tid >> 5;
    const int wm0 = (warp >> 2) * (BM / 2), wn0 = (warp & 3) * (BN / 4);
    uint32_t aB0 = smaddr(sAbuf), aB1 = aB0 + BM * 80;
    uint32_t bB0 = smaddr(sBbuf), bB1 = bB0 + BROW * SBv;

    g2s<BM, BN, BT>(A, lda, B, ldb, m0, n0, 0, aB0, bB0, tid);
    const int nch = K >> 5;
    for (int i = 0; i < nch; i++) {
        cpa_wait0();
        __syncthreads();
        uint32_t aB = (i & 1) ? aB1 : aB0, bB = (i & 1) ? bB1 : bB0;
        if (i + 1 < nch)
            g2s<BM, BN, BT>(A, lda, B, ldb, m0, n0, (i + 1) * 32,
                            (i & 1) ? aB0 : aB1, (i & 1) ? bB0 : bB1, tid);
        smma<BM, BN, BT>(aB, bB, lane, wm0, wn0, acc);
        __syncthreads();
    }
}

// ---------------- epilogue helpers ----------------
template<int BM, int BN>
__device__ __forceinline__ void epi_f32(float acc[][BN/32][4], float* C, int ldc,
                                        int m0, int n0, const float* bias)
{
    const int lane = threadIdx.x & 31, warp = threadIdx.x >> 5;
    const int lr = lane >> 2, lc = lane & 3;
    const int wm0 = (warp >> 2) * (BM / 2), wn0 = (warp & 3) * (BN / 4);
    #pragma unroll
    for (int mi = 0; mi < BM / 32; mi++) {
        int row = m0 + wm0 + mi * 16 + lr;
        #pragma unroll
        for (int ni = 0; ni < BN / 32; ni++) {
            int col = n0 + wn0 + ni * 8 + 2 * lc;
            float bx = 0.f, by = 0.f;
            if (bias) { bx = bias[col]; by = bias[col + 1]; }
            *(float2*)(C + (size_t)row * ldc + col) =
                make_float2(acc[mi][ni][0] + bx, acc[mi][ni][1] + by);
            *(float2*)(C + (size_t)(row + 8) * ldc + col) =
                make_float2(acc[mi][ni][2] + bx, acc[mi][ni][3] + by);
        }
    }
}

template<int BM, int BN>
__device__ __forceinline__ void epi_bf16(float acc[][BN/32][4], bf16* C, int ldc,
                                         int m0, int n0, float alpha)
{
    const int lane = threadIdx.x & 31, warp = threadIdx.x >> 5;
    const int lr = lane >> 2, lc = lane & 3;
    const int wm0 = (warp >> 2) * (BM / 2), wn0 = (warp & 3) * (BN / 4);
    #pragma unroll
    for (int mi = 0; mi < BM / 32; mi++) {
        int row = m0 + wm0 + mi * 16 + lr;
        #pragma unroll
        for (int ni = 0; ni < BN / 32; ni++) {
            int col = n0 + wn0 + ni * 8 + 2 * lc;
            *(bf162*)(C + (size_t)row * ldc + col) =
                __floats2bfloat162_rn(acc[mi][ni][0] * alpha, acc[mi][ni][1] * alpha);
            *(bf162*)(C + (size_t)(row + 8) * ldc + col) =
                __floats2bfloat162_rn(acc[mi][ni][2] * alpha, acc[mi][ni][3] * alpha);
        }
    }
}

// ---------------- kernels ----------------

// all 5 weight conversions in one kernel
__global__ __launch_bounds__(256) void k_prep(const float4* __restrict__ Wq,
                                              const float4* __restrict__ Wkv,
                                              const float4* __restrict__ Wout,
                                              const float4* __restrict__ Wff1,
                                              const float4* __restrict__ Wff2)
{
    int i = blockIdx.x * 256 + threadIdx.x;
    const float4* src; bf162* dst; int off;
    if      (i < 32768)   { src = Wq;   dst = (bf162*)g_Wq;   off = 0; }
    else if (i < 98304)   { src = Wkv;  dst = (bf162*)g_Wkv;  off = 32768; }
    else if (i < 2195456) { src = Wout; dst = (bf162*)g_Wout; off = 98304; }
    else if (i < 2326528) { src = Wff1; dst = (bf162*)g_Wff1; off = 2195456; }
    else                  { src = Wff2; dst = (bf162*)g_Wff2; off = 2326528; }
    int j = i - off;
    float4 v = src[j];
    dst[2 * j]     = __floats2bfloat162_rn(v.x, v.y);
    dst[2 * j + 1] = __floats2bfloat162_rn(v.z, v.w);
}

// x[b,d,m,n] -> g_xt / g_xtb [(b*N+n)*M+m][d]
__global__ __launch_bounds__(256) void k_tr(const float* __restrict__ x) {
    __shared__ float tile[32][33];
    int zi = blockIdx.z;
    int b = zi >> 3, m = zi & 7;
    int n0 = blockIdx.x * 32, d0 = blockIdx.y * 32;
    #pragma unroll
    for (int r = 0; r < 4; r++) {
        int d = d0 + threadIdx.y + r * 8;
        tile[threadIdx.y + r * 8][threadIdx.x] =
            x[((size_t)(b * ND + d) * NM + m) * NSEQ + n0 + threadIdx.x];
    }
    __syncthreads();
    #pragma unroll
    for (int r = 0; r < 4; r++) {
        int n = n0 + threadIdx.y + r * 8;
        int d = d0 + threadIdx.x;
        float v = tile[threadIdx.x][threadIdx.y + r * 8];
        size_t o = ((size_t)(b * NSEQ + n) * NM + m) * ND + d;
        g_xt[o]  = v;
        g_xtb[o] = __float2bfloat16(v);
    }
}

// fused Q + KV projection. blockIdx.x<4 -> Q tile (x0.125), else KV tile.
__global__ __launch_bounds__(256) void k_qkv() {
    __shared__ alignas(16) unsigned char sA[2 * 128 * 80];
    __shared__ alignas(16) unsigned char sB[2 * 32 * 272];
    float acc[4][4][4] = {};
    int m0 = blockIdx.y * 128;
    if (blockIdx.x < 4) {
        int n0 = blockIdx.x * 128;
        mma_loop<128, 128, false>(g_xtb, ND, g_Wq, NINNER, ND, m0, n0, acc, sA, sB);
        epi_bf16<128, 128>(acc, g_qb, NINNER, m0, n0, 0.125f);   // fold attn scale (exact)
    } else {
        int n0 = (blockIdx.x - 4) * 128;
        mma_loop<128, 128, false>(g_xtb, ND, g_Wkv, 2 * NINNER, ND, m0, n0, acc, sA, sB);
        epi_bf16<128, 128>(acc, g_kvb, 2 * NINNER, m0, n0, 1.f);
    }
}

// P[e][i*2048 + m*256 + j] = exp(Q'K^T) (Q pre-scaled).
// Per-block column sums -> g_psum[e][blockIdx.y][m*256+j]  (no atomics)
__global__ __launch_bounds__(256) void k_sim() {
    __shared__ alignas(16) unsigned char sA[2 * 128 * 80];
    __shared__ alignas(16) unsigned char sB[2 * 128 * 80];
    __shared__ float ssum[2][8][128];
    float acc[4][4][4] = {};
    int e = blockIdx.z;
    int z = e & 7, h = (e >> 3) & 7, b = e >> 6;
    int m0 = blockIdx.y * 128, n0 = blockIdx.x * 128;
    const bf16* A = g_qb  + (size_t)b * 2048 * NINNER + h * NDH;
    const bf16* B = g_kvb + ((size_t)b * 2048 + z) * (2 * NINNER) + h * NDH;
    mma_loop<128, 128, true>(A, NINNER, B, NM * 2 * NINNER, NDH, m0, n0, acc, sA, sB);

    const int lane = threadIdx.x & 31, warp = threadIdx.x >> 5;
    const int lr = lane >> 2, lc = lane & 3;
    const int wg = warp >> 2;
    const int wm0 = wg * 64, wn0 = (warp & 3) * 32;
    bf16* Pb = g_P + (size_t)e * 524288;
    #pragma unroll
    for (int ni = 0; ni < 4; ni++) {
        int colL = wn0 + ni * 8 + 2 * lc;
        int col = n0 + colL;
        float s0 = 0.f, s1 = 0.f;
        #pragma unroll
        for (int mi = 0; mi < 4; mi++) {
            int row = m0 + wm0 + mi * 16 + lr;
            float p0 = __expf(acc[mi][ni][0]);       // MUFU pipe; overlaps stores
            float p1 = __expf(acc[mi][ni][1]);
            float p2 = __expf(acc[mi][ni][2]);
            float p3 = __expf(acc[mi][ni][3]);
            s0 += p0 + p2; s1 += p1 + p3;
            *(bf162*)(Pb + (size_t)row * 256 + col)       = __floats2bfloat162_rn(p0, p1);
            *(bf162*)(Pb + (size_t)(row + 8) * 256 + col) = __floats2bfloat162_rn(p2, p3);
        }
        ssum[wg][lr][colL]     = s0;   // unique writer per slot per wg
        ssum[wg][lr][colL + 1] = s1;
    }
    __syncthreads();
    float* ps = g_psum + ((size_t)e * 16 + blockIdx.y) * 2048;
    #pragma unroll
    for (int q = 0; q < 4; q++) {
        int idx = threadIdx.x + q * 256;
        int m = idx >> 7, cl = idx & 127;
        ps[m * 256 + n0 + cl] = ssum[0][m][cl] + ssum[1][m][cl];
    }
}

// reduce 16 partials -> rs, then V'[e][k][d] = rs * V
__global__ __launch_bounds__(256) void k_vprime() {
    __shared__ float rs[256];
    int e = blockIdx.y;
    int k0 = blockIdx.x * 256;
    int tid = threadIdx.x;
    float s = 0.f;
    const float* ps = g_psum + (size_t)e * 16 * 2048 + k0 + tid;
    #pragma unroll
    for (int p = 0; p < 16; p++) s += ps[p * 2048];
    rs[tid] = 1.f / s;
    int b = e >> 6, h = (e >> 3) & 7;
    __syncthreads();
    #pragma unroll
    for (int q = 0; q < 8; q++) {
        int idx = tid + q * 256;
        int kk = idx >> 3, dc = idx & 7;
        int kg = k0 + kk, j = kg & 255, m = kg >> 8;
        float r = rs[kk];
        const bf16* vp = g_kvb + ((size_t)(b * 2048) + j * 8 + m) * 1024 + 512 + h * 64 + dc * 8;
        uint4 raw = *(const uint4*)vp;
        bf162* pr = (bf162*)&raw;
        uint4 outv;
        bf162* po = (bf162*)&outv;
        #pragma unroll
        for (int qq = 0; qq < 4; qq++) {
            float2 f = __bfloat1622float2(pr[qq]);
            f.x *= r; f.y *= r;
            po[qq] = __float22bfloat162_rn(f);
        }
        *(uint4*)(g_vp + ((size_t)e * 2048 + kg) * 64 + dc * 8) = outv;
    }
}

// O[e][i][d] = P[e] @ V'[e]   — plain pipelined GEMM, K=2048
__global__ __launch_bounds__(256) void k_av() {
    __shared__ alignas(16) unsigned char sA[2 * 128 * 80];
    __shared__ alignas(16) unsigned char sB[2 * 32 * 144];
    float acc[4][2][4] = {};
    int e = blockIdx.y;
    int z = e & 7, h = (e >> 3) & 7, b = e >> 6;
    int m0 = blockIdx.x * 128;
    const bf16* A = g_P  + (size_t)e * 524288;    // [256 i][2048 k]
    const bf16* B = g_vp + (size_t)e * 2048 * 64; // [2048 k][64 d]
    mma_loop<128, 64, false>(A, 2048, B, 64, 2048, m0, 0, acc, sA, sB);
    bf16* Ob = g_aob + (size_t)(b * 256) * 4096 + z * 512 + h * 64;
    epi_bf16<128, 64>(acc, Ob, 4096, m0, 0, 1.f);
}

__global__ __launch_bounds__(256) void k_wout(const float* __restrict__ bias) {
    __shared__ alignas(16) unsigned char sA[2 * 64 * 80];
    __shared__ alignas(16) unsigned char sB[2 * 32 * 144];
    float acc[2][2][4] = {};
    int m0 = blockIdx.y * 64, n0 = blockIdx.x * 64;
    mma_loop<64, 64, false>(g_aob, 4096, g_Wout, 2048, 4096, m0, n0, acc, sA, sB);
    epi_f32<64, 64>(acc, g_y1, 2048, m0, n0, bias);
}

__global__ __launch_bounds__(256) void k_ln(int mode,
                                            const float* __restrict__ g,
                                            const float* __restrict__ beta,
                                            float* __restrict__ out) {
    int t = blockIdx.x, d = threadIdx.x;
    float xv, yv;
    if (mode == 1) {
        int bn = t >> 3, m = t & 7;
        xv = g_xt[(size_t)t * ND + d];
        yv = g_y1[(size_t)bn * 2048 + m * ND + d];
    } else {
        xv = g_x2[(size_t)t * ND + d];
        yv = g_y2[(size_t)t * ND + d];
    }
    float v = xv + yv;
    float s = v, s2 = v * v;
    #pragma unroll
    for (int o = 16; o; o >>= 1) {
        s  += __shfl_xor_sync(0xffffffffu, s,  o);
        s2 += __shfl_xor_sync(0xffffffffu, s2, o);
    }
    __shared__ float sh[16];
    int w = d >> 5, l = d & 31;
    if (l == 0) { sh[w] = s; sh[8 + w] = s2; }
    __syncthreads();
    if (d == 0) {
        float ts = 0.f, ts2 = 0.f;
        #pragma unroll
        for (int i = 0; i < 8; i++) { ts += sh[i]; ts2 += sh[8 + i]; }
        float mu  = ts * (1.f / 256.f);
        float var = ts2 * (1.f / 256.f) - mu * mu;
        sh[0] = mu;
        sh[1] = rsqrtf(var + 1e-5f);
    }
    __syncthreads();
    float r = (v - sh[0]) * sh[1] * g[d] + beta[d];
    if (mode == 1) {
        g_x2 [(size_t)t * ND + d] = r;
        g_x2b[(size_t)t * ND + d] = __float2bfloat16(r);
    } else {
        out[(size_t)t * ND + d] = r;
    }
}

// FFN1 + GEGLU fused: per block, compute matching a-tile and gate-tile, emit bf16 activations
__global__ __launch_bounds__(256) void k_ff1g(const float* __restrict__ bias) {
    __shared__ alignas(16) unsigned char sA[2 * 128 * 80];
    __shared__ alignas(16) unsigned char sB[2 * 32 * 144];
    float aA[4][2][4] = {};
    float aG[4][2][4] = {};
    int m0 = blockIdx.y * 128, n0 = blockIdx.x * 64;
    mma_loop<128, 64, false>(g_x2b, ND, g_Wff1, 2048, ND, m0, n0,        aA, sA, sB);
    mma_loop<128, 64, false>(g_x2b, ND, g_Wff1, 2048, ND, m0, n0 + 1024, aG, sA, sB);

    const int lane = threadIdx.x & 31, warp = threadIdx.x >> 5;
    const int lr = lane >> 2, lc = lane & 3;
    const int wm0 = (warp >> 2) * 64, wn0 = (warp & 3) * 16;
    #pragma unroll
    for (int mi = 0; mi < 4; mi++) {
        int row = m0 + wm0 + mi * 16 + lr;
        #pragma unroll
        for (int ni = 0; ni < 2; ni++) {
            int col = n0 + wn0 + ni * 8 + 2 * lc;
            float ba0 = bias[col],        ba1 = bias[col + 1];
            float bg0 = bias[1024 + col], bg1 = bias[1024 + col + 1];
            #pragma unroll
            for (int half = 0; half < 2; half++) {
                int r = row + half * 8;
                float a0 = aA[mi][ni][2 * half + 0] + ba0;
                float a1 = aA[mi][ni][2 * half + 1] + ba1;
                float gt0 = aG[mi][ni][2 * half + 0] + bg0;
                float gt1 = aG[mi][ni][2 * half + 1] + bg1;
                float v0 = a0 * 0.5f * gt0 * (1.f + erff(gt0 * 0.70710678118654752f));
                float v1 = a1 * 0.5f * gt1 * (1.f + erff(gt1 * 0.70710678118654752f));
                *(bf162*)(g_fib + (size_t)r * 1024 + col) = __floats2bfloat162_rn(v0, v1);
            }
        }
    }
}

__global__ __launch_bounds__(256) void k_ff2(const float* __restrict__ bias) {
    __shared__ alignas(16) unsigned char sA[2 * 128 * 80];
    __shared__ alignas(16) unsigned char sB[2 * 32 * 144];
    float acc[4][2][4] = {};
    int m0 = blockIdx.y * 128, n0 = blockIdx.x * 64;
    mma_loop<128, 64, false>(g_fib, 1024, g_Wff2, ND, 1024, m0, n0, acc, sA, sB);
    epi_f32<128, 64>(acc, g_y2, ND, m0, n0, bias);
}

// ---------------- launch ----------------
extern "C" void kernel_launch(void* const* d_in, const int* in_sizes, int n_in,
                              void* d_out, int out_size) {
    const float* x     = (const float*)d_in[0];
    const float* Wq    = (const float*)d_in[1];
    const float* Wkv   = (const float*)d_in[2];
    const float* Wout  = (const float*)d_in[3];
    const float* bout  = (const float*)d_in[4];
    const float* g1    = (const float*)d_in[5];
    const float* beta1 = (const float*)d_in[6];
    const float* Wff1  = (const float*)d_in[7];
    const float* bff1  = (const float*)d_in[8];
    const float* Wff2  = (const float*)d_in[9];
    const float* bff2  = (const float*)d_in[10];
    const float* g2    = (const float*)d_in[11];
    const float* beta2 = (const float*)d_in[12];
    float* out = (float*)d_out;

    k_prep   <<<9344, 256>>>((const float4*)Wq, (const float4*)Wkv, (const float4*)Wout,
                             (const float4*)Wff1, (const float4*)Wff2);
    k_tr     <<<dim3(8, 8, 16), dim3(32, 8)>>>(x);
    k_qkv    <<<dim3(12, 32),      256>>>();
    k_sim    <<<dim3(2, 16, 128),  256>>>();
    k_vprime <<<dim3(8, 128),      256>>>();
    k_av     <<<dim3(2, 128),      256>>>();
    k_wout   <<<dim3(32, 8),       256>>>(bout);
    k_ln     <<<4096, 256>>>(1, g1, beta1, nullptr);
    k_ff1g   <<<dim3(16, 32),      256>>>(bff1);
    k_ff2    <<<dim3(4, 32),       256>>>(bff2);
    k_ln     <<<4096, 256>>>(2, g2, beta2, out);
}

// round 8
// speedup vs baseline: 5.3947x; 1.3636x over previous
#include <cuda_runtime.h>
#include <cuda_bf16.h>
#include <math.h>
#include <stdint.h>

#define NB     2
#define NSEQ   256
#define NM     8
#define ND     256
#define NH     8
#define NDH    64
#define NINNER 512
#define NTOK   (NB*NSEQ*NM)          // 4096
#define NBN    (NB*NSEQ)             // 512
typedef __nv_bfloat16 bf16;
typedef __nv_bfloat162 bf162;

// ---------------- scratch ----------------
__device__ float g_xt [NTOK*ND];                       // fp32 (residual)
__device__ bf16  g_xtb[NTOK*ND];
__device__ bf16  g_qb [NTOK*NINNER];
__device__ bf16  g_kvb[NTOK*2*NINNER];
__device__ bf16  g_aob[(size_t)NBN*4096];
__device__ float g_y1 [(size_t)NBN*2048];
__device__ float g_x2 [NTOK*ND];
__device__ bf16  g_x2b[NTOK*ND];
__device__ bf16  g_fib[(size_t)NTOK*1024];
__device__ float g_y2 [NTOK*ND];
// bf16 weights
__device__ bf16  g_Wq  [256*512];
__device__ bf16  g_Wkv [256*1024];
__device__ bf16  g_Wout[(size_t)4096*2048];
__device__ bf16  g_Wff1[256*2048];
__device__ bf16  g_Wff2[1024*256];

// ---------------- ptx helpers ----------------
__device__ __forceinline__ uint32_t smaddr(const void* p) {
    return (uint32_t)__cvta_generic_to_shared(p);
}
__device__ __forceinline__ void cpa16(uint32_t dst, const void* src) {
    asm volatile("cp.async.cg.shared.global [%0], [%1], 16;\n" :: "r"(dst), "l"(src) : "memory");
}
__device__ __forceinline__ void cpa_commit() { asm volatile("cp.async.commit_group;\n" ::: "memory"); }
__device__ __forceinline__ void cpa_wait0()  { asm volatile("cp.async.wait_group 0;\n" ::: "memory"); }

__device__ __forceinline__ void ldsm4(uint32_t& r0, uint32_t& r1, uint32_t& r2, uint32_t& r3, uint32_t a) {
    asm volatile("ldmatrix.sync.aligned.m8n8.x4.shared.b16 {%0,%1,%2,%3}, [%4];"
                 : "=r"(r0), "=r"(r1), "=r"(r2), "=r"(r3) : "r"(a));
}
__device__ __forceinline__ void ldsm2(uint32_t& r0, uint32_t& r1, uint32_t a) {
    asm volatile("ldmatrix.sync.aligned.m8n8.x2.shared.b16 {%0,%1}, [%2];"
                 : "=r"(r0), "=r"(r1) : "r"(a));
}
__device__ __forceinline__ void ldsm2t(uint32_t& r0, uint32_t& r1, uint32_t a) {
    asm volatile("ldmatrix.sync.aligned.m8n8.x2.trans.shared.b16 {%0,%1}, [%2];"
                 : "=r"(r0), "=r"(r1) : "r"(a));
}
__device__ __forceinline__ void mma_bf16(float* c, const uint32_t* a, const uint32_t* b) {
    asm volatile(
        "mma.sync.aligned.m16n8k16.row.col.f32.bf16.bf16.f32 "
        "{%0,%1,%2,%3}, {%4,%5,%6,%7}, {%8,%9}, {%0,%1,%2,%3};\n"
        : "+f"(c[0]), "+f"(c[1]), "+f"(c[2]), "+f"(c[3])
        : "r"(a[0]), "r"(a[1]), "r"(a[2]), "r"(a[3]), "r"(b[0]), "r"(b[1]));
}

// ---------------- generic GEMM building blocks (non-attention kernels) ----------------
template<int BM, int BN, bool BT>
__device__ __forceinline__ void g2s(const bf16* __restrict__ A, int lda,
                                    const bf16* __restrict__ B, int ldb,
                                    int m0, int n0, int k0,
                                    uint32_t aB, uint32_t bB, int tid)
{
    #pragma unroll
    for (int i = tid; i < BM * 4; i += 256) {
        int r = i >> 2, c = i & 3;
        cpa16(aB + r * 80 + c * 16, A + (size_t)(m0 + r) * lda + k0 + c * 8);
    }
    if (BT) {
        #pragma unroll
        for (int i = tid; i < BN * 4; i += 256) {
            int r = i >> 2, c = i & 3;
            cpa16(bB + r * 80 + c * 16, B + (size_t)(n0 + r) * ldb + k0 + c * 8);
        }
    } else {
        constexpr int NC = BN / 8, SBv = BN * 2 + 16;
        #pragma unroll
        for (int i = tid; i < 32 * NC; i += 256) {
            int kr = i / NC, c = i % NC;
            cpa16(bB + kr * SBv + c * 16, B + (size_t)(k0 + kr) * ldb + n0 + c * 8);
        }
    }
    cpa_commit();
}

template<int BM, int BN, bool BT>
__device__ __forceinline__ void smma(uint32_t aB, uint32_t bB, int lane,
                                     int wm0, int wn0, float acc[][BN/32][4])
{
    constexpr int MT = BM / 32, NT = BN / 32, SBv = BT ? 80 : (BN * 2 + 16);
    #pragma unroll
    for (int s = 0; s < 2; s++) {
        uint32_t af[MT][4], bf2[NT][2];
        #pragma unroll
        for (int mi = 0; mi < MT; mi++)
            ldsm4(af[mi][0], af[mi][1], af[mi][2], af[mi][3],
                  aB + (wm0 + mi * 16 + (lane & 15)) * 80 + s * 32 + (lane & 16));
        #pragma unroll
        for (int ni = 0; ni < NT; ni++) {
            if (BT)
                ldsm2(bf2[ni][0], bf2[ni][1],
                      bB + (wn0 + ni * 8 + (lane & 7)) * 80 + s * 32 + ((lane >> 3) & 1) * 16);
            else
                ldsm2t(bf2[ni][0], bf2[ni][1],
                       bB + (s * 16 + (lane & 15)) * SBv + (wn0 + ni * 8) * 2);
        }
        #pragma unroll
        for (int mi = 0; mi < MT; mi++)
            #pragma unroll
            for (int ni = 0; ni < NT; ni++)
                mma_bf16(acc[mi][ni], af[mi], bf2[ni]);
    }
}

template<int BM, int BN, bool BT>
__device__ __forceinline__ void mma_loop(const bf16* __restrict__ A, int lda,
                                         const bf16* __restrict__ B, int ldb,
                                         int K, int m0, int n0,
                                         float acc[][BN/32][4],
                                         unsigned char* sAbuf, unsigned char* sBbuf)
{
    constexpr int SBv  = BT ? 80 : (BN * 2 + 16);
    constexpr int BROW = BT ? BN : 32;
    const int tid = threadIdx.x, lane = tid & 31, warp = tid >> 5;
    const int wm0 = (warp >> 2) * (BM / 2), wn0 = (warp & 3) * (BN / 4);
    uint32_t aB0 = smaddr(sAbuf), aB1 = aB0 + BM * 80;
    uint32_t bB0 = smaddr(sBbuf), bB1 = bB0 + BROW * SBv;

    g2s<BM, BN, BT>(A, lda, B, ldb, m0, n0, 0, aB0, bB0, tid);
    const int nch = K >> 5;
    for (int i = 0; i < nch; i++) {
        cpa_wait0();
        __syncthreads();
        uint32_t aB = (i & 1) ? aB1 : aB0, bB = (i & 1) ? bB1 : bB0;
        if (i + 1 < nch)
            g2s<BM, BN, BT>(A, lda, B, ldb, m0, n0, (i + 1) * 32,
                            (i & 1) ? aB0 : aB1, (i & 1) ? bB0 : bB1, tid);
        smma<BM, BN, BT>(aB, bB, lane, wm0, wn0, acc);
        __syncthreads();
    }
}

template<int BM, int BN>
__device__ __forceinline__ void epi_f32(float acc[][BN/32][4], float* C, int ldc,
                                        int m0, int n0, const float* bias)
{
    const int lane = threadIdx.x & 31, warp = threadIdx.x >> 5;
    const int lr = lane >> 2, lc = lane & 3;
    const int wm0 = (warp >> 2) * (BM / 2), wn0 = (warp & 3) * (BN / 4);
    #pragma unroll
    for (int mi = 0; mi < BM / 32; mi++) {
        int row = m0 + wm0 + mi * 16 + lr;
        #pragma unroll
        for (int ni = 0; ni < BN / 32; ni++) {
            int col = n0 + wn0 + ni * 8 + 2 * lc;
            float bx = 0.f, by = 0.f;
            if (bias) { bx = bias[col]; by = bias[col + 1]; }
            *(float2*)(C + (size_t)row * ldc + col) =
                make_float2(acc[mi][ni][0] + bx, acc[mi][ni][1] + by);
            *(float2*)(C + (size_t)(row + 8) * ldc + col) =
                make_float2(acc[mi][ni][2] + bx, acc[mi][ni][3] + by);
        }
    }
}

template<int BM, int BN>
__device__ __forceinline__ void epi_bf16(float acc[][BN/32][4], bf16* C, int ldc,
                                         int m0, int n0, float alpha)
{
    const int lane = threadIdx.x & 31, warp = threadIdx.x >> 5;
    const int lr = lane >> 2, lc = lane & 3;
    const int wm0 = (warp >> 2) * (BM / 2), wn0 = (warp & 3) * (BN / 4);
    #pragma unroll
    for (int mi = 0; mi < BM / 32; mi++) {
        int row = m0 + wm0 + mi * 16 + lr;
        #pragma unroll
        for (int ni = 0; ni < BN / 32; ni++) {
            int col = n0 + wn0 + ni * 8 + 2 * lc;
            *(bf162*)(C + (size_t)row * ldc + col) =
                __floats2bfloat162_rn(acc[mi][ni][0] * alpha, acc[mi][ni][1] * alpha);
            *(bf162*)(C + (size_t)(row + 8) * ldc + col) =
                __floats2bfloat162_rn(acc[mi][ni][2] * alpha, acc[mi][ni][3] * alpha);
        }
    }
}

// ---------------- kernels ----------------

__global__ __launch_bounds__(256) void k_prep(const float4* __restrict__ Wq,
                                              const float4* __restrict__ Wkv,
                                              const float4* __restrict__ Wout,
                                              const float4* __restrict__ Wff1,
                                              const float4* __restrict__ Wff2)
{
    int i = blockIdx.x * 256 + threadIdx.x;
    const float4* src; bf162* dst; int off;
    if      (i < 32768)   { src = Wq;   dst = (bf162*)g_Wq;   off = 0; }
    else if (i < 98304)   { src = Wkv;  dst = (bf162*)g_Wkv;  off = 32768; }
    else if (i < 2195456) { src = Wout; dst = (bf162*)g_Wout; off = 98304; }
    else if (i < 2326528) { src = Wff1; dst = (bf162*)g_Wff1; off = 2195456; }
    else                  { src = Wff2; dst = (bf162*)g_Wff2; off = 2326528; }
    int j = i - off;
    float4 v = src[j];
    dst[2 * j]     = __floats2bfloat162_rn(v.x, v.y);
    dst[2 * j + 1] = __floats2bfloat162_rn(v.z, v.w);
}

__global__ __launch_bounds__(256) void k_tr(const float* __restrict__ x) {
    __shared__ float tile[32][33];
    int zi = blockIdx.z;
    int b = zi >> 3, m = zi & 7;
    int n0 = blockIdx.x * 32, d0 = blockIdx.y * 32;
    #pragma unroll
    for (int r = 0; r < 4; r++) {
        int d = d0 + threadIdx.y + r * 8;
        tile[threadIdx.y + r * 8][threadIdx.x] =
            x[((size_t)(b * ND + d) * NM + m) * NSEQ + n0 + threadIdx.x];
    }
    __syncthreads();
    #pragma unroll
    for (int r = 0; r < 4; r++) {
        int n = n0 + threadIdx.y + r * 8;
        int d = d0 + threadIdx.x;
        float v = tile[threadIdx.x][threadIdx.y + r * 8];
        size_t o = ((size_t)(b * NSEQ + n) * NM + m) * ND + d;
        g_xt[o]  = v;
        g_xtb[o] = __float2bfloat16(v);
    }
}

// fused Q + KV projection. blockIdx.x<4 -> Q tile (x0.125), else KV tile.
__global__ __launch_bounds__(256) void k_qkv() {
    __shared__ alignas(16) unsigned char sA[2 * 128 * 80];
    __shared__ alignas(16) unsigned char sB[2 * 32 * 272];
    float acc[4][4][4] = {};
    int m0 = blockIdx.y * 128;
    if (blockIdx.x < 4) {
        int n0 = blockIdx.x * 128;
        mma_loop<128, 128, false>(g_xtb, ND, g_Wq, NINNER, ND, m0, n0, acc, sA, sB);
        epi_bf16<128, 128>(acc, g_qb, NINNER, m0, n0, 0.125f);   // fold attn scale
    } else {
        int n0 = (blockIdx.x - 4) * 128;
        mma_loop<128, 128, false>(g_xtb, ND, g_Wkv, 2 * NINNER, ND, m0, n0, acc, sA, sB);
        epi_bf16<128, 128>(acc, g_kvb, 2 * NINNER, m0, n0, 1.f);
    }
}

// ============ fused attention: one CTA per e = (b,h,z), 512 threads ============
// For each chunk (m, j0): S = Q_m @ K^T (j0..j0+63), P = exp(S) -> smem,
// column sums over ALL 256 i (complete in-CTA), rs = 1/sum folded into V rows,
// O += P @ V'.  No HBM intermediates.
#define SATT_K   0
#define SATT_Q0  36864
#define SATT_Q1  73728
#define SATT_P   110592
#define SATT_V0  147456
#define SATT_V1  156672
#define SATT_PART 165888
#define SATT_RS   167936
#define SATT_SZ   168192

__global__ void __launch_bounds__(512, 1) k_attn() {
    extern __shared__ unsigned char smem[];
    const uint32_t base = smaddr(smem);
    const int tid = threadIdx.x, lane = tid & 31, warp = tid >> 5;
    const int lr = lane >> 2, lc = lane & 3;
    const int wm = warp >> 1, wn = warp & 1;          // 8 x 2 warp grid
    const int e = blockIdx.x;
    const int z = e & 7, h = (e >> 3) & 7, b = e >> 6;

    const bf16* Qe = g_qb  + (size_t)(b * 2048) * 512  + h * 64;
    const bf16* Ke = g_kvb + (size_t)(b * 2048) * 1024 + h * 64;
    const bf16* Ve = g_kvb + (size_t)(b * 2048) * 1024 + 512 + h * 64;
    float* part = (float*)(smem + SATT_PART);          // [64 col][8 wm]
    float* rs   = (float*)(smem + SATT_RS);            // [64]

    // loaders (strided rows; 128B rows at stride 144 -> conflict-free ldmatrix)
    auto loadK = [&]() {
        #pragma unroll
        for (int q = 0; q < 4; q++) {
            int idx = tid + q * 512, row = idx >> 3, c = idx & 7;
            cpa16(base + SATT_K + row * 144 + c * 16,
                  Ke + (size_t)(row * 8 + z) * 1024 + c * 8);
        }
    };
    auto loadQ = [&](int m, uint32_t dst) {
        #pragma unroll
        for (int q = 0; q < 4; q++) {
            int idx = tid + q * 512, row = idx >> 3, c = idx & 7;
            cpa16(dst + row * 144 + c * 16,
                  Qe + (size_t)(row * 8 + m) * 512 + c * 8);
        }
    };
    auto loadV = [&](int m, int j0, uint32_t dst) {
        int row = tid >> 3, c = tid & 7;
        cpa16(dst + row * 144 + c * 16,
              Ve + (size_t)((j0 + row) * 8 + m) * 1024 + c * 8);
    };

    float oacc[2][4][4] = {};   // O tile: rows wm*32(+32), cols d = wn*32(+32)

    loadK();
    loadQ(0, base + SATT_Q0);
    loadV(0, 0, base + SATT_V0);
    cpa_commit();

    for (int c = 0; c < 32; c++) {
        const int m = c >> 2, j0 = (c & 3) << 6;
        const uint32_t qB = base + ((m & 1) ? SATT_Q1 : SATT_Q0);
        const uint32_t vB = base + ((c & 1) ? SATT_V1 : SATT_V0);
        cpa_wait0();
        __syncthreads();                               // loads landed; prev PV done
        if (c < 31) {                                  // prefetch next chunk
            int cn = c + 1;
            loadV(cn >> 2, (cn & 3) << 6, base + ((cn & 1) ? SATT_V1 : SATT_V0));
            if ((c & 3) == 0 && m < 7)
                loadQ(m + 1, base + ((m & 1) ? SATT_Q0 : SATT_Q1));
            cpa_commit();
        }
        // ---- S = Q_m @ K[j0:j0+64]^T  (M=256, N=64 split 8x2, K=64) ----
        float sa[2][4][4] = {};
        #pragma unroll
        for (int s = 0; s < 4; s++) {
            uint32_t af[2][4], bf2[4][2];
            #pragma unroll
            for (int mi = 0; mi < 2; mi++)
                ldsm4(af[mi][0], af[mi][1], af[mi][2], af[mi][3],
                      qB + (wm * 32 + mi * 16 + (lane & 15)) * 144 + s * 32 + (lane & 16));
            #pragma unroll
            for (int ni = 0; ni < 4; ni++)
                ldsm2(bf2[ni][0], bf2[ni][1],
                      base + SATT_K + (j0 + wn * 32 + ni * 8 + (lane & 7)) * 144
                      + s * 32 + ((lane >> 3) & 1) * 16);
            #pragma unroll
            for (int mi = 0; mi < 2; mi++)
                #pragma unroll
                for (int ni = 0; ni < 4; ni++)
                    mma_bf16(sa[mi][ni], af[mi], bf2[ni]);
        }
        // ---- exp, write P chunk to smem, per-warp column partials ----
        float cs[4][2];
        #pragma unroll
        for (int ni = 0; ni < 4; ni++) { cs[ni][0] = 0.f; cs[ni][1] = 0.f; }
        #pragma unroll
        for (int mi = 0; mi < 2; mi++) {
            int row = wm * 32 + mi * 16 + lr;
            #pragma unroll
            for (int ni = 0; ni < 4; ni++) {
                int col = wn * 32 + ni * 8 + 2 * lc;
                float p0 = __expf(sa[mi][ni][0]);
                float p1 = __expf(sa[mi][ni][1]);
                float p2 = __expf(sa[mi][ni][2]);
                float p3 = __expf(sa[mi][ni][3]);
                cs[ni][0] += p0 + p2; cs[ni][1] += p1 + p3;
                *(bf162*)(smem + SATT_P + row * 144 + col * 2)       = __floats2bfloat162_rn(p0, p1);
                *(bf162*)(smem + SATT_P + (row + 8) * 144 + col * 2) = __floats2bfloat162_rn(p2, p3);
            }
        }
        #pragma unroll
        for (int ni = 0; ni < 4; ni++) {
            float a = cs[ni][0], bq = cs[ni][1];
            #pragma unroll
            for (int o = 4; o <= 16; o <<= 1) {
                a  += __shfl_xor_sync(0xffffffffu, a,  o);
                bq += __shfl_xor_sync(0xffffffffu, bq, o);
            }
            if (lane < 4) {                              // lr==0 lanes, lc=lane
                int col = wn * 32 + ni * 8 + 2 * lane;
                part[col * 8 + wm]       = a;
                part[(col + 1) * 8 + wm] = bq;
            }
        }
        __syncthreads();
        if (tid < 64) {                                  // complete column sums
            float t = 0.f;
            #pragma unroll
            for (int w8 = 0; w8 < 8; w8++) t += part[tid * 8 + w8];
            rs[tid] = 1.f / t;
        }
        __syncthreads();
        {   // ---- scale V chunk rows by rs (fold softmax normalize into B) ----
            int row = tid >> 3, cc = tid & 7;
            float r = rs[row];
            bf162* vp2 = (bf162*)(smem + (vB - base) + row * 144 + cc * 16);
            #pragma unroll
            for (int q = 0; q < 4; q++) {
                float2 f = __bfloat1622float2(vp2[q]);
                f.x *= r; f.y *= r;
                vp2[q] = __float22bfloat162_rn(f);
            }
        }
        __syncthreads();
        // ---- O += P @ V'  (M=256, N=64 d split, K=64 j) ----
        #pragma unroll
        for (int s = 0; s < 4; s++) {
            uint32_t af[2][4], bf2[4][2];
            #pragma unroll
            for (int mi = 0; mi < 2; mi++)
                ldsm4(af[mi][0], af[mi][1], af[mi][2], af[mi][3],
                      base + SATT_P + (wm * 32 + mi * 16 + (lane & 15)) * 144
                      + s * 32 + (lane & 16));
            #pragma unroll
            for (int ni = 0; ni < 4; ni++)
                ldsm2t(bf2[ni][0], bf2[ni][1],
                       vB + (s * 16 + (lane & 15)) * 144 + (wn * 32 + ni * 8) * 2);
            #pragma unroll
            for (int mi = 0; mi < 2; mi++)
                #pragma unroll
                for (int ni = 0; ni < 4; ni++)
                    mma_bf16(oacc[mi][ni], af[mi], bf2[ni]);
        }
    }
    // ---- epilogue: O -> g_aob[(b*256+i)][z*512 + h*64 + d] ----
    bf16* Ob = g_aob + (size_t)(b * 256) * 4096 + z * 512 + h * 64;
    #pragma unroll
    for (int mi = 0; mi < 2; mi++) {
        int row = wm * 32 + mi * 16 + lr;
        #pragma unroll
        for (int ni = 0; ni < 4; ni++) {
            int col = wn * 32 + ni * 8 + 2 * lc;
            *(bf162*)(Ob + (size_t)row * 4096 + col) =
                __floats2bfloat162_rn(oacc[mi][ni][0], oacc[mi][ni][1]);
            *(bf162*)(Ob + (size_t)(row + 8) * 4096 + col) =
                __floats2bfloat162_rn(oacc[mi][ni][2], oacc[mi][ni][3]);
        }
    }
}

__global__ __launch_bounds__(256) void k_wout(const float* __restrict__ bias) {
    __shared__ alignas(16) unsigned char sA[2 * 64 * 80];
    __shared__ alignas(16) unsigned char sB[2 * 32 * 144];
    float acc[2][2][4] = {};
    int m0 = blockIdx.y * 64, n0 = blockIdx.x * 64;
    mma_loop<64, 64, false>(g_aob, 4096, g_Wout, 2048, 4096, m0, n0, acc, sA, sB);
    epi_f32<64, 64>(acc, g_y1, 2048, m0, n0, bias);
}

__global__ __launch_bounds__(256) void k_ln(int mode,
                                            const float* __restrict__ g,
                                            const float* __restrict__ beta,
                                            float* __restrict__ out) {
    int t = blockIdx.x, d = threadIdx.x;
    float xv, yv;
    if (mode == 1) {
        int bn = t >> 3, m = t & 7;
        xv = g_xt[(size_t)t * ND + d];
        yv = g_y1[(size_t)bn * 2048 + m * ND + d];
    } else {
        xv = g_x2[(size_t)t * ND + d];
        yv = g_y2[(size_t)t * ND + d];
    }
    float v = xv + yv;
    float s = v, s2 = v * v;
    #pragma unroll
    for (int o = 16; o; o >>= 1) {
        s  += __shfl_xor_sync(0xffffffffu, s,  o);
        s2 += __shfl_xor_sync(0xffffffffu, s2, o);
    }
    __shared__ float sh[16];
    int w = d >> 5, l = d & 31;
    if (l == 0) { sh[w] = s; sh[8 + w] = s2; }
    __syncthreads();
    if (d == 0) {
        float ts = 0.f, ts2 = 0.f;
        #pragma unroll
        for (int i = 0; i < 8; i++) { ts += sh[i]; ts2 += sh[8 + i]; }
        float mu  = ts * (1.f / 256.f);
        float var = ts2 * (1.f / 256.f) - mu * mu;
        sh[0] = mu;
        sh[1] = rsqrtf(var + 1e-5f);
    }
    __syncthreads();
    float r = (v - sh[0]) * sh[1] * g[d] + beta[d];
    if (mode == 1) {
        g_x2 [(size_t)t * ND + d] = r;
        g_x2b[(size_t)t * ND + d] = __float2bfloat16(r);
    } else {
        out[(size_t)t * ND + d] = r;
    }
}

__global__ __launch_bounds__(256) void k_ff1g(const float* __restrict__ bias) {
    __shared__ alignas(16) unsigned char sA[2 * 128 * 80];
    __shared__ alignas(16) unsigned char sB[2 * 32 * 144];
    float aA[4][2][4] = {};
    float aG[4][2][4] = {};
    int m0 = blockIdx.y * 128, n0 = blockIdx.x * 64;
    mma_loop<128, 64, false>(g_x2b, ND, g_Wff1, 2048, ND, m0, n0,        aA, sA, sB);
    mma_loop<128, 64, false>(g_x2b, ND, g_Wff1, 2048, ND, m0, n0 + 1024, aG, sA, sB);

    const int lane = threadIdx.x & 31, warp = threadIdx.x >> 5;
    const int lr = lane >> 2, lc = lane & 3;
    const int wm0 = (warp >> 2) * 64, wn0 = (warp & 3) * 16;
    #pragma unroll
    for (int mi = 0; mi < 4; mi++) {
        int row = m0 + wm0 + mi * 16 + lr;
        #pragma unroll
        for (int ni = 0; ni < 2; ni++) {
            int col = n0 + wn0 + ni * 8 + 2 * lc;
            float ba0 = bias[col],        ba1 = bias[col + 1];
            float bg0 = bias[1024 + col], bg1 = bias[1024 + col + 1];
            #pragma unroll
            for (int half = 0; half < 2; half++) {
                int r = row + half * 8;
                float a0 = aA[mi][ni][2 * half + 0] + ba0;
                float a1 = aA[mi][ni][2 * half + 1] + ba1;
                float gt0 = aG[mi][ni][2 * half + 0] + bg0;
                float gt1 = aG[mi][ni][2 * half + 1] + bg1;
                float v0 = a0 * 0.5f * gt0 * (1.f + erff(gt0 * 0.70710678118654752f));
                float v1 = a1 * 0.5f * gt1 * (1.f + erff(gt1 * 0.70710678118654752f));
                *(bf162*)(g_fib + (size_t)r * 1024 + col) = __floats2bfloat162_rn(v0, v1);
            }
        }
    }
}

__global__ __launch_bounds__(256) void k_ff2(const float* __restrict__ bias) {
    __shared__ alignas(16) unsigned char sA[2 * 128 * 80];
    __shared__ alignas(16) unsigned char sB[2 * 32 * 144];
    float acc[4][2][4] = {};
    int m0 = blockIdx.y * 128, n0 = blockIdx.x * 64;
    mma_loop<128, 64, false>(g_fib, 1024, g_Wff2, ND, 1024, m0, n0, acc, sA, sB);
    epi_f32<128, 64>(acc, g_y2, ND, m0, n0, bias);
}

// ---------------- launch ----------------
extern "C" void kernel_launch(void* const* d_in, const int* in_sizes, int n_in,
                              void* d_out, int out_size) {
    const float* x     = (const float*)d_in[0];
    const float* Wq    = (const float*)d_in[1];
    const float* Wkv   = (const float*)d_in[2];
    const float* Wout  = (const float*)d_in[3];
    const float* bout  = (const float*)d_in[4];
    const float* g1    = (const float*)d_in[5];
    const float* beta1 = (const float*)d_in[6];
    const float* Wff1  = (const float*)d_in[7];
    const float* bff1  = (const float*)d_in[8];
    const float* Wff2  = (const float*)d_in[9];
    const float* bff2  = (const float*)d_in[10];
    const float* g2    = (const float*)d_in[11];
    const float* beta2 = (const float*)d_in[12];
    float* out = (float*)d_out;

    static int attr_set = 0;
    if (!attr_set) {
        cudaFuncSetAttribute(k_attn, cudaFuncAttributeMaxDynamicSharedMemorySize, SATT_SZ);
        attr_set = 1;
    }

    k_prep <<<9344, 256>>>((const float4*)Wq, (const float4*)Wkv, (const float4*)Wout,
                           (const float4*)Wff1, (const float4*)Wff2);
    k_tr   <<<dim3(8, 8, 16), dim3(32, 8)>>>(x);
    k_qkv  <<<dim3(12, 32), 256>>>();
    k_attn <<<128, 512, SATT_SZ>>>();
    k_wout <<<dim3(32, 8), 256>>>(bout);
    k_ln   <<<4096, 256>>>(1, g1, beta1, nullptr);
    k_ff1g <<<dim3(16, 32), 256>>>(bff1);
    k_ff2  <<<dim3(4, 32), 256>>>(bff2);
    k_ln   <<<4096, 256>>>(2, g2, beta2, out);
}

// round 9
// speedup vs baseline: 5.4397x; 1.0083x over previous
#include <cuda_runtime.h>
#include <cuda_bf16.h>
#include <math.h>
#include <stdint.h>

#define NB     2
#define NSEQ   256
#define NM     8
#define ND     256
#define NH     8
#define NDH    64
#define NINNER 512
#define NTOK   (NB*NSEQ*NM)          // 4096
#define NBN    (NB*NSEQ)             // 512
typedef __nv_bfloat16 bf16;
typedef __nv_bfloat162 bf162;

// ---------------- scratch ----------------
__device__ float g_xt [NTOK*ND];                       // fp32 (residual)
__device__ bf16  g_xtb[NTOK*ND];
__device__ bf16  g_qb [NTOK*NINNER];
__device__ bf16  g_kvb[NTOK*2*NINNER];
__device__ bf16  g_aob[(size_t)NBN*4096];
__device__ float g_y1 [(size_t)NBN*2048];
__device__ float g_x2 [NTOK*ND];
__device__ bf16  g_x2b[NTOK*ND];
__device__ bf16  g_fib[(size_t)NTOK*1024];
__device__ float g_y2 [NTOK*ND];
// bf16 weights
__device__ bf16  g_Wq  [256*512];
__device__ bf16  g_Wkv [256*1024];
__device__ bf16  g_Wout[(size_t)4096*2048];
__device__ bf16  g_Wff1[256*2048];
__device__ bf16  g_Wff2[1024*256];

// ---------------- ptx helpers ----------------
__device__ __forceinline__ uint32_t smaddr(const void* p) {
    return (uint32_t)__cvta_generic_to_shared(p);
}
__device__ __forceinline__ void cpa16(uint32_t dst, const void* src) {
    asm volatile("cp.async.cg.shared.global [%0], [%1], 16;\n" :: "r"(dst), "l"(src) : "memory");
}
__device__ __forceinline__ void cpa_commit() { asm volatile("cp.async.commit_group;\n" ::: "memory"); }
__device__ __forceinline__ void cpa_wait0()  { asm volatile("cp.async.wait_group 0;\n" ::: "memory"); }
__device__ __forceinline__ void cpa_wait1()  { asm volatile("cp.async.wait_group 1;\n" ::: "memory"); }

__device__ __forceinline__ void bar_sync(int id, int cnt) {
    asm volatile("bar.sync %0, %1;" :: "r"(id), "r"(cnt) : "memory");
}
__device__ __forceinline__ void bar_arrive(int id, int cnt) {
    asm volatile("bar.arrive %0, %1;" :: "r"(id), "r"(cnt) : "memory");
}

__device__ __forceinline__ void ldsm4(uint32_t& r0, uint32_t& r1, uint32_t& r2, uint32_t& r3, uint32_t a) {
    asm volatile("ldmatrix.sync.aligned.m8n8.x4.shared.b16 {%0,%1,%2,%3}, [%4];"
                 : "=r"(r0), "=r"(r1), "=r"(r2), "=r"(r3) : "r"(a));
}
__device__ __forceinline__ void ldsm2(uint32_t& r0, uint32_t& r1, uint32_t a) {
    asm volatile("ldmatrix.sync.aligned.m8n8.x2.shared.b16 {%0,%1}, [%2];"
                 : "=r"(r0), "=r"(r1) : "r"(a));
}
__device__ __forceinline__ void ldsm2t(uint32_t& r0, uint32_t& r1, uint32_t a) {
    asm volatile("ldmatrix.sync.aligned.m8n8.x2.trans.shared.b16 {%0,%1}, [%2];"
                 : "=r"(r0), "=r"(r1) : "r"(a));
}
__device__ __forceinline__ void mma_bf16(float* c, const uint32_t* a, const uint32_t* b) {
    asm volatile(
        "mma.sync.aligned.m16n8k16.row.col.f32.bf16.bf16.f32 "
        "{%0,%1,%2,%3}, {%4,%5,%6,%7}, {%8,%9}, {%0,%1,%2,%3};\n"
        : "+f"(c[0]), "+f"(c[1]), "+f"(c[2]), "+f"(c[3])
        : "r"(a[0]), "r"(a[1]), "r"(a[2]), "r"(a[3]), "r"(b[0]), "r"(b[1]));
}

// ---------------- generic GEMM building blocks (non-attention kernels) ----------------
template<int BM, int BN, bool BT>
__device__ __forceinline__ void g2s(const bf16* __restrict__ A, int lda,
                                    const bf16* __restrict__ B, int ldb,
                                    int m0, int n0, int k0,
                                    uint32_t aB, uint32_t bB, int tid)
{
    #pragma unroll
    for (int i = tid; i < BM * 4; i += 256) {
        int r = i >> 2, c = i & 3;
        cpa16(aB + r * 80 + c * 16, A + (size_t)(m0 + r) * lda + k0 + c * 8);
    }
    if (BT) {
        #pragma unroll
        for (int i = tid; i < BN * 4; i += 256) {
            int r = i >> 2, c = i & 3;
            cpa16(bB + r * 80 + c * 16, B + (size_t)(n0 + r) * ldb + k0 + c * 8);
        }
    } else {
        constexpr int NC = BN / 8, SBv = BN * 2 + 16;
        #pragma unroll
        for (int i = tid; i < 32 * NC; i += 256) {
            int kr = i / NC, c = i % NC;
            cpa16(bB + kr * SBv + c * 16, B + (size_t)(k0 + kr) * ldb + n0 + c * 8);
        }
    }
    cpa_commit();
}

template<int BM, int BN, bool BT>
__device__ __forceinline__ void smma(uint32_t aB, uint32_t bB, int lane,
                                     int wm0, int wn0, float acc[][BN/32][4])
{
    constexpr int MT = BM / 32, NT = BN / 32, SBv = BT ? 80 : (BN * 2 + 16);
    #pragma unroll
    for (int s = 0; s < 2; s++) {
        uint32_t af[MT][4], bf2[NT][2];
        #pragma unroll
        for (int mi = 0; mi < MT; mi++)
            ldsm4(af[mi][0], af[mi][1], af[mi][2], af[mi][3],
                  aB + (wm0 + mi * 16 + (lane & 15)) * 80 + s * 32 + (lane & 16));
        #pragma unroll
        for (int ni = 0; ni < NT; ni++) {
            if (BT)
                ldsm2(bf2[ni][0], bf2[ni][1],
                      bB + (wn0 + ni * 8 + (lane & 7)) * 80 + s * 32 + ((lane >> 3) & 1) * 16);
            else
                ldsm2t(bf2[ni][0], bf2[ni][1],
                       bB + (s * 16 + (lane & 15)) * SBv + (wn0 + ni * 8) * 2);
        }
        #pragma unroll
        for (int mi = 0; mi < MT; mi++)
            #pragma unroll
            for (int ni = 0; ni < NT; ni++)
                mma_bf16(acc[mi][ni], af[mi], bf2[ni]);
    }
}

template<int BM, int BN, bool BT>
__device__ __forceinline__ void mma_loop(const bf16* __restrict__ A, int lda,
                                         const bf16* __restrict__ B, int ldb,
                                         int K, int m0, int n0,
                                         float acc[][BN/32][4],
                                         unsigned char* sAbuf, unsigned char* sBbuf)
{
    constexpr int SBv  = BT ? 80 : (BN * 2 + 16);
    constexpr int BROW = BT ? BN : 32;
    const int tid = threadIdx.x, lane = tid & 31, warp = tid >> 5;
    const int wm0 = (warp >> 2) * (BM / 2), wn0 = (warp & 3) * (BN / 4);
    uint32_t aB0 = smaddr(sAbuf), aB1 = aB0 + BM * 80;
    uint32_t bB0 = smaddr(sBbuf), bB1 = bB0 + BROW * SBv;

    g2s<BM, BN, BT>(A, lda, B, ldb, m0, n0, 0, aB0, bB0, tid);
    const int nch = K >> 5;
    for (int i = 0; i < nch; i++) {
        cpa_wait0();
        __syncthreads();
        uint32_t aB = (i & 1) ? aB1 : aB0, bB = (i & 1) ? bB1 : bB0;
        if (i + 1 < nch)
            g2s<BM, BN, BT>(A, lda, B, ldb, m0, n0, (i + 1) * 32,
                            (i & 1) ? aB0 : aB1, (i & 1) ? bB0 : bB1, tid);
        smma<BM, BN, BT>(aB, bB, lane, wm0, wn0, acc);
        __syncthreads();
    }
}

template<int BM, int BN>
__device__ __forceinline__ void epi_f32(float acc[][BN/32][4], float* C, int ldc,
                                        int m0, int n0, const float* bias)
{
    const int lane = threadIdx.x & 31, warp = threadIdx.x >> 5;
    const int lr = lane >> 2, lc = lane & 3;
    const int wm0 = (warp >> 2) * (BM / 2), wn0 = (warp & 3) * (BN / 4);
    #pragma unroll
    for (int mi = 0; mi < BM / 32; mi++) {
        int row = m0 + wm0 + mi * 16 + lr;
        #pragma unroll
        for (int ni = 0; ni < BN / 32; ni++) {
            int col = n0 + wn0 + ni * 8 + 2 * lc;
            float bx = 0.f, by = 0.f;
            if (bias) { bx = bias[col]; by = bias[col + 1]; }
            *(float2*)(C + (size_t)row * ldc + col) =
                make_float2(acc[mi][ni][0] + bx, acc[mi][ni][1] + by);
            *(float2*)(C + (size_t)(row + 8) * ldc + col) =
                make_float2(acc[mi][ni][2] + bx, acc[mi][ni][3] + by);
        }
    }
}

template<int BM, int BN>
__device__ __forceinline__ void epi_bf16(float acc[][BN/32][4], bf16* C, int ldc,
                                         int m0, int n0, float alpha)
{
    const int lane = threadIdx.x & 31, warp = threadIdx.x >> 5;
    const int lr = lane >> 2, lc = lane & 3;
    const int wm0 = (warp >> 2) * (BM / 2), wn0 = (warp & 3) * (BN / 4);
    #pragma unroll
    for (int mi = 0; mi < BM / 32; mi++) {
        int row = m0 + wm0 + mi * 16 + lr;
        #pragma unroll
        for (int ni = 0; ni < BN / 32; ni++) {
            int col = n0 + wn0 + ni * 8 + 2 * lc;
            *(bf162*)(C + (size_t)row * ldc + col) =
                __floats2bfloat162_rn(acc[mi][ni][0] * alpha, acc[mi][ni][1] * alpha);
            *(bf162*)(C + (size_t)(row + 8) * ldc + col) =
                __floats2bfloat162_rn(acc[mi][ni][2] * alpha, acc[mi][ni][3] * alpha);
        }
    }
}

// ---------------- kernels ----------------

__global__ __launch_bounds__(256) void k_prep(const float4* __restrict__ Wq,
                                              const float4* __restrict__ Wkv,
                                              const float4* __restrict__ Wout,
                                              const float4* __restrict__ Wff1,
                                              const float4* __restrict__ Wff2)
{
    int i = blockIdx.x * 256 + threadIdx.x;
    const float4* src; bf162* dst; int off;
    if      (i < 32768)   { src = Wq;   dst = (bf162*)g_Wq;   off = 0; }
    else if (i < 98304)   { src = Wkv;  dst = (bf162*)g_Wkv;  off = 32768; }
    else if (i < 2195456) { src = Wout; dst = (bf162*)g_Wout; off = 98304; }
    else if (i < 2326528) { src = Wff1; dst = (bf162*)g_Wff1; off = 2195456; }
    else                  { src = Wff2; dst = (bf162*)g_Wff2; off = 2326528; }
    int j = i - off;
    float4 v = src[j];
    dst[2 * j]     = __floats2bfloat162_rn(v.x, v.y);
    dst[2 * j + 1] = __floats2bfloat162_rn(v.z, v.w);
}

__global__ __launch_bounds__(256) void k_tr(const float* __restrict__ x) {
    __shared__ float tile[32][33];
    int zi = blockIdx.z;
    int b = zi >> 3, m = zi & 7;
    int n0 = blockIdx.x * 32, d0 = blockIdx.y * 32;
    #pragma unroll
    for (int r = 0; r < 4; r++) {
        int d = d0 + threadIdx.y + r * 8;
        tile[threadIdx.y + r * 8][threadIdx.x] =
            x[((size_t)(b * ND + d) * NM + m) * NSEQ + n0 + threadIdx.x];
    }
    __syncthreads();
    #pragma unroll
    for (int r = 0; r < 4; r++) {
        int n = n0 + threadIdx.y + r * 8;
        int d = d0 + threadIdx.x;
        float v = tile[threadIdx.x][threadIdx.y + r * 8];
        size_t o = ((size_t)(b * NSEQ + n) * NM + m) * ND + d;
        g_xt[o]  = v;
        g_xtb[o] = __float2bfloat16(v);
    }
}

// fused Q + KV projection. blockIdx.x<4 -> Q tile (x0.125), else KV tile.
__global__ __launch_bounds__(256) void k_qkv() {
    __shared__ alignas(16) unsigned char sA[2 * 128 * 80];
    __shared__ alignas(16) unsigned char sB[2 * 32 * 272];
    float acc[4][4][4] = {};
    int m0 = blockIdx.y * 128;
    if (blockIdx.x < 4) {
        int n0 = blockIdx.x * 128;
        mma_loop<128, 128, false>(g_xtb, ND, g_Wq, NINNER, ND, m0, n0, acc, sA, sB);
        epi_bf16<128, 128>(acc, g_qb, NINNER, m0, n0, 0.125f);   // fold attn scale
    } else {
        int n0 = (blockIdx.x - 4) * 128;
        mma_loop<128, 128, false>(g_xtb, ND, g_Wkv, 2 * NINNER, ND, m0, n0, acc, sA, sB);
        epi_bf16<128, 128>(acc, g_kvb, 2 * NINNER, m0, n0, 1.f);
    }
}

// ============ warp-specialized fused attention: one CTA per e, 512 threads ============
// Producer (warps 0-7): S = Q_m @ K^T, exp in regs, complete column sums,
//   store P' = exp * (1/sum) as bf16 (rs folded into P; V never rewritten).
// Consumer (warps 8-15): O += P' @ V. Double-buffered P/V/Q, named-barrier handshake.
#define SATT_K    0
#define SATT_Q0   36864
#define SATT_Q1   73728
#define SATT_P0   110592
#define SATT_P1   147456
#define SATT_V0   184320
#define SATT_V1   193536
#define SATT_PART 202752
#define SATT_RS   203776
#define SATT_SZ   204032
// barrier ids: FULL0=1 FULL1=2 EMPTY0=3 EMPTY1=4, producer-local=5, consumer-local=6

__global__ void __launch_bounds__(512, 1) k_attn() {
    extern __shared__ unsigned char smem[];
    const uint32_t base = smaddr(smem);
    const int tid = threadIdx.x, lane = tid & 31, warp = tid >> 5;
    const int lr = lane >> 2, lc = lane & 3;
    const int e = blockIdx.x;
    const int z = e & 7, h = (e >> 3) & 7, b = e >> 6;

    const bf16* Qe = g_qb  + (size_t)(b * 2048) * 512  + h * 64;
    const bf16* Ke = g_kvb + (size_t)(b * 2048) * 1024 + h * 64;
    const bf16* Ve = g_kvb + (size_t)(b * 2048) * 1024 + 512 + h * 64;
    float* part = (float*)(smem + SATT_PART);   // [64 col][4 wm]
    float* rs   = (float*)(smem + SATT_RS);     // [64]

    const uint32_t qB[2] = { base + SATT_Q0, base + SATT_Q1 };
    const uint32_t pB[2] = { base + SATT_P0, base + SATT_P1 };
    const uint32_t vB[2] = { base + SATT_V0, base + SATT_V1 };

    if (warp < 8) {
        // ---------------- PRODUCER ----------------
        const int ptid = tid;                 // 0..255
        const int wm = warp >> 1, wn = warp & 1;   // 4(m:64 rows) x 2(n:32 cols)
        auto loadK = [&]() {
            #pragma unroll
            for (int q = 0; q < 8; q++) {
                int idx = ptid + q * 256, row = idx >> 3, cc = idx & 7;
                cpa16(base + SATT_K + row * 144 + cc * 16,
                      Ke + (size_t)(row * 8 + z) * 1024 + cc * 8);
            }
        };
        auto loadQ = [&](int m, uint32_t dst) {
            #pragma unroll
            for (int q = 0; q < 8; q++) {
                int idx = ptid + q * 256, row = idx >> 3, cc = idx & 7;
                cpa16(dst + row * 144 + cc * 16,
                      Qe + (size_t)(row * 8 + m) * 512 + cc * 8);
            }
        };
        loadK();
        loadQ(0, qB[0]);
        cpa_commit();

        for (int c = 0; c < 32; c++) {
            const int m = c >> 2, j0 = (c & 3) << 6, s = c & 1;
            if ((c & 3) == 0) {
                if (m < 7) loadQ(m + 1, qB[(m + 1) & 1]);
                cpa_commit();
                cpa_wait1();                  // all but newest group done -> K, Q(m) ready
                bar_sync(5, 256);
            }
            bar_sync(3 + s, 512);             // EMPTY[s]: P buffer free
            const uint32_t qb = qB[m & 1];
            // ---- S = Q_m @ K[j0:+64]^T  (warp tile 64x32) ----
            float sa[4][4][4] = {};
            #pragma unroll
            for (int s4 = 0; s4 < 4; s4++) {
                uint32_t af[4][4], bf2[4][2];
                #pragma unroll
                for (int mi = 0; mi < 4; mi++)
                    ldsm4(af[mi][0], af[mi][1], af[mi][2], af[mi][3],
                          qb + (wm * 64 + mi * 16 + (lane & 15)) * 144 + s4 * 32 + (lane & 16));
                #pragma unroll
                for (int ni = 0; ni < 4; ni++)
                    ldsm2(bf2[ni][0], bf2[ni][1],
                          base + SATT_K + (j0 + wn * 32 + ni * 8 + (lane & 7)) * 144
                          + s4 * 32 + ((lane >> 3) & 1) * 16);
                #pragma unroll
                for (int mi = 0; mi < 4; mi++)
                    #pragma unroll
                    for (int ni = 0; ni < 4; ni++)
                        mma_bf16(sa[mi][ni], af[mi], bf2[ni]);
            }
            // ---- exp in regs + column partial sums ----
            float cs[4][2];
            #pragma unroll
            for (int ni = 0; ni < 4; ni++) { cs[ni][0] = 0.f; cs[ni][1] = 0.f; }
            #pragma unroll
            for (int mi = 0; mi < 4; mi++)
                #pragma unroll
                for (int ni = 0; ni < 4; ni++) {
                    float p0 = __expf(sa[mi][ni][0]);
                    float p1 = __expf(sa[mi][ni][1]);
                    float p2 = __expf(sa[mi][ni][2]);
                    float p3 = __expf(sa[mi][ni][3]);
                    sa[mi][ni][0] = p0; sa[mi][ni][1] = p1;
                    sa[mi][ni][2] = p2; sa[mi][ni][3] = p3;
                    cs[ni][0] += p0 + p2; cs[ni][1] += p1 + p3;
                }
            #pragma unroll
            for (int ni = 0; ni < 4; ni++) {
                float a = cs[ni][0], bq = cs[ni][1];
                #pragma unroll
                for (int o = 4; o <= 16; o <<= 1) {
                    a  += __shfl_xor_sync(0xffffffffu, a,  o);
                    bq += __shfl_xor_sync(0xffffffffu, bq, o);
                }
                if (lane < 4) {
                    int col = wn * 32 + ni * 8 + 2 * lane;
                    part[col * 4 + wm]       = a;
                    part[(col + 1) * 4 + wm] = bq;
                }
            }
            bar_sync(5, 256);
            if (ptid < 64)
                rs[ptid] = 1.f / (part[4 * ptid] + part[4 * ptid + 1]
                                + part[4 * ptid + 2] + part[4 * ptid + 3]);
            bar_sync(5, 256);
            // ---- store P' = exp * rs ----
            const uint32_t pb = pB[s];
            #pragma unroll
            for (int ni = 0; ni < 4; ni++) {
                int col = wn * 32 + ni * 8 + 2 * lc;
                float r0 = rs[col], r1 = rs[col + 1];
                #pragma unroll
                for (int mi = 0; mi < 4; mi++) {
                    int row = wm * 64 + mi * 16 + lr;
                    *(bf162*)(smem + (pb - base) + row * 144 + col * 2) =
                        __floats2bfloat162_rn(sa[mi][ni][0] * r0, sa[mi][ni][1] * r1);
                    *(bf162*)(smem + (pb - base) + (row + 8) * 144 + col * 2) =
                        __floats2bfloat162_rn(sa[mi][ni][2] * r0, sa[mi][ni][3] * r1);
                }
            }
            bar_arrive(1 + s, 512);           // FULL[s]
        }
    } else {
        // ---------------- CONSUMER ----------------
        const int ctid = tid - 256;           // 0..255
        const int cw = warp - 8;
        const int wm = cw >> 1, wn = cw & 1;
        auto loadV = [&](int m, int j0, uint32_t dst) {
            #pragma unroll
            for (int q = 0; q < 2; q++) {
                int idx = ctid + q * 256, row = idx >> 3, cc = idx & 7;
                cpa16(dst + row * 144 + cc * 16,
                      Ve + (size_t)((j0 + row) * 8 + m) * 1024 + cc * 8);
            }
        };
        bar_arrive(3, 512);                   // pre-arrive EMPTY0
        bar_arrive(4, 512);                   // pre-arrive EMPTY1
        loadV(0, 0, vB[0]);
        cpa_commit();

        float oacc[4][4][4] = {};
        for (int c = 0; c < 32; c++) {
            const int s = c & 1;
            if (c < 31) {
                int cn = c + 1;
                loadV(cn >> 2, (cn & 3) << 6, vB[cn & 1]);
                cpa_commit();
                cpa_wait1();
            } else {
                cpa_wait0();
            }
            bar_sync(6, 256);                 // V[s] visible to consumer group
            bar_sync(1 + s, 512);             // FULL[s]: P'[s] ready
            const uint32_t pb = pB[s], vb = vB[s];
            #pragma unroll
            for (int s4 = 0; s4 < 4; s4++) {
                uint32_t af[4][4], bf2[4][2];
                #pragma unroll
                for (int mi = 0; mi < 4; mi++)
                    ldsm4(af[mi][0], af[mi][1], af[mi][2], af[mi][3],
                          pb + (wm * 64 + mi * 16 + (lane & 15)) * 144 + s4 * 32 + (lane & 16));
                #pragma unroll
                for (int ni = 0; ni < 4; ni++)
                    ldsm2t(bf2[ni][0], bf2[ni][1],
                           vb + (s4 * 16 + (lane & 15)) * 144 + (wn * 32 + ni * 8) * 2);
                #pragma unroll
                for (int mi = 0; mi < 4; mi++)
                    #pragma unroll
                    for (int ni = 0; ni < 4; ni++)
                        mma_bf16(oacc[mi][ni], af[mi], bf2[ni]);
            }
            bar_arrive(3 + s, 512);           // EMPTY[s]
        }
        // ---- epilogue: O -> g_aob[(b*256+i)][z*512 + h*64 + d] ----
        bf16* Ob = g_aob + (size_t)(b * 256) * 4096 + z * 512 + h * 64;
        #pragma unroll
        for (int mi = 0; mi < 4; mi++) {
            int row = wm * 64 + mi * 16 + lr;
            #pragma unroll
            for (int ni = 0; ni < 4; ni++) {
                int col = wn * 32 + ni * 8 + 2 * lc;
                *(bf162*)(Ob + (size_t)row * 4096 + col) =
                    __floats2bfloat162_rn(oacc[mi][ni][0], oacc[mi][ni][1]);
                *(bf162*)(Ob + (size_t)(row + 8) * 4096 + col) =
                    __floats2bfloat162_rn(oacc[mi][ni][2], oacc[mi][ni][3]);
            }
        }
    }
}

__global__ __launch_bounds__(256) void k_wout(const float* __restrict__ bias) {
    __shared__ alignas(16) unsigned char sA[2 * 128 * 80];
    __shared__ alignas(16) unsigned char sB[2 * 32 * 144];
    float acc[4][2][4] = {};
    int m0 = blockIdx.y * 128, n0 = blockIdx.x * 64;
    mma_loop<128, 64, false>(g_aob, 4096, g_Wout, 2048, 4096, m0, n0, acc, sA, sB);
    epi_f32<128, 64>(acc, g_y1, 2048, m0, n0, bias);
}

__global__ __launch_bounds__(256) void k_ln(int mode,
                                            const float* __restrict__ g,
                                            const float* __restrict__ beta,
                                            float* __restrict__ out) {
    int t = blockIdx.x, d = threadIdx.x;
    float xv, yv;
    if (mode == 1) {
        int bn = t >> 3, m = t & 7;
        xv = g_xt[(size_t)t * ND + d];
        yv = g_y1[(size_t)bn * 2048 + m * ND + d];
    } else {
        xv = g_x2[(size_t)t * ND + d];
        yv = g_y2[(size_t)t * ND + d];
    }
    float v = xv + yv;
    float s = v, s2 = v * v;
    #pragma unroll
    for (int o = 16; o; o >>= 1) {
        s  += __shfl_xor_sync(0xffffffffu, s,  o);
        s2 += __shfl_xor_sync(0xffffffffu, s2, o);
    }
    __shared__ float sh[16];
    int w = d >> 5, l = d & 31;
    if (l == 0) { sh[w] = s; sh[8 + w] = s2; }
    __syncthreads();
    if (d == 0) {
        float ts = 0.f, ts2 = 0.f;
        #pragma unroll
        for (int i = 0; i < 8; i++) { ts += sh[i]; ts2 += sh[8 + i]; }
        float mu  = ts * (1.f / 256.f);
        float var = ts2 * (1.f / 256.f) - mu * mu;
        sh[0] = mu;
        sh[1] = rsqrtf(var + 1e-5f);
    }
    __syncthreads();
    float r = (v - sh[0]) * sh[1] * g[d] + beta[d];
    if (mode == 1) {
        g_x2 [(size_t)t * ND + d] = r;
        g_x2b[(size_t)t * ND + d] = __float2bfloat16(r);
    } else {
        out[(size_t)t * ND + d] = r;
    }
}

__global__ __launch_bounds__(256) void k_ff1g(const float* __restrict__ bias) {
    __shared__ alignas(16) unsigned char sA[2 * 128 * 80];
    __shared__ alignas(16) unsigned char sB[2 * 32 * 144];
    float aA[4][2][4] = {};
    float aG[4][2][4] = {};
    int m0 = blockIdx.y * 128, n0 = blockIdx.x * 64;
    mma_loop<128, 64, false>(g_x2b, ND, g_Wff1, 2048, ND, m0, n0,        aA, sA, sB);
    mma_loop<128, 64, false>(g_x2b, ND, g_Wff1, 2048, ND, m0, n0 + 1024, aG, sA, sB);

    const int lane = threadIdx.x & 31, warp = threadIdx.x >> 5;
    const int lr = lane >> 2, lc = lane & 3;
    const int wm0 = (warp >> 2) * 64, wn0 = (warp & 3) * 16;
    #pragma unroll
    for (int mi = 0; mi < 4; mi++) {
        int row = m0 + wm0 + mi * 16 + lr;
        #pragma unroll
        for (int ni = 0; ni < 2; ni++) {
            int col = n0 + wn0 + ni * 8 + 2 * lc;
            float ba0 = bias[col],        ba1 = bias[col + 1];
            float bg0 = bias[1024 + col], bg1 = bias[1024 + col + 1];
            #pragma unroll
            for (int half = 0; half < 2; half++) {
                int r = row + half * 8;
                float a0 = aA[mi][ni][2 * half + 0] + ba0;
                float a1 = aA[mi][ni][2 * half + 1] + ba1;
                float gt0 = aG[mi][ni][2 * half + 0] + bg0;
                float gt1 = aG[mi][ni][2 * half + 1] + bg1;
                float v0 = a0 * 0.5f * gt0 * (1.f + erff(gt0 * 0.70710678118654752f));
                float v1 = a1 * 0.5f * gt1 * (1.f + erff(gt1 * 0.70710678118654752f));
                *(bf162*)(g_fib + (size_t)r * 1024 + col) = __floats2bfloat162_rn(v0, v1);
            }
        }
    }
}

__global__ __launch_bounds__(256) void k_ff2(const float* __restrict__ bias) {
    __shared__ alignas(16) unsigned char sA[2 * 128 * 80];
    __shared__ alignas(16) unsigned char sB[2 * 32 * 144];
    float acc[4][2][4] = {};
    int m0 = blockIdx.y * 128, n0 = blockIdx.x * 64;
    mma_loop<128, 64, false>(g_fib, 1024, g_Wff2, ND, 1024, m0, n0, acc, sA, sB);
    epi_f32<128, 64>(acc, g_y2, ND, m0, n0, bias);
}

// ---------------- launch ----------------
extern "C" void kernel_launch(void* const* d_in, const int* in_sizes, int n_in,
                              void* d_out, int out_size) {
    const float* x     = (const float*)d_in[0];
    const float* Wq    = (const float*)d_in[1];
    const float* Wkv   = (const float*)d_in[2];
    const float* Wout  = (const float*)d_in[3];
    const float* bout  = (const float*)d_in[4];
    const float* g1    = (const float*)d_in[5];
    const float* beta1 = (const float*)d_in[6];
    const float* Wff1  = (const float*)d_in[7];
    const float* bff1  = (const float*)d_in[8];
    const float* Wff2  = (const float*)d_in[9];
    const float* bff2  = (const float*)d_in[10];
    const float* g2    = (const float*)d_in[11];
    const float* beta2 = (const float*)d_in[12];
    float* out = (float*)d_out;

    static int attr_set = 0;
    if (!attr_set) {
        cudaFuncSetAttribute(k_attn, cudaFuncAttributeMaxDynamicSharedMemorySize, SATT_SZ);
        attr_set = 1;
    }

    k_prep <<<9344, 256>>>((const float4*)Wq, (const float4*)Wkv, (const float4*)Wout,
                           (const float4*)Wff1, (const float4*)Wff2);
    k_tr   <<<dim3(8, 8, 16), dim3(32, 8)>>>(x);
    k_qkv  <<<dim3(12, 32), 256>>>();
    k_attn <<<128, 512, SATT_SZ>>>();
    k_wout <<<dim3(32, 4), 256>>>(bout);
    k_ln   <<<4096, 256>>>(1, g1, beta1, nullptr);
    k_ff1g <<<dim3(16, 32), 256>>>(bff1);
    k_ff2  <<<dim3(4, 32), 256>>>(bff2);
    k_ln   <<<4096, 256>>>(2, g2, beta2, out);
}

// round 10
// speedup vs baseline: 6.4002x; 1.1766x over previous
#include <cuda_runtime.h>
#include <cuda_bf16.h>
#include <math.h>
#include <stdint.h>

#define NB     2
#define NSEQ   256
#define NM     8
#define ND     256
#define NH     8
#define NDH    64
#define NINNER 512
#define NTOK   (NB*NSEQ*NM)          // 4096
#define NBN    (NB*NSEQ)             // 512
typedef __nv_bfloat16 bf16;
typedef __nv_bfloat162 bf162;

#define QSCALE 0.18033688011112042f   // 0.125 * log2(e): exp(S) == exp2(S')

// ---------------- scratch ----------------
__device__ float g_xt [NTOK*ND];                       // fp32 (residual)
__device__ bf16  g_xtb[NTOK*ND];
__device__ bf16  g_qb [NTOK*NINNER];
__device__ bf16  g_kvb[NTOK*2*NINNER];
__device__ bf16  g_aob[(size_t)NBN*4096];
__device__ float g_y1 [(size_t)NBN*2048];
__device__ float g_x2 [NTOK*ND];
__device__ bf16  g_x2b[NTOK*ND];
__device__ bf16  g_fib[(size_t)NTOK*1024];
__device__ float g_y2 [NTOK*ND];
// bf16 weights
__device__ bf16  g_Wq  [256*512];
__device__ bf16  g_Wkv [256*1024];
__device__ bf16  g_Wout[(size_t)4096*2048];
__device__ bf16  g_Wff1[256*2048];
__device__ bf16  g_Wff2[1024*256];

// ---------------- ptx helpers ----------------
__device__ __forceinline__ uint32_t smaddr(const void* p) {
    return (uint32_t)__cvta_generic_to_shared(p);
}
__device__ __forceinline__ void cpa16(uint32_t dst, const void* src) {
    asm volatile("cp.async.cg.shared.global [%0], [%1], 16;\n" :: "r"(dst), "l"(src) : "memory");
}
__device__ __forceinline__ void cpa_commit() { asm volatile("cp.async.commit_group;\n" ::: "memory"); }
__device__ __forceinline__ void cpa_wait0()  { asm volatile("cp.async.wait_group 0;\n" ::: "memory"); }
__device__ __forceinline__ void cpa_wait1()  { asm volatile("cp.async.wait_group 1;\n" ::: "memory"); }

__device__ __forceinline__ void bar_sync(int id, int cnt) {
    asm volatile("bar.sync %0, %1;" :: "r"(id), "r"(cnt) : "memory");
}
__device__ __forceinline__ void bar_arrive(int id, int cnt) {
    asm volatile("bar.arrive %0, %1;" :: "r"(id), "r"(cnt) : "memory");
}
__device__ __forceinline__ float fex2(float x) {
    float r;
    asm("ex2.approx.f32 %0, %1;" : "=f"(r) : "f"(x));
    return r;
}

__device__ __forceinline__ void ldsm4(uint32_t& r0, uint32_t& r1, uint32_t& r2, uint32_t& r3, uint32_t a) {
    asm volatile("ldmatrix.sync.aligned.m8n8.x4.shared.b16 {%0,%1,%2,%3}, [%4];"
                 : "=r"(r0), "=r"(r1), "=r"(r2), "=r"(r3) : "r"(a));
}
__device__ __forceinline__ void ldsm2(uint32_t& r0, uint32_t& r1, uint32_t a) {
    asm volatile("ldmatrix.sync.aligned.m8n8.x2.shared.b16 {%0,%1}, [%2];"
                 : "=r"(r0), "=r"(r1) : "r"(a));
}
__device__ __forceinline__ void ldsm2t(uint32_t& r0, uint32_t& r1, uint32_t a) {
    asm volatile("ldmatrix.sync.aligned.m8n8.x2.trans.shared.b16 {%0,%1}, [%2];"
                 : "=r"(r0), "=r"(r1) : "r"(a));
}
__device__ __forceinline__ void mma_bf16(float* c, const uint32_t* a, const uint32_t* b) {
    asm volatile(
        "mma.sync.aligned.m16n8k16.row.col.f32.bf16.bf16.f32 "
        "{%0,%1,%2,%3}, {%4,%5,%6,%7}, {%8,%9}, {%0,%1,%2,%3};\n"
        : "+f"(c[0]), "+f"(c[1]), "+f"(c[2]), "+f"(c[3])
        : "r"(a[0]), "r"(a[1]), "r"(a[2]), "r"(a[3]), "r"(b[0]), "r"(b[1]));
}

// ---------------- dense GEMM building blocks (K-chunk 64, dynamic smem) ----------------
// A smem: [BM rows][144B] (64 bf16 + 16B pad). B smem: [64 rows][BN*2+16].

template<int BM, int BN>
__device__ __forceinline__ void g2s64(const bf16* __restrict__ A, int lda,
                                      const bf16* __restrict__ B, int ldb,
                                      int m0, int n0, int k0,
                                      uint32_t aB, uint32_t bB, int tid)
{
    #pragma unroll
    for (int i = tid; i < BM * 8; i += 256) {
        int r = i >> 3, c = i & 7;
        cpa16(aB + r * 144 + c * 16, A + (size_t)(m0 + r) * lda + k0 + c * 8);
    }
    constexpr int NC = BN / 8, SBv = BN * 2 + 16;
    #pragma unroll
    for (int i = tid; i < 64 * NC; i += 256) {
        int kr = i / NC, c = i % NC;
        cpa16(bB + kr * SBv + c * 16, B + (size_t)(k0 + kr) * ldb + n0 + c * 8);
    }
    cpa_commit();
}

template<int BM, int BN>
__device__ __forceinline__ void smma64(uint32_t aB, uint32_t bB, int lane,
                                       int wm0, int wn0, float acc[][BN/32][4])
{
    constexpr int MT = BM / 32, NT = BN / 32, SBv = BN * 2 + 16;
    #pragma unroll
    for (int s = 0; s < 4; s++) {
        uint32_t af[MT][4], bf2[NT][2];
        #pragma unroll
        for (int mi = 0; mi < MT; mi++)
            ldsm4(af[mi][0], af[mi][1], af[mi][2], af[mi][3],
                  aB + (wm0 + mi * 16 + (lane & 15)) * 144 + s * 32 + (lane & 16));
        #pragma unroll
        for (int ni = 0; ni < NT; ni++)
            ldsm2t(bf2[ni][0], bf2[ni][1],
                   bB + (s * 16 + (lane & 15)) * SBv + (wn0 + ni * 8) * 2);
        #pragma unroll
        for (int mi = 0; mi < MT; mi++)
            #pragma unroll
            for (int ni = 0; ni < NT; ni++)
                mma_bf16(acc[mi][ni], af[mi], bf2[ni]);
    }
}

template<int BM, int BN>
__device__ __forceinline__ void mma_loop(const bf16* __restrict__ A, int lda,
                                         const bf16* __restrict__ B, int ldb,
                                         int K, int m0, int n0,
                                         float acc[][BN/32][4],
                                         unsigned char* sAbuf, unsigned char* sBbuf)
{
    constexpr int SBv = BN * 2 + 16;
    const int tid = threadIdx.x, lane = tid & 31, warp = tid >> 5;
    const int wm0 = (warp >> 2) * (BM / 2), wn0 = (warp & 3) * (BN / 4);
    uint32_t aB0 = smaddr(sAbuf), aB1 = aB0 + BM * 144;
    uint32_t bB0 = smaddr(sBbuf), bB1 = bB0 + 64 * SBv;

    g2s64<BM, BN>(A, lda, B, ldb, m0, n0, 0, aB0, bB0, tid);
    const int nch = K >> 6;
    for (int i = 0; i < nch; i++) {
        cpa_wait0();
        __syncthreads();
        uint32_t aB = (i & 1) ? aB1 : aB0, bB = (i & 1) ? bB1 : bB0;
        if (i + 1 < nch)
            g2s64<BM, BN>(A, lda, B, ldb, m0, n0, (i + 1) * 64,
                          (i & 1) ? aB0 : aB1, (i & 1) ? bB0 : bB1, tid);
        smma64<BM, BN>(aB, bB, lane, wm0, wn0, acc);
        __syncthreads();
    }
}

// smem budgets
#define SM_QKV  (2*128*144 + 2*64*272)   // 71680
#define SM_G64  (2*128*144 + 2*64*144)   // 55296

// ---------------- epilogue helpers ----------------
template<int BM, int BN>
__device__ __forceinline__ void epi_f32(float acc[][BN/32][4], float* C, int ldc,
                                        int m0, int n0, const float* bias)
{
    const int lane = threadIdx.x & 31, warp = threadIdx.x >> 5;
    const int lr = lane >> 2, lc = lane & 3;
    const int wm0 = (warp >> 2) * (BM / 2), wn0 = (warp & 3) * (BN / 4);
    #pragma unroll
    for (int mi = 0; mi < BM / 32; mi++) {
        int row = m0 + wm0 + mi * 16 + lr;
        #pragma unroll
        for (int ni = 0; ni < BN / 32; ni++) {
            int col = n0 + wn0 + ni * 8 + 2 * lc;
            float bx = 0.f, by = 0.f;
            if (bias) { bx = bias[col]; by = bias[col + 1]; }
            *(float2*)(C + (size_t)row * ldc + col) =
                make_float2(acc[mi][ni][0] + bx, acc[mi][ni][1] + by);
            *(float2*)(C + (size_t)(row + 8) * ldc + col) =
                make_float2(acc[mi][ni][2] + bx, acc[mi][ni][3] + by);
        }
    }
}

template<int BM, int BN>
__device__ __forceinline__ void epi_bf16(float acc[][BN/32][4], bf16* C, int ldc,
                                         int m0, int n0, float alpha)
{
    const int lane = threadIdx.x & 31, warp = threadIdx.x >> 5;
    const int lr = lane >> 2, lc = lane & 3;
    const int wm0 = (warp >> 2) * (BM / 2), wn0 = (warp & 3) * (BN / 4);
    #pragma unroll
    for (int mi = 0; mi < BM / 32; mi++) {
        int row = m0 + wm0 + mi * 16 + lr;
        #pragma unroll
        for (int ni = 0; ni < BN / 32; ni++) {
            int col = n0 + wn0 + ni * 8 + 2 * lc;
            *(bf162*)(C + (size_t)row * ldc + col) =
                __floats2bfloat162_rn(acc[mi][ni][0] * alpha, acc[mi][ni][1] * alpha);
            *(bf162*)(C + (size_t)(row + 8) * ldc + col) =
                __floats2bfloat162_rn(acc[mi][ni][2] * alpha, acc[mi][ni][3] * alpha);
        }
    }
}

// ---------------- kernels ----------------

__global__ __launch_bounds__(256) void k_prep(const float4* __restrict__ Wq,
                                              const float4* __restrict__ Wkv,
                                              const float4* __restrict__ Wout,
                                              const float4* __restrict__ Wff1,
                                              const float4* __restrict__ Wff2)
{
    int i = blockIdx.x * 256 + threadIdx.x;
    const float4* src; bf162* dst; int off;
    if      (i < 32768)   { src = Wq;   dst = (bf162*)g_Wq;   off = 0; }
    else if (i < 98304)   { src = Wkv;  dst = (bf162*)g_Wkv;  off = 32768; }
    else if (i < 2195456) { src = Wout; dst = (bf162*)g_Wout; off = 98304; }
    else if (i < 2326528) { src = Wff1; dst = (bf162*)g_Wff1; off = 2195456; }
    else                  { src = Wff2; dst = (bf162*)g_Wff2; off = 2326528; }
    int j = i - off;
    float4 v = src[j];
    dst[2 * j]     = __floats2bfloat162_rn(v.x, v.y);
    dst[2 * j + 1] = __floats2bfloat162_rn(v.z, v.w);
}

__global__ __launch_bounds__(256) void k_tr(const float* __restrict__ x) {
    __shared__ float tile[32][33];
    int zi = blockIdx.z;
    int b = zi >> 3, m = zi & 7;
    int n0 = blockIdx.x * 32, d0 = blockIdx.y * 32;
    #pragma unroll
    for (int r = 0; r < 4; r++) {
        int d = d0 + threadIdx.y + r * 8;
        tile[threadIdx.y + r * 8][threadIdx.x] =
            x[((size_t)(b * ND + d) * NM + m) * NSEQ + n0 + threadIdx.x];
    }
    __syncthreads();
    #pragma unroll
    for (int r = 0; r < 4; r++) {
        int n = n0 + threadIdx.y + r * 8;
        int d = d0 + threadIdx.x;
        float v = tile[threadIdx.x][threadIdx.y + r * 8];
        size_t o = ((size_t)(b * NSEQ + n) * NM + m) * ND + d;
        g_xt[o]  = v;
        g_xtb[o] = __float2bfloat16(v);
    }
}

// fused Q + KV projection. blockIdx.x<4 -> Q tile (x QSCALE), else KV tile.
__global__ __launch_bounds__(256) void k_qkv() {
    extern __shared__ unsigned char dsm[];
    unsigned char* sA = dsm;
    unsigned char* sB = dsm + 2 * 128 * 144;
    float acc[4][4][4] = {};
    int m0 = blockIdx.y * 128;
    if (blockIdx.x < 4) {
        int n0 = blockIdx.x * 128;
        mma_loop<128, 128>(g_xtb, ND, g_Wq, NINNER, ND, m0, n0, acc, sA, sB);
        epi_bf16<128, 128>(acc, g_qb, NINNER, m0, n0, QSCALE);   // fold scale + log2e
    } else {
        int n0 = (blockIdx.x - 4) * 128;
        mma_loop<128, 128>(g_xtb, ND, g_Wkv, 2 * NINNER, ND, m0, n0, acc, sA, sB);
        epi_bf16<128, 128>(acc, g_kvb, 2 * NINNER, m0, n0, 1.f);
    }
}

// ============ warp-specialized fused attention: one CTA per e, 512 threads ============
// Producer (warps 0-7): S' = Q_m @ K^T (log2e pre-folded), raw exp2 -> P[s] (bf16),
//   column partial sums -> part[s]. Barriers: EMPTY wait + FULL arrive only.
// Consumer (warps 8-15): computes rs from part, folds rs into V rows, O += P @ V'.
#define SATT_K    0
#define SATT_Q0   36864
#define SATT_Q1   73728
#define SATT_P0   110592
#define SATT_P1   147456
#define SATT_V0   184320
#define SATT_V1   193536
#define SATT_PART 202752
#define SATT_RSC  204800
#define SATT_SZ   205056
// barrier ids: FULL0=1 FULL1=2 EMPTY0=3 EMPTY1=4, producer-local=5, consumer-local=6

__global__ void __launch_bounds__(512, 1) k_attn() {
    extern __shared__ unsigned char smem[];
    const uint32_t base = smaddr(smem);
    const int tid = threadIdx.x, lane = tid & 31, warp = tid >> 5;
    const int lr = lane >> 2, lc = lane & 3;
    const int e = blockIdx.x;
    const int z = e & 7, h = (e >> 3) & 7, b = e >> 6;

    const bf16* Qe = g_qb  + (size_t)(b * 2048) * 512  + h * 64;
    const bf16* Ke = g_kvb + (size_t)(b * 2048) * 1024 + h * 64;
    const bf16* Ve = g_kvb + (size_t)(b * 2048) * 1024 + 512 + h * 64;
    float* part = (float*)(smem + SATT_PART);   // [2][64 col][4 wm]
    float* rsc  = (float*)(smem + SATT_RSC);    // [64]

    const uint32_t qB[2] = { base + SATT_Q0, base + SATT_Q1 };
    const uint32_t pB[2] = { base + SATT_P0, base + SATT_P1 };
    const uint32_t vB[2] = { base + SATT_V0, base + SATT_V1 };

    if (warp < 8) {
        // ---------------- PRODUCER ----------------
        const int ptid = tid;                      // 0..255
        const int wm = warp >> 1, wn = warp & 1;   // 4(m:64 rows) x 2(n:32 cols)
        auto loadK = [&]() {
            #pragma unroll
            for (int q = 0; q < 8; q++) {
                int idx = ptid + q * 256, row = idx >> 3, cc = idx & 7;
                cpa16(base + SATT_K + row * 144 + cc * 16,
                      Ke + (size_t)(row * 8 + z) * 1024 + cc * 8);
            }
        };
        auto loadQ = [&](int m, uint32_t dst) {
            #pragma unroll
            for (int q = 0; q < 8; q++) {
                int idx = ptid + q * 256, row = idx >> 3, cc = idx & 7;
                cpa16(dst + row * 144 + cc * 16,
                      Qe + (size_t)(row * 8 + m) * 512 + cc * 8);
            }
        };
        loadK();
        loadQ(0, qB[0]);
        cpa_commit();

        for (int c = 0; c < 32; c++) {
            const int m = c >> 2, j0 = (c & 3) << 6, s = c & 1;
            if ((c & 3) == 0) {
                if (m < 7) loadQ(m + 1, qB[(m + 1) & 1]);
                cpa_commit();
                cpa_wait1();                       // K + Q(m) landed
                bar_sync(5, 256);
            }
            bar_sync(3 + s, 512);                  // EMPTY[s]: P[s], part[s] free
            const uint32_t qb = qB[m & 1];
            // ---- S' = Q_m @ K[j0:+64]^T  (warp tile 64x32) ----
            float sa[4][4][4] = {};
            #pragma unroll
            for (int s4 = 0; s4 < 4; s4++) {
                uint32_t af[4][4], bf2[4][2];
                #pragma unroll
                for (int mi = 0; mi < 4; mi++)
                    ldsm4(af[mi][0], af[mi][1], af[mi][2], af[mi][3],
                          qb + (wm * 64 + mi * 16 + (lane & 15)) * 144 + s4 * 32 + (lane & 16));
                #pragma unroll
                for (int ni = 0; ni < 4; ni++)
                    ldsm2(bf2[ni][0], bf2[ni][1],
                          base + SATT_K + (j0 + wn * 32 + ni * 8 + (lane & 7)) * 144
                          + s4 * 32 + ((lane >> 3) & 1) * 16);
                #pragma unroll
                for (int mi = 0; mi < 4; mi++)
                    #pragma unroll
                    for (int ni = 0; ni < 4; ni++)
                        mma_bf16(sa[mi][ni], af[mi], bf2[ni]);
            }
            // ---- exp2 in regs + column partial sums ----
            float cs[4][2];
            #pragma unroll
            for (int ni = 0; ni < 4; ni++) { cs[ni][0] = 0.f; cs[ni][1] = 0.f; }
            #pragma unroll
            for (int mi = 0; mi < 4; mi++)
                #pragma unroll
                for (int ni = 0; ni < 4; ni++) {
                    float p0 = fex2(sa[mi][ni][0]);
                    float p1 = fex2(sa[mi][ni][1]);
                    float p2 = fex2(sa[mi][ni][2]);
                    float p3 = fex2(sa[mi][ni][3]);
                    sa[mi][ni][0] = p0; sa[mi][ni][1] = p1;
                    sa[mi][ni][2] = p2; sa[mi][ni][3] = p3;
                    cs[ni][0] += p0 + p2; cs[ni][1] += p1 + p3;
                }
            #pragma unroll
            for (int ni = 0; ni < 4; ni++) {
                float a = cs[ni][0], bq = cs[ni][1];
                #pragma unroll
                for (int o = 4; o <= 16; o <<= 1) {
                    a  += __shfl_xor_sync(0xffffffffu, a,  o);
                    bq += __shfl_xor_sync(0xffffffffu, bq, o);
                }
                if (lane < 4) {
                    int col = wn * 32 + ni * 8 + 2 * lane;
                    part[s * 256 + col * 4 + wm]       = a;
                    part[s * 256 + (col + 1) * 4 + wm] = bq;
                }
            }
            // ---- store raw exp P ----
            const uint32_t po = (s ? SATT_P1 : SATT_P0);
            #pragma unroll
            for (int ni = 0; ni < 4; ni++) {
                int col = wn * 32 + ni * 8 + 2 * lc;
                #pragma unroll
                for (int mi = 0; mi < 4; mi++) {
                    int row = wm * 64 + mi * 16 + lr;
                    *(bf162*)(smem + po + row * 144 + col * 2) =
                        __floats2bfloat162_rn(sa[mi][ni][0], sa[mi][ni][1]);
                    *(bf162*)(smem + po + (row + 8) * 144 + col * 2) =
                        __floats2bfloat162_rn(sa[mi][ni][2], sa[mi][ni][3]);
                }
            }
            bar_arrive(1 + s, 512);                // FULL[s]
        }
    } else {
        // ---------------- CONSUMER ----------------
        const int ctid = tid - 256;                // 0..255
        const int cw = warp - 8;
        const int wm = cw >> 1, wn = cw & 1;
        auto loadV = [&](int m, int j0, uint32_t dst) {
            #pragma unroll
            for (int q = 0; q < 2; q++) {
                int idx = ctid + q * 256, row = idx >> 3, cc = idx & 7;
                cpa16(dst + row * 144 + cc * 16,
                      Ve + (size_t)((j0 + row) * 8 + m) * 1024 + cc * 8);
            }
        };
        bar_arrive(3, 512);                        // pre-arrive EMPTY0
        bar_arrive(4, 512);                        // pre-arrive EMPTY1
        loadV(0, 0, vB[0]);
        cpa_commit();

        float oacc[4][4][4] = {};
        for (int c = 0; c < 32; c++) {
            const int s = c & 1;
            bar_sync(1 + s, 512);                  // FULL[s]; also all consumers done MMA(c-1)
            if (c < 31) {                          // safe: every consumer passed MMA(c-1)
                int cn = c + 1;
                loadV(cn >> 2, (cn & 3) << 6, vB[cn & 1]);
                cpa_commit();
                cpa_wait1();                       // V(c) landed
            } else {
                cpa_wait0();
            }
            if (ctid < 64)
                rsc[ctid] = 1.f / (part[s * 256 + 4 * ctid]     + part[s * 256 + 4 * ctid + 1]
                                 + part[s * 256 + 4 * ctid + 2] + part[s * 256 + 4 * ctid + 3]);
            bar_sync(6, 256);                      // rsc + V(c) visible to group
            const uint32_t vb = vB[s], pb = pB[s];
            {   // fold rs into V rows (row = j index)
                #pragma unroll
                for (int q = 0; q < 2; q++) {
                    int idx = ctid + q * 256, row = idx >> 3, cc = idx & 7;
                    float r = rsc[row];
                    bf162* vp2 = (bf162*)(smem + (vb - base) + row * 144 + cc * 16);
                    #pragma unroll
                    for (int qq = 0; qq < 4; qq++) {
                        float2 f = __bfloat1622float2(vp2[qq]);
                        f.x *= r; f.y *= r;
                        vp2[qq] = __float22bfloat162_rn(f);
                    }
                }
            }
            bar_sync(6, 256);                      // V' ready
            #pragma unroll
            for (int s4 = 0; s4 < 4; s4++) {
                uint32_t af[4][4], bf2[4][2];
                #pragma unroll
                for (int mi = 0; mi < 4; mi++)
                    ldsm4(af[mi][0], af[mi][1], af[mi][2], af[mi][3],
                          pb + (wm * 64 + mi * 16 + (lane & 15)) * 144 + s4 * 32 + (lane & 16));
                #pragma unroll
                for (int ni = 0; ni < 4; ni++)
                    ldsm2t(bf2[ni][0], bf2[ni][1],
                           vb + (s4 * 16 + (lane & 15)) * 144 + (wn * 32 + ni * 8) * 2);
                #pragma unroll
                for (int mi = 0; mi < 4; mi++)
                    #pragma unroll
                    for (int ni = 0; ni < 4; ni++)
                        mma_bf16(oacc[mi][ni], af[mi], bf2[ni]);
            }
            bar_arrive(3 + s, 512);                // EMPTY[s]
        }
        // ---- epilogue ----
        bf16* Ob = g_aob + (size_t)(b * 256) * 4096 + z * 512 + h * 64;
        #pragma unroll
        for (int mi = 0; mi < 4; mi++) {
            int row = wm * 64 + mi * 16 + lr;
            #pragma unroll
            for (int ni = 0; ni < 4; ni++) {
                int col = wn * 32 + ni * 8 + 2 * lc;
                *(bf162*)(Ob + (size_t)row * 4096 + col) =
                    __floats2bfloat162_rn(oacc[mi][ni][0], oacc[mi][ni][1]);
                *(bf162*)(Ob + (size_t)(row + 8) * 4096 + col) =
                    __floats2bfloat162_rn(oacc[mi][ni][2], oacc[mi][ni][3]);
            }
        }
    }
}

__global__ __launch_bounds__(256) void k_wout(const float* __restrict__ bias) {
    extern __shared__ unsigned char dsm[];
    unsigned char* sA = dsm;
    unsigned char* sB = dsm + 2 * 128 * 144;
    float acc[4][2][4] = {};
    int m0 = blockIdx.y * 128, n0 = blockIdx.x * 64;
    mma_loop<128, 64>(g_aob, 4096, g_Wout, 2048, 4096, m0, n0, acc, sA, sB);
    epi_f32<128, 64>(acc, g_y1, 2048, m0, n0, bias);
}

__global__ __launch_bounds__(256) void k_ln(int mode,
                                            const float* __restrict__ g,
                                            const float* __restrict__ beta,
                                            float* __restrict__ out) {
    int t = blockIdx.x, d = threadIdx.x;
    float xv, yv;
    if (mode == 1) {
        int bn = t >> 3, m = t & 7;
        xv = g_xt[(size_t)t * ND + d];
        yv = g_y1[(size_t)bn * 2048 + m * ND + d];
    } else {
        xv = g_x2[(size_t)t * ND + d];
        yv = g_y2[(size_t)t * ND + d];
    }
    float v = xv + yv;
    float s = v, s2 = v * v;
    #pragma unroll
    for (int o = 16; o; o >>= 1) {
        s  += __shfl_xor_sync(0xffffffffu, s,  o);
        s2 += __shfl_xor_sync(0xffffffffu, s2, o);
    }
    __shared__ float sh[16];
    int w = d >> 5, l = d & 31;
    if (l == 0) { sh[w] = s; sh[8 + w] = s2; }
    __syncthreads();
    if (d == 0) {
        float ts = 0.f, ts2 = 0.f;
        #pragma unroll
        for (int i = 0; i < 8; i++) { ts += sh[i]; ts2 += sh[8 + i]; }
        float mu  = ts * (1.f / 256.f);
        float var = ts2 * (1.f / 256.f) - mu * mu;
        sh[0] = mu;
        sh[1] = rsqrtf(var + 1e-5f);
    }
    __syncthreads();
    float r = (v - sh[0]) * sh[1] * g[d] + beta[d];
    if (mode == 1) {
        g_x2 [(size_t)t * ND + d] = r;
        g_x2b[(size_t)t * ND + d] = __float2bfloat16(r);
    } else {
        out[(size_t)t * ND + d] = r;
    }
}

__global__ __launch_bounds__(256) void k_ff1g(const float* __restrict__ bias) {
    extern __shared__ unsigned char dsm[];
    unsigned char* sA = dsm;
    unsigned char* sB = dsm + 2 * 128 * 144;
    float aA[4][2][4] = {};
    float aG[4][2][4] = {};
    int m0 = blockIdx.y * 128, n0 = blockIdx.x * 64;
    mma_loop<128, 64>(g_x2b, ND, g_Wff1, 2048, ND, m0, n0,        aA, sA, sB);
    mma_loop<128, 64>(g_x2b, ND, g_Wff1, 2048, ND, m0, n0 + 1024, aG, sA, sB);

    const int lane = threadIdx.x & 31, warp = threadIdx.x >> 5;
    const int lr = lane >> 2, lc = lane & 3;
    const int wm0 = (warp >> 2) * 64, wn0 = (warp & 3) * 16;
    #pragma unroll
    for (int mi = 0; mi < 4; mi++) {
        int row = m0 + wm0 + mi * 16 + lr;
        #pragma unroll
        for (int ni = 0; ni < 2; ni++) {
            int col = n0 + wn0 + ni * 8 + 2 * lc;
            float ba0 = bias[col],        ba1 = bias[col + 1];
            float bg0 = bias[1024 + col], bg1 = bias[1024 + col + 1];
            #pragma unroll
            for (int half = 0; half < 2; half++) {
                int r = row + half * 8;
                float a0 = aA[mi][ni][2 * half + 0] + ba0;
                float a1 = aA[mi][ni][2 * half + 1] + ba1;
                float gt0 = aG[mi][ni][2 * half + 0] + bg0;
                float gt1 = aG[mi][ni][2 * half + 1] + bg1;
                float v0 = a0 * 0.5f * gt0 * (1.f + erff(gt0 * 0.70710678118654752f));
                float v1 = a1 * 0.5f * gt1 * (1.f + erff(gt1 * 0.70710678118654752f));
                *(bf162*)(g_fib + (size_t)r * 1024 + col) = __floats2bfloat162_rn(v0, v1);
            }
        }
    }
}

__global__ __launch_bounds__(256) void k_ff2(const float* __restrict__ bias) {
    extern __shared__ unsigned char dsm[];
    unsigned char* sA = dsm;
    unsigned char* sB = dsm + 2 * 128 * 144;
    float acc[4][2][4] = {};
    int m0 = blockIdx.y * 128, n0 = blockIdx.x * 64;
    mma_loop<128, 64>(g_fib, 1024, g_Wff2, ND, 1024, m0, n0, acc, sA, sB);
    epi_f32<128, 64>(acc, g_y2, ND, m0, n0, bias);
}

// ---------------- launch ----------------
extern "C" void kernel_launch(void* const* d_in, const int* in_sizes, int n_in,
                              void* d_out, int out_size) {
    const float* x     = (const float*)d_in[0];
    const float* Wq    = (const float*)d_in[1];
    const float* Wkv   = (const float*)d_in[2];
    const float* Wout  = (const float*)d_in[3];
    const float* bout  = (const float*)d_in[4];
    const float* g1    = (const float*)d_in[5];
    const float* beta1 = (const float*)d_in[6];
    const float* Wff1  = (const float*)d_in[7];
    const float* bff1  = (const float*)d_in[8];
    const float* Wff2  = (const float*)d_in[9];
    const float* bff2  = (const float*)d_in[10];
    const float* g2    = (const float*)d_in[11];
    const float* beta2 = (const float*)d_in[12];
    float* out = (float*)d_out;

    static int attr_set = 0;
    if (!attr_set) {
        cudaFuncSetAttribute(k_attn, cudaFuncAttributeMaxDynamicSharedMemorySize, SATT_SZ);
        cudaFuncSetAttribute(k_qkv,  cudaFuncAttributeMaxDynamicSharedMemorySize, SM_QKV);
        cudaFuncSetAttribute(k_wout, cudaFuncAttributeMaxDynamicSharedMemorySize, SM_G64);
        cudaFuncSetAttribute(k_ff1g, cudaFuncAttributeMaxDynamicSharedMemorySize, SM_G64);
        cudaFuncSetAttribute(k_ff2,  cudaFuncAttributeMaxDynamicSharedMemorySize, SM_G64);
        attr_set = 1;
    }

    k_prep <<<9344, 256>>>((const float4*)Wq, (const float4*)Wkv, (const float4*)Wout,
                           (const float4*)Wff1, (const float4*)Wff2);
    k_tr   <<<dim3(8, 8, 16), dim3(32, 8)>>>(x);
    k_qkv  <<<dim3(12, 32), 256, SM_QKV>>>();
    k_attn <<<128, 512, SATT_SZ>>>();
    k_wout <<<dim3(32, 4), 256, SM_G64>>>(bout);
    k_ln   <<<4096, 256>>>(1, g1, beta1, nullptr);
    k_ff1g <<<dim3(16, 32), 256, SM_G64>>>(bff1);
    k_ff2  <<<dim3(4, 32), 256, SM_G64>>>(bff2);
    k_ln   <<<4096, 256>>>(2, g2, beta2, out);
}

// round 12
// speedup vs baseline: 6.9297x; 1.0827x over previous
#include <cuda_runtime.h>
#include <cuda_bf16.h>
#include <math.h>
#include <stdint.h>

#define NB     2
#define NSEQ   256
#define NM     8
#define ND     256
#define NH     8
#define NDH    64
#define NINNER 512
#define NTOK   (NB*NSEQ*NM)          // 4096
#define NBN    (NB*NSEQ)             // 512
typedef __nv_bfloat16 bf16;
typedef __nv_bfloat162 bf162;

#define QSCALE 0.18033688011112042f   // 0.125 * log2(e): exp(S) == exp2(S')

// ---------------- scratch ----------------
__device__ float g_xt [NTOK*ND];                       // fp32 (residual)
__device__ bf16  g_xtb[NTOK*ND];
__device__ bf16  g_qb [NTOK*NINNER];
__device__ bf16  g_kvb[NTOK*2*NINNER];
__device__ bf16  g_aob[(size_t)NBN*4096];
__device__ float g_wp [(size_t)4*NBN*2048];            // wout split-K partials (16.8MB)
__device__ float g_x2 [NTOK*ND];
__device__ bf16  g_x2b[NTOK*ND];
__device__ bf16  g_fib[(size_t)NTOK*1024];
__device__ float g_y2p[(size_t)2*NTOK*ND];             // ff2 split-K partials (8.4MB)
// bf16 weights
__device__ bf16  g_Wq  [256*512];
__device__ bf16  g_Wkv [256*1024];
__device__ bf16  g_Wout[(size_t)4096*2048];
__device__ bf16  g_Wff1[256*2048];
__device__ bf16  g_Wff2[1024*256];

// ---------------- ptx helpers ----------------
__device__ __forceinline__ uint32_t smaddr(const void* p) {
    return (uint32_t)__cvta_generic_to_shared(p);
}
__device__ __forceinline__ void cpa16(uint32_t dst, const void* src) {
    asm volatile("cp.async.cg.shared.global [%0], [%1], 16;\n" :: "r"(dst), "l"(src) : "memory");
}
__device__ __forceinline__ void cpa_commit() { asm volatile("cp.async.commit_group;\n" ::: "memory"); }
__device__ __forceinline__ void cpa_wait0()  { asm volatile("cp.async.wait_group 0;\n" ::: "memory"); }
__device__ __forceinline__ void cpa_wait1()  { asm volatile("cp.async.wait_group 1;\n" ::: "memory"); }

__device__ __forceinline__ void bar_sync(int id, int cnt) {
    asm volatile("bar.sync %0, %1;" :: "r"(id), "r"(cnt) : "memory");
}
__device__ __forceinline__ void bar_arrive(int id, int cnt) {
    asm volatile("bar.arrive %0, %1;" :: "r"(id), "r"(cnt) : "memory");
}
__device__ __forceinline__ float fex2(float x) {
    float r;
    asm("ex2.approx.f32 %0, %1;" : "=f"(r) : "f"(x));
    return r;
}

__device__ __forceinline__ void ldsm4(uint32_t& r0, uint32_t& r1, uint32_t& r2, uint32_t& r3, uint32_t a) {
    asm volatile("ldmatrix.sync.aligned.m8n8.x4.shared.b16 {%0,%1,%2,%3}, [%4];"
                 : "=r"(r0), "=r"(r1), "=r"(r2), "=r"(r3) : "r"(a));
}
__device__ __forceinline__ void ldsm2(uint32_t& r0, uint32_t& r1, uint32_t a) {
    asm volatile("ldmatrix.sync.aligned.m8n8.x2.shared.b16 {%0,%1}, [%2];"
                 : "=r"(r0), "=r"(r1) : "r"(a));
}
__device__ __forceinline__ void ldsm2t(uint32_t& r0, uint32_t& r1, uint32_t a) {
    asm volatile("ldmatrix.sync.aligned.m8n8.x2.trans.shared.b16 {%0,%1}, [%2];"
                 : "=r"(r0), "=r"(r1) : "r"(a));
}
__device__ __forceinline__ void mma_bf16(float* c, const uint32_t* a, const uint32_t* b) {
    asm volatile(
        "mma.sync.aligned.m16n8k16.row.col.f32.bf16.bf16.f32 "
        "{%0,%1,%2,%3}, {%4,%5,%6,%7}, {%8,%9}, {%0,%1,%2,%3};\n"
        : "+f"(c[0]), "+f"(c[1]), "+f"(c[2]), "+f"(c[3])
        : "r"(a[0]), "r"(a[1]), "r"(a[2]), "r"(a[3]), "r"(b[0]), "r"(b[1]));
}

// ---------------- dense GEMM building blocks (K-chunk 64, dynamic smem) ----------------
// A smem: [BM rows][144B] (64 bf16 + 16B pad). B smem: [64 rows][BN*2+16].

template<int BM, int BN>
__device__ __forceinline__ void g2s64(const bf16* __restrict__ A, int lda,
                                      const bf16* __restrict__ B, int ldb,
                                      int m0, int n0, int k0,
                                      uint32_t aB, uint32_t bB, int tid)
{
    #pragma unroll
    for (int i = tid; i < BM * 8; i += 256) {
        int r = i >> 3, c = i & 7;
        cpa16(aB + r * 144 + c * 16, A + (size_t)(m0 + r) * lda + k0 + c * 8);
    }
    constexpr int NC = BN / 8, SBv = BN * 2 + 16;
    #pragma unroll
    for (int i = tid; i < 64 * NC; i += 256) {
        int kr = i / NC, c = i % NC;
        cpa16(bB + kr * SBv + c * 16, B + (size_t)(k0 + kr) * ldb + n0 + c * 8);
    }
    cpa_commit();
}

template<int BM, int BN>
__device__ __forceinline__ void smma64(uint32_t aB, uint32_t bB, int lane,
                                       int wm0, int wn0, float acc[][BN/32][4])
{
    constexpr int MT = BM / 32, NT = BN / 32, SBv = BN * 2 + 16;
    #pragma unroll
    for (int s = 0; s < 4; s++) {
        uint32_t af[MT][4], bf2[NT][2];
        #pragma unroll
        for (int mi = 0; mi < MT; mi++)
            ldsm4(af[mi][0], af[mi][1], af[mi][2], af[mi][3],
                  aB + (wm0 + mi * 16 + (lane & 15)) * 144 + s * 32 + (lane & 16));
        #pragma unroll
        for (int ni = 0; ni < NT; ni++)
            ldsm2t(bf2[ni][0], bf2[ni][1],
                   bB + (s * 16 + (lane & 15)) * SBv + (wn0 + ni * 8) * 2);
        #pragma unroll
        for (int mi = 0; mi < MT; mi++)
            #pragma unroll
            for (int ni = 0; ni < NT; ni++)
                mma_bf16(acc[mi][ni], af[mi], bf2[ni]);
    }
}

template<int BM, int BN>
__device__ __forceinline__ void mma_loop(const bf16* __restrict__ A, int lda,
                                         const bf16* __restrict__ B, int ldb,
                                         int K, int m0, int n0,
                                         float acc[][BN/32][4],
                                         unsigned char* sAbuf, unsigned char* sBbuf)
{
    constexpr int SBv = BN * 2 + 16;
    const int tid = threadIdx.x, lane = tid & 31, warp = tid >> 5;
    const int wm0 = (warp >> 2) * (BM / 2), wn0 = (warp & 3) * (BN / 4);
    uint32_t aB0 = smaddr(sAbuf), aB1 = aB0 + BM * 144;
    uint32_t bB0 = smaddr(sBbuf), bB1 = bB0 + 64 * SBv;

    g2s64<BM, BN>(A, lda, B, ldb, m0, n0, 0, aB0, bB0, tid);
    const int nch = K >> 6;
    for (int i = 0; i < nch; i++) {
        cpa_wait0();
        __syncthreads();
        uint32_t aB = (i & 1) ? aB1 : aB0, bB = (i & 1) ? bB1 : bB0;
        if (i + 1 < nch)
            g2s64<BM, BN>(A, lda, B, ldb, m0, n0, (i + 1) * 64,
                          (i & 1) ? aB0 : aB1, (i & 1) ? bB0 : bB1, tid);
        smma64<BM, BN>(aB, bB, lane, wm0, wn0, acc);
        __syncthreads();
    }
}

// smem budgets
#define SM_QKV  (2*128*144 + 2*64*272)   // 71680
#define SM_G64  (2*128*144 + 2*64*144)   // 55296

// ---------------- epilogue helpers ----------------
template<int BM, int BN>
__device__ __forceinline__ void epi_f32(float acc[][BN/32][4], float* C, int ldc,
                                        int m0, int n0, const float* bias)
{
    const int lane = threadIdx.x & 31, warp = threadIdx.x >> 5;
    const int lr = lane >> 2, lc = lane & 3;
    const int wm0 = (warp >> 2) * (BM / 2), wn0 = (warp & 3) * (BN / 4);
    #pragma unroll
    for (int mi = 0; mi < BM / 32; mi++) {
        int row = m0 + wm0 + mi * 16 + lr;
        #pragma unroll
        for (int ni = 0; ni < BN / 32; ni++) {
            int col = n0 + wn0 + ni * 8 + 2 * lc;
            float bx = 0.f, by = 0.f;
            if (bias) { bx = bias[col]; by = bias[col + 1]; }
            *(float2*)(C + (size_t)row * ldc + col) =
                make_float2(acc[mi][ni][0] + bx, acc[mi][ni][1] + by);
            *(float2*)(C + (size_t)(row + 8) * ldc + col) =
                make_float2(acc[mi][ni][2] + bx, acc[mi][ni][3] + by);
        }
    }
}

template<int BM, int BN>
__device__ __forceinline__ void epi_bf16(float acc[][BN/32][4], bf16* C, int ldc,
                                         int m0, int n0, float alpha)
{
    const int lane = threadIdx.x & 31, warp = threadIdx.x >> 5;
    const int lr = lane >> 2, lc = lane & 3;
    const int wm0 = (warp >> 2) * (BM / 2), wn0 = (warp & 3) * (BN / 4);
    #pragma unroll
    for (int mi = 0; mi < BM / 32; mi++) {
        int row = m0 + wm0 + mi * 16 + lr;
        #pragma unroll
        for (int ni = 0; ni < BN / 32; ni++) {
            int col = n0 + wn0 + ni * 8 + 2 * lc;
            *(bf162*)(C + (size_t)row * ldc + col) =
                __floats2bfloat162_rn(acc[mi][ni][0] * alpha, acc[mi][ni][1] * alpha);
            *(bf162*)(C + (size_t)(row + 8) * ldc + col) =
                __floats2bfloat162_rn(acc[mi][ni][2] * alpha, acc[mi][ni][3] * alpha);
        }
    }
}

// ---------------- kernels ----------------

__global__ __launch_bounds__(256) void k_prep(const float4* __restrict__ Wq,
                                              const float4* __restrict__ Wkv,
                                              const float4* __restrict__ Wout,
                                              const float4* __restrict__ Wff1,
                                              const float4* __restrict__ Wff2)
{
    int i = blockIdx.x * 256 + threadIdx.x;
    const float4* src; bf162* dst; int off;
    if      (i < 32768)   { src = Wq;   dst = (bf162*)g_Wq;   off = 0; }
    else if (i < 98304)   { src = Wkv;  dst = (bf162*)g_Wkv;  off = 32768; }
    else if (i < 2195456) { src = Wout; dst = (bf162*)g_Wout; off = 98304; }
    else if (i < 2326528) { src = Wff1; dst = (bf162*)g_Wff1; off = 2195456; }
    else                  { src = Wff2; dst = (bf162*)g_Wff2; off = 2326528; }
    int j = i - off;
    float4 v = src[j];
    dst[2 * j]     = __floats2bfloat162_rn(v.x, v.y);
    dst[2 * j + 1] = __floats2bfloat162_rn(v.z, v.w);
}

__global__ __launch_bounds__(256) void k_tr(const float* __restrict__ x) {
    __shared__ float tile[32][33];
    int zi = blockIdx.z;
    int b = zi >> 3, m = zi & 7;
    int n0 = blockIdx.x * 32, d0 = blockIdx.y * 32;
    #pragma unroll
    for (int r = 0; r < 4; r++) {
        int d = d0 + threadIdx.y + r * 8;
        tile[threadIdx.y + r * 8][threadIdx.x] =
            x[((size_t)(b * ND + d) * NM + m) * NSEQ + n0 + threadIdx.x];
    }
    __syncthreads();
    #pragma unroll
    for (int r = 0; r < 4; r++) {
        int n = n0 + threadIdx.y + r * 8;
        int d = d0 + threadIdx.x;
        float v = tile[threadIdx.x][threadIdx.y + r * 8];
        size_t o = ((size_t)(b * NSEQ + n) * NM + m) * ND + d;
        g_xt[o]  = v;
        g_xtb[o] = __float2bfloat16(v);
    }
}

// fused Q + KV projection. blockIdx.x<4 -> Q tile (x QSCALE), else KV tile.
__global__ __launch_bounds__(256) void k_qkv() {
    extern __shared__ unsigned char dsm[];
    unsigned char* sA = dsm;
    unsigned char* sB = dsm + 2 * 128 * 144;
    float acc[4][4][4] = {};
    int m0 = blockIdx.y * 128;
    if (blockIdx.x < 4) {
        int n0 = blockIdx.x * 128;
        mma_loop<128, 128>(g_xtb, ND, g_Wq, NINNER, ND, m0, n0, acc, sA, sB);
        epi_bf16<128, 128>(acc, g_qb, NINNER, m0, n0, QSCALE);   // fold scale + log2e
    } else {
        int n0 = (blockIdx.x - 4) * 128;
        mma_loop<128, 128>(g_xtb, ND, g_Wkv, 2 * NINNER, ND, m0, n0, acc, sA, sB);
        epi_bf16<128, 128>(acc, g_kvb, 2 * NINNER, m0, n0, 1.f);
    }
}

// ============ warp-specialized fused attention: one CTA per e, 512 threads ============
#define SATT_K    0
#define SATT_Q0   36864
#define SATT_Q1   73728
#define SATT_P0   110592
#define SATT_P1   147456
#define SATT_V0   184320
#define SATT_V1   193536
#define SATT_PART 202752
#define SATT_RSC  204800
#define SATT_SZ   205056
// barrier ids: FULL0=1 FULL1=2 EMPTY0=3 EMPTY1=4, producer-local=5, consumer-local=6

__global__ void __launch_bounds__(512, 1) k_attn() {
    extern __shared__ unsigned char smem[];
    const uint32_t base = smaddr(smem);
    const int tid = threadIdx.x, lane = tid & 31, warp = tid >> 5;
    const int lr = lane >> 2, lc = lane & 3;
    const int e = blockIdx.x;
    const int z = e & 7, h = (e >> 3) & 7, b = e >> 6;

    const bf16* Qe = g_qb  + (size_t)(b * 2048) * 512  + h * 64;
    const bf16* Ke = g_kvb + (size_t)(b * 2048) * 1024 + h * 64;
    const bf16* Ve = g_kvb + (size_t)(b * 2048) * 1024 + 512 + h * 64;
    float* part = (float*)(smem + SATT_PART);   // [2][64 col][4 wm]
    float* rsc  = (float*)(smem + SATT_RSC);    // [64]

    const uint32_t qB[2] = { base + SATT_Q0, base + SATT_Q1 };
    const uint32_t pB[2] = { base + SATT_P0, base + SATT_P1 };
    const uint32_t vB[2] = { base + SATT_V0, base + SATT_V1 };

    if (warp < 8) {
        // ---------------- PRODUCER ----------------
        const int ptid = tid;                      // 0..255
        const int wm = warp >> 1, wn = warp & 1;   // 4(m:64 rows) x 2(n:32 cols)
        auto loadK = [&]() {
            #pragma unroll
            for (int q = 0; q < 8; q++) {
                int idx = ptid + q * 256, row = idx >> 3, cc = idx & 7;
                cpa16(base + SATT_K + row * 144 + cc * 16,
                      Ke + (size_t)(row * 8 + z) * 1024 + cc * 8);
            }
        };
        auto loadQ = [&](int m, uint32_t dst) {
            #pragma unroll
            for (int q = 0; q < 8; q++) {
                int idx = ptid + q * 256, row = idx >> 3, cc = idx & 7;
                cpa16(dst + row * 144 + cc * 16,
                      Qe + (size_t)(row * 8 + m) * 512 + cc * 8);
            }
        };
        loadK();
        loadQ(0, qB[0]);
        cpa_commit();

        for (int c = 0; c < 32; c++) {
            const int m = c >> 2, j0 = (c & 3) << 6, s = c & 1;
            if ((c & 3) == 0) {
                if (m < 7) loadQ(m + 1, qB[(m + 1) & 1]);
                cpa_commit();
                cpa_wait1();                       // K + Q(m) landed
                bar_sync(5, 256);
            }
            bar_sync(3 + s, 512);                  // EMPTY[s]: P[s], part[s] free
            const uint32_t qb = qB[m & 1];
            // ---- S' = Q_m @ K[j0:+64]^T  (warp tile 64x32) ----
            float sa[4][4][4] = {};
            #pragma unroll
            for (int s4 = 0; s4 < 4; s4++) {
                uint32_t af[4][4], bf2[4][2];
                #pragma unroll
                for (int mi = 0; mi < 4; mi++)
                    ldsm4(af[mi][0], af[mi][1], af[mi][2], af[mi][3],
                          qb + (wm * 64 + mi * 16 + (lane & 15)) * 144 + s4 * 32 + (lane & 16));
                #pragma unroll
                for (int ni = 0; ni < 4; ni++)
                    ldsm2(bf2[ni][0], bf2[ni][1],
                          base + SATT_K + (j0 + wn * 32 + ni * 8 + (lane & 7)) * 144
                          + s4 * 32 + ((lane >> 3) & 1) * 16);
                #pragma unroll
                for (int mi = 0; mi < 4; mi++)
                    #pragma unroll
                    for (int ni = 0; ni < 4; ni++)
                        mma_bf16(sa[mi][ni], af[mi], bf2[ni]);
            }
            // ---- exp2 in regs + column partial sums ----
            float cs[4][2];
            #pragma unroll
            for (int ni = 0; ni < 4; ni++) { cs[ni][0] = 0.f; cs[ni][1] = 0.f; }
            #pragma unroll
            for (int mi = 0; mi < 4; mi++)
                #pragma unroll
                for (int ni = 0; ni < 4; ni++) {
                    float p0 = fex2(sa[mi][ni][0]);
                    float p1 = fex2(sa[mi][ni][1]);
                    float p2 = fex2(sa[mi][ni][2]);
                    float p3 = fex2(sa[mi][ni][3]);
                    sa[mi][ni][0] = p0; sa[mi][ni][1] = p1;
                    sa[mi][ni][2] = p2; sa[mi][ni][3] = p3;
                    cs[ni][0] += p0 + p2; cs[ni][1] += p1 + p3;
                }
            #pragma unroll
            for (int ni = 0; ni < 4; ni++) {
                float a = cs[ni][0], bq = cs[ni][1];
                #pragma unroll
                for (int o = 4; o <= 16; o <<= 1) {
                    a  += __shfl_xor_sync(0xffffffffu, a,  o);
                    bq += __shfl_xor_sync(0xffffffffu, bq, o);
                }
                if (lane < 4) {
                    int col = wn * 32 + ni * 8 + 2 * lane;
                    part[s * 256 + col * 4 + wm]       = a;
                    part[s * 256 + (col + 1) * 4 + wm] = bq;
                }
            }
            // ---- store raw exp P ----
            const uint32_t po = (s ? SATT_P1 : SATT_P0);
            #pragma unroll
            for (int ni = 0; ni < 4; ni++) {
                int col = wn * 32 + ni * 8 + 2 * lc;
                #pragma unroll
                for (int mi = 0; mi < 4; mi++) {
                    int row = wm * 64 + mi * 16 + lr;
                    *(bf162*)(smem + po + row * 144 + col * 2) =
                        __floats2bfloat162_rn(sa[mi][ni][0], sa[mi][ni][1]);
                    *(bf162*)(smem + po + (row + 8) * 144 + col * 2) =
                        __floats2bfloat162_rn(sa[mi][ni][2], sa[mi][ni][3]);
                }
            }
            bar_arrive(1 + s, 512);                // FULL[s]
        }
    } else {
        // ---------------- CONSUMER ----------------
        const int ctid = tid - 256;                // 0..255
        const int cw = warp - 8;
        const int wm = cw >> 1, wn = cw & 1;
        auto loadV = [&](int m, int j0, uint32_t dst) {
            #pragma unroll
            for (int q = 0; q < 2; q++) {
                int idx = ctid + q * 256, row = idx >> 3, cc = idx & 7;
                cpa16(dst + row * 144 + cc * 16,
                      Ve + (size_t)((j0 + row) * 8 + m) * 1024 + cc * 8);
            }
        };
        bar_arrive(3, 512);                        // pre-arrive EMPTY0
        bar_arrive(4, 512);                        // pre-arrive EMPTY1
        loadV(0, 0, vB[0]);
        cpa_commit();

        float oacc[4][4][4] = {};
        for (int c = 0; c < 32; c++) {
            const int s = c & 1;
            bar_sync(1 + s, 512);                  // FULL[s]; all consumers done MMA(c-1)
            if (c < 31) {
                int cn = c + 1;
                loadV(cn >> 2, (cn & 3) << 6, vB[cn & 1]);
                cpa_commit();
                cpa_wait1();                       // V(c) landed
            } else {
                cpa_wait0();
            }
            if (ctid < 64)
                rsc[ctid] = 1.f / (part[s * 256 + 4 * ctid]     + part[s * 256 + 4 * ctid + 1]
                                 + part[s * 256 + 4 * ctid + 2] + part[s * 256 + 4 * ctid + 3]);
            bar_sync(6, 256);                      // rsc + V(c) visible to group
            const uint32_t vb = vB[s], pb = pB[s];
            {   // fold rs into V rows (row = j index)
                #pragma unroll
                for (int q = 0; q < 2; q++) {
                    int idx = ctid + q * 256, row = idx >> 3, cc = idx & 7;
                    float r = rsc[row];
                    bf162* vp2 = (bf162*)(smem + (vb - base) + row * 144 + cc * 16);
                    #pragma unroll
                    for (int qq = 0; qq < 4; qq++) {
                        float2 f = __bfloat1622float2(vp2[qq]);
                        f.x *= r; f.y *= r;
                        vp2[qq] = __float22bfloat162_rn(f);
                    }
                }
            }
            bar_sync(6, 256);                      // V' ready
            #pragma unroll
            for (int s4 = 0; s4 < 4; s4++) {
                uint32_t af[4][4], bf2[4][2];
                #pragma unroll
                for (int mi = 0; mi < 4; mi++)
                    ldsm4(af[mi][0], af[mi][1], af[mi][2], af[mi][3],
                          pb + (wm * 64 + mi * 16 + (lane & 15)) * 144 + s4 * 32 + (lane & 16));
                #pragma unroll
                for (int ni = 0; ni < 4; ni++)
                    ldsm2t(bf2[ni][0], bf2[ni][1],
                           vb + (s4 * 16 + (lane & 15)) * 144 + (wn * 32 + ni * 8) * 2);
                #pragma unroll
                for (int mi = 0; mi < 4; mi++)
                    #pragma unroll
                    for (int ni = 0; ni < 4; ni++)
                        mma_bf16(oacc[mi][ni], af[mi], bf2[ni]);
            }
            bar_arrive(3 + s, 512);                // EMPTY[s]
        }
        // ---- epilogue ----
        bf16* Ob = g_aob + (size_t)(b * 256) * 4096 + z * 512 + h * 64;
        #pragma unroll
        for (int mi = 0; mi < 4; mi++) {
            int row = wm * 64 + mi * 16 + lr;
            #pragma unroll
            for (int ni = 0; ni < 4; ni++) {
                int col = wn * 32 + ni * 8 + 2 * lc;
                *(bf162*)(Ob + (size_t)row * 4096 + col) =
                    __floats2bfloat162_rn(oacc[mi][ni][0], oacc[mi][ni][1]);
                *(bf162*)(Ob + (size_t)(row + 8) * 4096 + col) =
                    __floats2bfloat162_rn(oacc[mi][ni][2], oacc[mi][ni][3]);
            }
        }
    }
}

// Wout split-K x4: partial GEMM over K slice -> g_wp[z]
__global__ __launch_bounds__(256) void k_wout() {
    extern __shared__ unsigned char dsm[];
    unsigned char* sA = dsm;
    unsigned char* sB = dsm + 2 * 128 * 144;
    float acc[4][2][4] = {};
    int m0 = blockIdx.y * 128, n0 = blockIdx.x * 64;
    int ks = blockIdx.z * 1024;
    mma_loop<128, 64>(g_aob + ks, 4096, g_Wout + (size_t)ks * 2048, 2048,
                      1024, m0, n0, acc, sA, sB);
    epi_f32<128, 64>(acc, g_wp + (size_t)blockIdx.z * NBN * 2048, 2048, m0, n0, nullptr);
}

// residual + LayerNorm with split-K partial reduction.
// mode 1: y = sum_4 g_wp + bout ; mode 2: y = sum_2 g_y2p + bff2 -> out
__global__ __launch_bounds__(256) void k_ln(int mode,
                                            const float* __restrict__ g,
                                            const float* __restrict__ beta,
                                            const float* __restrict__ bias,
                                            float* __restrict__ out) {
    int t = blockIdx.x, d = threadIdx.x;
    float xv, yv;
    if (mode == 1) {
        int bn = t >> 3, m = t & 7;
        size_t idx = (size_t)bn * 2048 + m * 256 + d;
        xv = g_xt[(size_t)t * ND + d];
        yv = g_wp[idx] + g_wp[idx + (size_t)NBN * 2048]
           + g_wp[idx + (size_t)2 * NBN * 2048] + g_wp[idx + (size_t)3 * NBN * 2048]
           + bias[m * 256 + d];
    } else {
        size_t idx = (size_t)t * ND + d;
        xv = g_x2[idx];
        yv = g_y2p[idx] + g_y2p[idx + (size_t)NTOK * ND] + bias[d];
    }
    float v = xv + yv;
    float s = v, s2 = v * v;
    #pragma unroll
    for (int o = 16; o; o >>= 1) {
        s  += __shfl_xor_sync(0xffffffffu, s,  o);
        s2 += __shfl_xor_sync(0xffffffffu, s2, o);
    }
    __shared__ float sh[16];
    int w = d >> 5, l = d & 31;
    if (l == 0) { sh[w] = s; sh[8 + w] = s2; }
    __syncthreads();
    if (d == 0) {
        float ts = 0.f, ts2 = 0.f;
        #pragma unroll
        for (int i = 0; i < 8; i++) { ts += sh[i]; ts2 += sh[8 + i]; }
        float mu  = ts * (1.f / 256.f);
        float var = ts2 * (1.f / 256.f) - mu * mu;
        sh[0] = mu;
        sh[1] = rsqrtf(var + 1e-5f);
    }
    __syncthreads();
    float r = (v - sh[0]) * sh[1] * g[d] + beta[d];
    if (mode == 1) {
        g_x2 [(size_t)t * ND + d] = r;
        g_x2b[(size_t)t * ND + d] = __float2bfloat16(r);
    } else {
        out[(size_t)t * ND + d] = r;
    }
}

__global__ __launch_bounds__(256) void k_ff1g(const float* __restrict__ bias) {
    extern __shared__ unsigned char dsm[];
    unsigned char* sA = dsm;
    unsigned char* sB = dsm + 2 * 128 * 144;
    float aA[4][2][4] = {};
    float aG[4][2][4] = {};
    int m0 = blockIdx.y * 128, n0 = blockIdx.x * 64;
    mma_loop<128, 64>(g_x2b, ND, g_Wff1, 2048, ND, m0, n0,        aA, sA, sB);
    mma_loop<128, 64>(g_x2b, ND, g_Wff1, 2048, ND, m0, n0 + 1024, aG, sA, sB);

    const int lane = threadIdx.x & 31, warp = threadIdx.x >> 5;
    const int lr = lane >> 2, lc = lane & 3;
    const int wm0 = (warp >> 2) * 64, wn0 = (warp & 3) * 16;
    #pragma unroll
    for (int mi = 0; mi < 4; mi++) {
        int row = m0 + wm0 + mi * 16 + lr;
        #pragma unroll
        for (int ni = 0; ni < 2; ni++) {
            int col = n0 + wn0 + ni * 8 + 2 * lc;
            float ba0 = bias[col],        ba1 = bias[col + 1];
            float bg0 = bias[1024 + col], bg1 = bias[1024 + col + 1];
            #pragma unroll
            for (int half = 0; half < 2; half++) {
                int r = row + half * 8;
                float a0 = aA[mi][ni][2 * half + 0] + ba0;
                float a1 = aA[mi][ni][2 * half + 1] + ba1;
                float gt0 = aG[mi][ni][2 * half + 0] + bg0;
                float gt1 = aG[mi][ni][2 * half + 1] + bg1;
                float v0 = a0 * 0.5f * gt0 * (1.f + erff(gt0 * 0.70710678118654752f));
                float v1 = a1 * 0.5f * gt1 * (1.f + erff(gt1 * 0.70710678118654752f));
                *(bf162*)(g_fib + (size_t)r * 1024 + col) = __floats2bfloat162_rn(v0, v1);
            }
        }
    }
}

// FF2 split-K x2: partial GEMM over K slice -> g_y2p[z]
__global__ __launch_bounds__(256) void k_ff2() {
    extern __shared__ unsigned char dsm[];
    unsigned char* sA = dsm;
    unsigned char* sB = dsm + 2 * 128 * 144;
    float acc[4][2][4] = {};
    int m0 = blockIdx.y * 128, n0 = blockIdx.x * 64;
    int ks = blockIdx.z * 512;
    mma_loop<128, 64>(g_fib + ks, 1024, g_Wff2 + (size_t)ks * ND, ND,
                      512, m0, n0, acc, sA, sB);
    epi_f32<128, 64>(acc, g_y2p + (size_t)blockIdx.z * NTOK * ND, ND, m0, n0, nullptr);
}

// ---------------- launch ----------------
extern "C" void kernel_launch(void* const* d_in, const int* in_sizes, int n_in,
                              void* d_out, int out_size) {
    const float* x     = (const float*)d_in[0];
    const float* Wq    = (const float*)d_in[1];
    const float* Wkv   = (const float*)d_in[2];
    const float* Wout  = (const float*)d_in[3];
    const float* bout  = (const float*)d_in[4];
    const float* g1    = (const float*)d_in[5];
    const float* beta1 = (const float*)d_in[6];
    const float* Wff1  = (const float*)d_in[7];
    const float* bff1  = (const float*)d_in[8];
    const float* Wff2  = (const float*)d_in[9];
    const float* bff2  = (const float*)d_in[10];
    const float* g2    = (const float*)d_in[11];
    const float* beta2 = (const float*)d_in[12];
    float* out = (float*)d_out;

    static int attr_set = 0;
    if (!attr_set) {
        cudaFuncSetAttribute(k_attn, cudaFuncAttributeMaxDynamicSharedMemorySize, SATT_SZ);
        cudaFuncSetAttribute(k_qkv,  cudaFuncAttributeMaxDynamicSharedMemorySize, SM_QKV);
        cudaFuncSetAttribute(k_wout, cudaFuncAttributeMaxDynamicSharedMemorySize, SM_G64);
        cudaFuncSetAttribute(k_ff1g, cudaFuncAttributeMaxDynamicSharedMemorySize, SM_G64);
        cudaFuncSetAttribute(k_ff2,  cudaFuncAttributeMaxDynamicSharedMemorySize, SM_G64);
        attr_set = 1;
    }

    k_prep <<<9344, 256>>>((const float4*)Wq, (const float4*)Wkv, (const float4*)Wout,
                           (const float4*)Wff1, (const float4*)Wff2);
    k_tr   <<<dim3(8, 8, 16), dim3(32, 8)>>>(x);
    k_qkv  <<<dim3(12, 32), 256, SM_QKV>>>();
    k_attn <<<128, 512, SATT_SZ>>>();
    k_wout <<<dim3(32, 4, 4), 256, SM_G64>>>();
    k_ln   <<<4096, 256>>>(1, g1, beta1, bout, nullptr);
    k_ff1g <<<dim3(16, 32), 256, SM_G64>>>(bff1);
    k_ff2  <<<dim3(4, 32, 2), 256, SM_G64>>>();
    k_ln   <<<4096, 256>>>(2, g2, beta2, bff2, out);
}

// round 13
// speedup vs baseline: 7.3257x; 1.0571x over previous
#include <cuda_runtime.h>
#include <cuda_bf16.h>
#include <math.h>
#include <stdint.h>

#define NB     2
#define NSEQ   256
#define NM     8
#define ND     256
#define NH     8
#define NDH    64
#define NINNER 512
#define NTOK   (NB*NSEQ*NM)          // 4096
#define NBN    (NB*NSEQ)             // 512
typedef __nv_bfloat16 bf16;
typedef __nv_bfloat162 bf162;

#define QSCALE 0.18033688011112042f   // 0.125 * log2(e): exp(S) == exp2(S')

// ---------------- scratch ----------------
__device__ float g_xt [NTOK*ND];                       // fp32 (residual)
__device__ bf16  g_xtb[NTOK*ND];
__device__ bf16  g_qb [NTOK*NINNER];
__device__ bf16  g_kvb[NTOK*2*NINNER];
__device__ bf16  g_aob[(size_t)NBN*4096];
__device__ float g_wp [(size_t)4*NBN*2048];            // wout split-K partials (16.8MB)
__device__ float g_x2 [NTOK*ND];
__device__ bf16  g_x2b[NTOK*ND];
__device__ bf16  g_fib[(size_t)NTOK*1024];
__device__ float g_y2p[(size_t)2*NTOK*ND];             // ff2 split-K partials (8.4MB)
// bf16 weights
__device__ bf16  g_Wq  [256*512];
__device__ bf16  g_Wkv [256*1024];
__device__ bf16  g_Wout[(size_t)4096*2048];
__device__ bf16  g_Wff1[256*2048];
__device__ bf16  g_Wff2[1024*256];

// ---------------- ptx helpers ----------------
__device__ __forceinline__ uint32_t smaddr(const void* p) {
    return (uint32_t)__cvta_generic_to_shared(p);
}
__device__ __forceinline__ void cpa16(uint32_t dst, const void* src) {
    asm volatile("cp.async.cg.shared.global [%0], [%1], 16;\n" :: "r"(dst), "l"(src) : "memory");
}
__device__ __forceinline__ void cpa_commit() { asm volatile("cp.async.commit_group;\n" ::: "memory"); }
__device__ __forceinline__ void cpa_wait0()  { asm volatile("cp.async.wait_group 0;\n" ::: "memory"); }
__device__ __forceinline__ void cpa_wait1()  { asm volatile("cp.async.wait_group 1;\n" ::: "memory"); }

__device__ __forceinline__ void bar_sync(int id, int cnt) {
    asm volatile("bar.sync %0, %1;" :: "r"(id), "r"(cnt) : "memory");
}
__device__ __forceinline__ void bar_arrive(int id, int cnt) {
    asm volatile("bar.arrive %0, %1;" :: "r"(id), "r"(cnt) : "memory");
}
__device__ __forceinline__ float fex2(float x) {
    float r;
    asm("ex2.approx.f32 %0, %1;" : "=f"(r) : "f"(x));
    return r;
}

__device__ __forceinline__ void ldsm4(uint32_t& r0, uint32_t& r1, uint32_t& r2, uint32_t& r3, uint32_t a) {
    asm volatile("ldmatrix.sync.aligned.m8n8.x4.shared.b16 {%0,%1,%2,%3}, [%4];"
                 : "=r"(r0), "=r"(r1), "=r"(r2), "=r"(r3) : "r"(a));
}
__device__ __forceinline__ void ldsm2(uint32_t& r0, uint32_t& r1, uint32_t a) {
    asm volatile("ldmatrix.sync.aligned.m8n8.x2.shared.b16 {%0,%1}, [%2];"
                 : "=r"(r0), "=r"(r1) : "r"(a));
}
__device__ __forceinline__ void ldsm2t(uint32_t& r0, uint32_t& r1, uint32_t a) {
    asm volatile("ldmatrix.sync.aligned.m8n8.x2.trans.shared.b16 {%0,%1}, [%2];"
                 : "=r"(r0), "=r"(r1) : "r"(a));
}
__device__ __forceinline__ void mma_bf16(float* c, const uint32_t* a, const uint32_t* b) {
    asm volatile(
        "mma.sync.aligned.m16n8k16.row.col.f32.bf16.bf16.f32 "
        "{%0,%1,%2,%3}, {%4,%5,%6,%7}, {%8,%9}, {%0,%1,%2,%3};\n"
        : "+f"(c[0]), "+f"(c[1]), "+f"(c[2]), "+f"(c[3])
        : "r"(a[0]), "r"(a[1]), "r"(a[2]), "r"(a[3]), "r"(b[0]), "r"(b[1]));
}

// ---------------- dense GEMM building blocks (K-chunk 64, dynamic smem) ----------------
// A smem: [BM rows][144B] (64 bf16 + 16B pad). B smem: [64 rows][BN*2+16].

template<int BM, int BN>
__device__ __forceinline__ void g2s64(const bf16* __restrict__ A, int lda,
                                      const bf16* __restrict__ B, int ldb,
                                      int m0, int n0, int k0,
                                      uint32_t aB, uint32_t bB, int tid)
{
    #pragma unroll
    for (int i = tid; i < BM * 8; i += 256) {
        int r = i >> 3, c = i & 7;
        cpa16(aB + r * 144 + c * 16, A + (size_t)(m0 + r) * lda + k0 + c * 8);
    }
    constexpr int NC = BN / 8, SBv = BN * 2 + 16;
    #pragma unroll
    for (int i = tid; i < 64 * NC; i += 256) {
        int kr = i / NC, c = i % NC;
        cpa16(bB + kr * SBv + c * 16, B + (size_t)(k0 + kr) * ldb + n0 + c * 8);
    }
    cpa_commit();
}

template<int BM, int BN>
__device__ __forceinline__ void smma64(uint32_t aB, uint32_t bB, int lane,
                                       int wm0, int wn0, float acc[][BN/32][4])
{
    constexpr int MT = BM / 32, NT = BN / 32, SBv = BN * 2 + 16;
    #pragma unroll
    for (int s = 0; s < 4; s++) {
        uint32_t af[MT][4], bf2[NT][2];
        #pragma unroll
        for (int mi = 0; mi < MT; mi++)
            ldsm4(af[mi][0], af[mi][1], af[mi][2], af[mi][3],
                  aB + (wm0 + mi * 16 + (lane & 15)) * 144 + s * 32 + (lane & 16));
        #pragma unroll
        for (int ni = 0; ni < NT; ni++)
            ldsm2t(bf2[ni][0], bf2[ni][1],
                   bB + (s * 16 + (lane & 15)) * SBv + (wn0 + ni * 8) * 2);
        #pragma unroll
        for (int mi = 0; mi < MT; mi++)
            #pragma unroll
            for (int ni = 0; ni < NT; ni++)
                mma_bf16(acc[mi][ni], af[mi], bf2[ni]);
    }
}

template<int BM, int BN>
__device__ __forceinline__ void mma_loop(const bf16* __restrict__ A, int lda,
                                         const bf16* __restrict__ B, int ldb,
                                         int K, int m0, int n0,
                                         float acc[][BN/32][4],
                                         unsigned char* sAbuf, unsigned char* sBbuf)
{
    constexpr int SBv = BN * 2 + 16;
    const int tid = threadIdx.x, lane = tid & 31, warp = tid >> 5;
    const int wm0 = (warp >> 2) * (BM / 2), wn0 = (warp & 3) * (BN / 4);
    uint32_t aB0 = smaddr(sAbuf), aB1 = aB0 + BM * 144;
    uint32_t bB0 = smaddr(sBbuf), bB1 = bB0 + 64 * SBv;

    g2s64<BM, BN>(A, lda, B, ldb, m0, n0, 0, aB0, bB0, tid);
    const int nch = K >> 6;
    for (int i = 0; i < nch; i++) {
        cpa_wait0();
        __syncthreads();
        uint32_t aB = (i & 1) ? aB1 : aB0, bB = (i & 1) ? bB1 : bB0;
        if (i + 1 < nch)
            g2s64<BM, BN>(A, lda, B, ldb, m0, n0, (i + 1) * 64,
                          (i & 1) ? aB0 : aB1, (i & 1) ? bB0 : bB1, tid);
        smma64<BM, BN>(aB, bB, lane, wm0, wn0, acc);
        __syncthreads();
    }
}

// smem budgets
#define SM_QKV  (2*128*144 + 2*64*272)   // 71680
#define SM_G64  (2*128*144 + 2*64*144)   // 55296

// ---------------- epilogue helpers ----------------
template<int BM, int BN>
__device__ __forceinline__ void epi_f32(float acc[][BN/32][4], float* C, int ldc,
                                        int m0, int n0, const float* bias)
{
    const int lane = threadIdx.x & 31, warp = threadIdx.x >> 5;
    const int lr = lane >> 2, lc = lane & 3;
    const int wm0 = (warp >> 2) * (BM / 2), wn0 = (warp & 3) * (BN / 4);
    #pragma unroll
    for (int mi = 0; mi < BM / 32; mi++) {
        int row = m0 + wm0 + mi * 16 + lr;
        #pragma unroll
        for (int ni = 0; ni < BN / 32; ni++) {
            int col = n0 + wn0 + ni * 8 + 2 * lc;
            float bx = 0.f, by = 0.f;
            if (bias) { bx = bias[col]; by = bias[col + 1]; }
            *(float2*)(C + (size_t)row * ldc + col) =
                make_float2(acc[mi][ni][0] + bx, acc[mi][ni][1] + by);
            *(float2*)(C + (size_t)(row + 8) * ldc + col) =
                make_float2(acc[mi][ni][2] + bx, acc[mi][ni][3] + by);
        }
    }
}

template<int BM, int BN>
__device__ __forceinline__ void epi_bf16(float acc[][BN/32][4], bf16* C, int ldc,
                                         int m0, int n0, float alpha)
{
    const int lane = threadIdx.x & 31, warp = threadIdx.x >> 5;
    const int lr = lane >> 2, lc = lane & 3;
    const int wm0 = (warp >> 2) * (BM / 2), wn0 = (warp & 3) * (BN / 4);
    #pragma unroll
    for (int mi = 0; mi < BM / 32; mi++) {
        int row = m0 + wm0 + mi * 16 + lr;
        #pragma unroll
        for (int ni = 0; ni < BN / 32; ni++) {
            int col = n0 + wn0 + ni * 8 + 2 * lc;
            *(bf162*)(C + (size_t)row * ldc + col) =
                __floats2bfloat162_rn(acc[mi][ni][0] * alpha, acc[mi][ni][1] * alpha);
            *(bf162*)(C + (size_t)(row + 8) * ldc + col) =
                __floats2bfloat162_rn(acc[mi][ni][2] * alpha, acc[mi][ni][3] * alpha);
        }
    }
}

// ---------------- kernels ----------------

// merged: small weight conversions (Wq/Wkv/Wff1/Wff2) + input transpose.
// blocks [0,1152): conversion; blocks [1152,2176): transpose.
__global__ __launch_bounds__(256) void k_prep(const float4* __restrict__ Wq,
                                              const float4* __restrict__ Wkv,
                                              const float4* __restrict__ Wff1,
                                              const float4* __restrict__ Wff2,
                                              const float* __restrict__ x)
{
    if (blockIdx.x < 1152) {
        int i = blockIdx.x * 256 + threadIdx.x;
        const float4* src; bf162* dst; int off;
        if      (i < 32768)  { src = Wq;   dst = (bf162*)g_Wq;   off = 0; }
        else if (i < 98304)  { src = Wkv;  dst = (bf162*)g_Wkv;  off = 32768; }
        else if (i < 229376) { src = Wff1; dst = (bf162*)g_Wff1; off = 98304; }
        else                 { src = Wff2; dst = (bf162*)g_Wff2; off = 229376; }
        int j = i - off;
        float4 v = src[j];
        dst[2 * j]     = __floats2bfloat162_rn(v.x, v.y);
        dst[2 * j + 1] = __floats2bfloat162_rn(v.z, v.w);
        return;
    }
    // ---- transpose x[b,d,m,n] -> g_xt/g_xtb [(b*N+n)*M+m][d] ----
    __shared__ float tile[32][33];
    int bi = blockIdx.x - 1152;
    int bx = bi & 7, by = (bi >> 3) & 7, zi = bi >> 6;
    int b = zi >> 3, m = zi & 7;
    int n0 = bx * 32, d0 = by * 32;
    int tx = threadIdx.x & 31, ty = threadIdx.x >> 5;
    #pragma unroll
    for (int r = 0; r < 4; r++) {
        int d = d0 + ty + r * 8;
        tile[ty + r * 8][tx] =
            x[((size_t)(b * ND + d) * NM + m) * NSEQ + n0 + tx];
    }
    __syncthreads();
    #pragma unroll
    for (int r = 0; r < 4; r++) {
        int n = n0 + ty + r * 8;
        int d = d0 + tx;
        float v = tile[tx][ty + r * 8];
        size_t o = ((size_t)(b * NSEQ + n) * NM + m) * ND + d;
        g_xt[o]  = v;
        g_xtb[o] = __float2bfloat16(v);
    }
}

// fused Q + KV projection. blockIdx.x<4 -> Q tile (x QSCALE), else KV tile.
__global__ __launch_bounds__(256) void k_qkv() {
    extern __shared__ unsigned char dsm[];
    unsigned char* sA = dsm;
    unsigned char* sB = dsm + 2 * 128 * 144;
    float acc[4][4][4] = {};
    int m0 = blockIdx.y * 128;
    if (blockIdx.x < 4) {
        int n0 = blockIdx.x * 128;
        mma_loop<128, 128>(g_xtb, ND, g_Wq, NINNER, ND, m0, n0, acc, sA, sB);
        epi_bf16<128, 128>(acc, g_qb, NINNER, m0, n0, QSCALE);   // fold scale + log2e
    } else {
        int n0 = (blockIdx.x - 4) * 128;
        mma_loop<128, 128>(g_xtb, ND, g_Wkv, 2 * NINNER, ND, m0, n0, acc, sA, sB);
        epi_bf16<128, 128>(acc, g_kvb, 2 * NINNER, m0, n0, 1.f);
    }
}

// ============ warp-specialized fused attention + hidden Wout conversion ============
// Blocks 0-127: attention (one CTA per e, 512 threads).
// Blocks 128-147: convert Wout fp32->bf16 on the 20 otherwise-idle SMs.
#define SATT_K    0
#define SATT_Q0   36864
#define SATT_Q1   73728
#define SATT_P0   110592
#define SATT_P1   147456
#define SATT_V0   184320
#define SATT_V1   193536
#define SATT_PART 202752
#define SATT_RSC  204800
#define SATT_SZ   205056
// barrier ids: FULL0=1 FULL1=2 EMPTY0=3 EMPTY1=4, producer-local=5, consumer-local=6

__global__ void __launch_bounds__(512, 1) k_attn(const float4* __restrict__ WoutSrc) {
    if (blockIdx.x >= 128) {
        // ---------------- Wout converter (idle-SM work) ----------------
        const size_t total = (size_t)4096 * 2048 / 4;         // 2097152 float4
        bf162* dst = (bf162*)g_Wout;
        for (size_t i = (size_t)(blockIdx.x - 128) * 512 + threadIdx.x;
             i < total; i += (size_t)20 * 512) {
            float4 v = WoutSrc[i];
            dst[2 * i]     = __floats2bfloat162_rn(v.x, v.y);
            dst[2 * i + 1] = __floats2bfloat162_rn(v.z, v.w);
        }
        return;
    }
    extern __shared__ unsigned char smem[];
    const uint32_t base = smaddr(smem);
    const int tid = threadIdx.x, lane = tid & 31, warp = tid >> 5;
    const int lr = lane >> 2, lc = lane & 3;
    const int e = blockIdx.x;
    const int z = e & 7, h = (e >> 3) & 7, b = e >> 6;

    const bf16* Qe = g_qb  + (size_t)(b * 2048) * 512  + h * 64;
    const bf16* Ke = g_kvb + (size_t)(b * 2048) * 1024 + h * 64;
    const bf16* Ve = g_kvb + (size_t)(b * 2048) * 1024 + 512 + h * 64;
    float* part = (float*)(smem + SATT_PART);   // [2][64 col][4 wm]
    float* rsc  = (float*)(smem + SATT_RSC);    // [64]

    const uint32_t qB[2] = { base + SATT_Q0, base + SATT_Q1 };
    const uint32_t pB[2] = { base + SATT_P0, base + SATT_P1 };
    const uint32_t vB[2] = { base + SATT_V0, base + SATT_V1 };

    if (warp < 8) {
        // ---------------- PRODUCER ----------------
        const int ptid = tid;                      // 0..255
        const int wm = warp >> 1, wn = warp & 1;   // 4(m:64 rows) x 2(n:32 cols)
        auto loadK = [&]() {
            #pragma unroll
            for (int q = 0; q < 8; q++) {
                int idx = ptid + q * 256, row = idx >> 3, cc = idx & 7;
                cpa16(base + SATT_K + row * 144 + cc * 16,
                      Ke + (size_t)(row * 8 + z) * 1024 + cc * 8);
            }
        };
        auto loadQ = [&](int m, uint32_t dst) {
            #pragma unroll
            for (int q = 0; q < 8; q++) {
                int idx = ptid + q * 256, row = idx >> 3, cc = idx & 7;
                cpa16(dst + row * 144 + cc * 16,
                      Qe + (size_t)(row * 8 + m) * 512 + cc * 8);
            }
        };
        loadK();
        loadQ(0, qB[0]);
        cpa_commit();

        for (int c = 0; c < 32; c++) {
            const int m = c >> 2, j0 = (c & 3) << 6, s = c & 1;
            if ((c & 3) == 0) {
                if (m < 7) loadQ(m + 1, qB[(m + 1) & 1]);
                cpa_commit();
                cpa_wait1();                       // K + Q(m) landed
                bar_sync(5, 256);
            }
            bar_sync(3 + s, 512);                  // EMPTY[s]: P[s], part[s] free
            const uint32_t qb = qB[m & 1];
            // ---- S' = Q_m @ K[j0:+64]^T  (warp tile 64x32) ----
            float sa[4][4][4] = {};
            #pragma unroll
            for (int s4 = 0; s4 < 4; s4++) {
                uint32_t af[4][4], bf2[4][2];
                #pragma unroll
                for (int mi = 0; mi < 4; mi++)
                    ldsm4(af[mi][0], af[mi][1], af[mi][2], af[mi][3],
                          qb + (wm * 64 + mi * 16 + (lane & 15)) * 144 + s4 * 32 + (lane & 16));
                #pragma unroll
                for (int ni = 0; ni < 4; ni++)
                    ldsm2(bf2[ni][0], bf2[ni][1],
                          base + SATT_K + (j0 + wn * 32 + ni * 8 + (lane & 7)) * 144
                          + s4 * 32 + ((lane >> 3) & 1) * 16);
                #pragma unroll
                for (int mi = 0; mi < 4; mi++)
                    #pragma unroll
                    for (int ni = 0; ni < 4; ni++)
                        mma_bf16(sa[mi][ni], af[mi], bf2[ni]);
            }
            // ---- exp2 in regs + column partial sums ----
            float cs[4][2];
            #pragma unroll
            for (int ni = 0; ni < 4; ni++) { cs[ni][0] = 0.f; cs[ni][1] = 0.f; }
            #pragma unroll
            for (int mi = 0; mi < 4; mi++)
                #pragma unroll
                for (int ni = 0; ni < 4; ni++) {
                    float p0 = fex2(sa[mi][ni][0]);
                    float p1 = fex2(sa[mi][ni][1]);
                    float p2 = fex2(sa[mi][ni][2]);
                    float p3 = fex2(sa[mi][ni][3]);
                    sa[mi][ni][0] = p0; sa[mi][ni][1] = p1;
                    sa[mi][ni][2] = p2; sa[mi][ni][3] = p3;
                    cs[ni][0] += p0 + p2; cs[ni][1] += p1 + p3;
                }
            #pragma unroll
            for (int ni = 0; ni < 4; ni++) {
                float a = cs[ni][0], bq = cs[ni][1];
                #pragma unroll
                for (int o = 4; o <= 16; o <<= 1) {
                    a  += __shfl_xor_sync(0xffffffffu, a,  o);
                    bq += __shfl_xor_sync(0xffffffffu, bq, o);
                }
                if (lane < 4) {
                    int col = wn * 32 + ni * 8 + 2 * lane;
                    part[s * 256 + col * 4 + wm]       = a;
                    part[s * 256 + (col + 1) * 4 + wm] = bq;
                }
            }
            // ---- store raw exp P ----
            const uint32_t po = (s ? SATT_P1 : SATT_P0);
            #pragma unroll
            for (int ni = 0; ni < 4; ni++) {
                int col = wn * 32 + ni * 8 + 2 * lc;
                #pragma unroll
                for (int mi = 0; mi < 4; mi++) {
                    int row = wm * 64 + mi * 16 + lr;
                    *(bf162*)(smem + po + row * 144 + col * 2) =
                        __floats2bfloat162_rn(sa[mi][ni][0], sa[mi][ni][1]);
                    *(bf162*)(smem + po + (row + 8) * 144 + col * 2) =
                        __floats2bfloat162_rn(sa[mi][ni][2], sa[mi][ni][3]);
                }
            }
            bar_arrive(1 + s, 512);                // FULL[s]
        }
    } else {
        // ---------------- CONSUMER ----------------
        const int ctid = tid - 256;                // 0..255
        const int cw = warp - 8;
        const int wm = cw >> 1, wn = cw & 1;
        auto loadV = [&](int m, int j0, uint32_t dst) {
            #pragma unroll
            for (int q = 0; q < 2; q++) {
                int idx = ctid + q * 256, row = idx >> 3, cc = idx & 7;
                cpa16(dst + row * 144 + cc * 16,
                      Ve + (size_t)((j0 + row) * 8 + m) * 1024 + cc * 8);
            }
        };
        bar_arrive(3, 512);                        // pre-arrive EMPTY0
        bar_arrive(4, 512);                        // pre-arrive EMPTY1
        loadV(0, 0, vB[0]);
        cpa_commit();

        float oacc[4][4][4] = {};
        for (int c = 0; c < 32; c++) {
            const int s = c & 1;
            bar_sync(1 + s, 512);                  // FULL[s]; all consumers done MMA(c-1)
            if (c < 31) {
                int cn = c + 1;
                loadV(cn >> 2, (cn & 3) << 6, vB[cn & 1]);
                cpa_commit();
                cpa_wait1();                       // V(c) landed
            } else {
                cpa_wait0();
            }
            if (ctid < 64)
                rsc[ctid] = 1.f / (part[s * 256 + 4 * ctid]     + part[s * 256 + 4 * ctid + 1]
                                 + part[s * 256 + 4 * ctid + 2] + part[s * 256 + 4 * ctid + 3]);
            bar_sync(6, 256);                      // rsc + V(c) visible to group
            const uint32_t vb = vB[s], pb = pB[s];
            {   // fold rs into V rows (row = j index)
                #pragma unroll
                for (int q = 0; q < 2; q++) {
                    int idx = ctid + q * 256, row = idx >> 3, cc = idx & 7;
                    float r = rsc[row];
                    bf162* vp2 = (bf162*)(smem + (vb - base) + row * 144 + cc * 16);
                    #pragma unroll
                    for (int qq = 0; qq < 4; qq++) {
                        float2 f = __bfloat1622float2(vp2[qq]);
                        f.x *= r; f.y *= r;
                        vp2[qq] = __float22bfloat162_rn(f);
                    }
                }
            }
            bar_sync(6, 256);                      // V' ready
            #pragma unroll
            for (int s4 = 0; s4 < 4; s4++) {
                uint32_t af[4][4], bf2[4][2];
                #pragma unroll
                for (int mi = 0; mi < 4; mi++)
                    ldsm4(af[mi][0], af[mi][1], af[mi][2], af[mi][3],
                          pb + (wm * 64 + mi * 16 + (lane & 15)) * 144 + s4 * 32 + (lane & 16));
                #pragma unroll
                for (int ni = 0; ni < 4; ni++)
                    ldsm2t(bf2[ni][0], bf2[ni][1],
                           vb + (s4 * 16 + (lane & 15)) * 144 + (wn * 32 + ni * 8) * 2);
                #pragma unroll
                for (int mi = 0; mi < 4; mi++)
                    #pragma unroll
                    for (int ni = 0; ni < 4; ni++)
                        mma_bf16(oacc[mi][ni], af[mi], bf2[ni]);
            }
            bar_arrive(3 + s, 512);                // EMPTY[s]
        }
        // ---- epilogue ----
        bf16* Ob = g_aob + (size_t)(b * 256) * 4096 + z * 512 + h * 64;
        #pragma unroll
        for (int mi = 0; mi < 4; mi++) {
            int row = wm * 64 + mi * 16 + lr;
            #pragma unroll
            for (int ni = 0; ni < 4; ni++) {
                int col = wn * 32 + ni * 8 + 2 * lc;
                *(bf162*)(Ob + (size_t)row * 4096 + col) =
                    __floats2bfloat162_rn(oacc[mi][ni][0], oacc[mi][ni][1]);
                *(bf162*)(Ob + (size_t)(row + 8) * 4096 + col) =
                    __floats2bfloat162_rn(oacc[mi][ni][2], oacc[mi][ni][3]);
            }
        }
    }
}

// Wout split-K x4: partial GEMM over K slice -> g_wp[z]
__global__ __launch_bounds__(256) void k_wout() {
    extern __shared__ unsigned char dsm[];
    unsigned char* sA = dsm;
    unsigned char* sB = dsm + 2 * 128 * 144;
    float acc[4][2][4] = {};
    int m0 = blockIdx.y * 128, n0 = blockIdx.x * 64;
    int ks = blockIdx.z * 1024;
    mma_loop<128, 64>(g_aob + ks, 4096, g_Wout + (size_t)ks * 2048, 2048,
                      1024, m0, n0, acc, sA, sB);
    epi_f32<128, 64>(acc, g_wp + (size_t)blockIdx.z * NBN * 2048, 2048, m0, n0, nullptr);
}

// residual + LayerNorm with split-K partial reduction.
// mode 1: y = sum_4 g_wp + bout ; mode 2: y = sum_2 g_y2p + bff2 -> out
__global__ __launch_bounds__(256) void k_ln(int mode,
                                            const float* __restrict__ g,
                                            const float* __restrict__ beta,
                                            const float* __restrict__ bias,
                                            float* __restrict__ out) {
    int t = blockIdx.x, d = threadIdx.x;
    float xv, yv;
    if (mode == 1) {
        int bn = t >> 3, m = t & 7;
        size_t idx = (size_t)bn * 2048 + m * 256 + d;
        xv = g_xt[(size_t)t * ND + d];
        yv = g_wp[idx] + g_wp[idx + (size_t)NBN * 2048]
           + g_wp[idx + (size_t)2 * NBN * 2048] + g_wp[idx + (size_t)3 * NBN * 2048]
           + bias[m * 256 + d];
    } else {
        size_t idx = (size_t)t * ND + d;
        xv = g_x2[idx];
        yv = g_y2p[idx] + g_y2p[idx + (size_t)NTOK * ND] + bias[d];
    }
    float v = xv + yv;
    float s = v, s2 = v * v;
    #pragma unroll
    for (int o = 16; o; o >>= 1) {
        s  += __shfl_xor_sync(0xffffffffu, s,  o);
        s2 += __shfl_xor_sync(0xffffffffu, s2, o);
    }
    __shared__ float sh[16];
    int w = d >> 5, l = d & 31;
    if (l == 0) { sh[w] = s; sh[8 + w] = s2; }
    __syncthreads();
    if (d == 0) {
        float ts = 0.f, ts2 = 0.f;
        #pragma unroll
        for (int i = 0; i < 8; i++) { ts += sh[i]; ts2 += sh[8 + i]; }
        float mu  = ts * (1.f / 256.f);
        float var = ts2 * (1.f / 256.f) - mu * mu;
        sh[0] = mu;
        sh[1] = rsqrtf(var + 1e-5f);
    }
    __syncthreads();
    float r = (v - sh[0]) * sh[1] * g[d] + beta[d];
    if (mode == 1) {
        g_x2 [(size_t)t * ND + d] = r;
        g_x2b[(size_t)t * ND + d] = __float2bfloat16(r);
    } else {
        out[(size_t)t * ND + d] = r;
    }
}

__global__ __launch_bounds__(256) void k_ff1g(const float* __restrict__ bias) {
    extern __shared__ unsigned char dsm[];
    unsigned char* sA = dsm;
    unsigned char* sB = dsm + 2 * 128 * 144;
    float aA[4][2][4] = {};
    float aG[4][2][4] = {};
    int m0 = blockIdx.y * 128, n0 = blockIdx.x * 64;
    mma_loop<128, 64>(g_x2b, ND, g_Wff1, 2048, ND, m0, n0,        aA, sA, sB);
    mma_loop<128, 64>(g_x2b, ND, g_Wff1, 2048, ND, m0, n0 + 1024, aG, sA, sB);

    const int lane = threadIdx.x & 31, warp = threadIdx.x >> 5;
    const int lr = lane >> 2, lc = lane & 3;
    const int wm0 = (warp >> 2) * 64, wn0 = (warp & 3) * 16;
    #pragma unroll
    for (int mi = 0; mi < 4; mi++) {
        int row = m0 + wm0 + mi * 16 + lr;
        #pragma unroll
        for (int ni = 0; ni < 2; ni++) {
            int col = n0 + wn0 + ni * 8 + 2 * lc;
            float ba0 = bias[col],        ba1 = bias[col + 1];
            float bg0 = bias[1024 + col], bg1 = bias[1024 + col + 1];
            #pragma unroll
            for (int half = 0; half < 2; half++) {
                int r = row + half * 8;
                float a0 = aA[mi][ni][2 * half + 0] + ba0;
                float a1 = aA[mi][ni][2 * half + 1] + ba1;
                float gt0 = aG[mi][ni][2 * half + 0] + bg0;
                float gt1 = aG[mi][ni][2 * half + 1] + bg1;
                float v0 = a0 * 0.5f * gt0 * (1.f + erff(gt0 * 0.70710678118654752f));
                float v1 = a1 * 0.5f * gt1 * (1.f + erff(gt1 * 0.70710678118654752f));
                *(bf162*)(g_fib + (size_t)r * 1024 + col) = __floats2bfloat162_rn(v0, v1);
            }
        }
    }
}

// FF2 split-K x2: partial GEMM over K slice -> g_y2p[z]
__global__ __launch_bounds__(256) void k_ff2() {
    extern __shared__ unsigned char dsm[];
    unsigned char* sA = dsm;
    unsigned char* sB = dsm + 2 * 128 * 144;
    float acc[4][2][4] = {};
    int m0 = blockIdx.y * 128, n0 = blockIdx.x * 64;
    int ks = blockIdx.z * 512;
    mma_loop<128, 64>(g_fib + ks, 1024, g_Wff2 + (size_t)ks * ND, ND,
                      512, m0, n0, acc, sA, sB);
    epi_f32<128, 64>(acc, g_y2p + (size_t)blockIdx.z * NTOK * ND, ND, m0, n0, nullptr);
}

// ---------------- launch ----------------
extern "C" void kernel_launch(void* const* d_in, const int* in_sizes, int n_in,
                              void* d_out, int out_size) {
    const float* x     = (const float*)d_in[0];
    const float* Wq    = (const float*)d_in[1];
    const float* Wkv   = (const float*)d_in[2];
    const float* Wout  = (const float*)d_in[3];
    const float* bout  = (const float*)d_in[4];
    const float* g1    = (const float*)d_in[5];
    const float* beta1 = (const float*)d_in[6];
    const float* Wff1  = (const float*)d_in[7];
    const float* bff1  = (const float*)d_in[8];
    const float* Wff2  = (const float*)d_in[9];
    const float* bff2  = (const float*)d_in[10];
    const float* g2    = (const float*)d_in[11];
    const float* beta2 = (const float*)d_in[12];
    float* out = (float*)d_out;

    static int attr_set = 0;
    if (!attr_set) {
        cudaFuncSetAttribute(k_attn, cudaFuncAttributeMaxDynamicSharedMemorySize, SATT_SZ);
        cudaFuncSetAttribute(k_qkv,  cudaFuncAttributeMaxDynamicSharedMemorySize, SM_QKV);
        cudaFuncSetAttribute(k_wout, cudaFuncAttributeMaxDynamicSharedMemorySize, SM_G64);
        cudaFuncSetAttribute(k_ff1g, cudaFuncAttributeMaxDynamicSharedMemorySize, SM_G64);
        cudaFuncSetAttribute(k_ff2,  cudaFuncAttributeMaxDynamicSharedMemorySize, SM_G64);
        attr_set = 1;
    }

    k_prep <<<2176, 256>>>((const float4*)Wq, (const float4*)Wkv,
                           (const float4*)Wff1, (const float4*)Wff2, x);
    k_qkv  <<<dim3(12, 32), 256, SM_QKV>>>();
    k_attn <<<148, 512, SATT_SZ>>>((const float4*)Wout);
    k_wout <<<dim3(32, 4, 4), 256, SM_G64>>>();
    k_ln   <<<4096, 256>>>(1, g1, beta1, bout, nullptr);
    k_ff1g <<<dim3(16, 32), 256, SM_G64>>>(bff1);
    k_ff2  <<<dim3(4, 32, 2), 256, SM_G64>>>();
    k_ln   <<<4096, 256>>>(2, g2, beta2, bff2, out);
}